// round 1
// baseline (speedup 1.0000x reference)
#include <cuda_runtime.h>
#include <math_constants.h>

#define NN 100000
#define NE 1600000

typedef unsigned long long ull;

// ---------------- device scratch (static, no allocation) ----------------
__device__ float g_h[NN * 160];       // per-layer linear output h  (max 160 cols)
__device__ float g_agg[NN * 128];     // aggregated GAT output (layers 0/1)
__device__ float g_as[4 * NN];        // a_src, head-major [4][NN]
__device__ float g_ad[4 * NN];        // a_dst, head-major [4][NN]
__device__ int   g_deg[NN];
__device__ int   g_rowptr[NN + 1];
__device__ int   g_pos[NN];
__device__ int   g_srcs[NE];          // src indices sorted by dst (CSR)
__device__ float g_Wm0[128 * 128];
__device__ float g_Wm1[128 * 128];
__device__ float g_Wm2[128 * 160];
__device__ float g_thr;
__device__ float g_bnsum[128], g_bnsq[128];
__device__ float g_scale[128], g_shift[128];

// ---------------- f32x2 helpers (Blackwell packed fp32) ----------------
__device__ __forceinline__ ull pack2(float a, float b) {
    ull r; asm("mov.b64 %0, {%1, %2};" : "=l"(r) : "f"(a), "f"(b)); return r;
}
__device__ __forceinline__ void unpack2(ull v, float& a, float& b) {
    asm("mov.b64 {%0, %1}, %2;" : "=f"(a), "=f"(b) : "l"(v));
}
__device__ __forceinline__ ull fma2(ull a, ull b, ull c) {
    ull d; asm("fma.rn.f32x2 %0, %1, %2, %3;" : "=l"(d) : "l"(a), "l"(b), "l"(c)); return d;
}

// ---------------- exact percentile (rank select over |scores|) ----------------
// n = 53248 values (32768 from s01, 20480 from s2); torch-style index k = 26624
// (0-based) of ascending sort. Bitwise radix select on the uint pattern of the
// non-negative floats (order-isomorphic), so the threshold is bit-exact.
__global__ void thr_kernel(const float* __restrict__ s01, const float* __restrict__ s2) {
    extern __shared__ unsigned sm[];
    unsigned* red = sm + 53248;
    int t = threadIdx.x;
    for (int i = t; i < 32768; i += 1024) sm[i] = __float_as_uint(fabsf(s01[i]));
    for (int i = t; i < 20480; i += 1024) sm[32768 + i] = __float_as_uint(fabsf(s2[i]));
    __syncthreads();
    unsigned prefix = 0;
    int k = 26624;
    for (int bit = 30; bit >= 0; --bit) {   // bit 31 is always 0 for |x|
        unsigned himask = 0xFFFFFFFEu << bit;   // bits [bit+1 .. 31]
        unsigned bitm = 1u << bit;
        int cnt = 0;
        for (int i = t; i < 53248; i += 1024) {
            unsigned v = sm[i];
            cnt += ((((v ^ prefix) & himask) == 0u) && ((v & bitm) == 0u)) ? 1 : 0;
        }
        #pragma unroll
        for (int o = 16; o; o >>= 1) cnt += __shfl_xor_sync(0xffffffffu, cnt, o);
        if ((t & 31) == 0) red[t >> 5] = (unsigned)cnt;
        __syncthreads();
        int total = 0;
        #pragma unroll
        for (int w = 0; w < 32; w++) total += (int)red[w];
        if (k >= total) { prefix |= bitm; k -= total; }
        __syncthreads();
    }
    if (t == 0) g_thr = __uint_as_float(prefix);
}

// ---------------- masked weights ----------------
__global__ void mask_kernel(const float* __restrict__ w01, const float* __restrict__ s01,
                            const float* __restrict__ w2, const float* __restrict__ s2) {
    float thr = g_thr;
    int i = blockIdx.x * blockDim.x + threadIdx.x;
    if (i < 16384)       g_Wm0[i] = (fabsf(s01[i]) < thr) ? 0.f : w01[i];
    else if (i < 32768)  g_Wm1[i - 16384] = (fabsf(s01[i]) < thr) ? 0.f : w01[i];
    else if (i < 53248) { int j = i - 32768; g_Wm2[j] = (fabsf(s2[j]) < thr) ? 0.f : w2[j]; }
}

// ---------------- CSR build (sorted-by-dst edge list) ----------------
__global__ void zero_deg_kernel() {
    int i = blockIdx.x * blockDim.x + threadIdx.x;
    if (i < NN) g_deg[i] = 0;
}
__global__ void hist_kernel(const int* __restrict__ dst) {
    int e = blockIdx.x * blockDim.x + threadIdx.x;
    if (e < NE) atomicAdd(&g_deg[dst[e]], 1);
}
__global__ void scan_kernel() {
    __shared__ int sums[1024];
    int t = threadIdx.x;
    const int CH = 98;                        // ceil(100000/1024)
    int lo = t * CH, hi = min(lo + CH, NN);
    int s = 0;
    for (int i = lo; i < hi; i++) s += g_deg[i];
    sums[t] = s;
    __syncthreads();
    for (int off = 1; off < 1024; off <<= 1) {
        int v = (t >= off) ? sums[t - off] : 0;
        __syncthreads();
        sums[t] += v;
        __syncthreads();
    }
    int run = (t == 0) ? 0 : sums[t - 1];
    for (int i = lo; i < hi; i++) {
        g_rowptr[i] = run; g_pos[i] = run; run += g_deg[i];
    }
    if (t == 0) g_rowptr[NN] = sums[1023];
}
__global__ void scatter_kernel(const int* __restrict__ src, const int* __restrict__ dst) {
    int e = blockIdx.x * blockDim.x + threadIdx.x;
    if (e < NE) {
        int d = dst[e];
        int p = atomicAdd(&g_pos[d], 1);
        g_srcs[p] = src[e];
    }
}

// ---------------- GEMM: h = act(X) @ Wm, K=128, NC in {128,160} ----------------
// 64-row tiles, full W in smem. Warp covers all columns (x-operand broadcast ->
// conflict-free smem). Row-paired f32x2 accumulation.
template<int NC>
__global__ void __launch_bounds__(256) gemm_kernel(const float* __restrict__ Xopt,
                                                   int widx, int useBN) {
    constexpr int TN = NC / 32;
    extern __shared__ float smf[];
    float* Ws = smf;            // [128][NC]
    float* Xs = smf + NC * 128; // [64][128]
    const float* X = Xopt ? Xopt : g_agg;
    const float* W = (widx == 0) ? g_Wm0 : (widx == 1) ? g_Wm1 : g_Wm2;
    float* H = g_h;

    const int tid = threadIdx.x;
    const int tx = tid & 31, ty = tid >> 5;
    const int row0 = blockIdx.x * 64;

    {   // load W (128*NC floats)
        float4* wd = (float4*)Ws;
        const float4* wsrc = (const float4*)W;
        for (int i = tid; i < NC * 32; i += 256) wd[i] = wsrc[i];
    }
    {   // load X tile, optional fused BN(scale/shift) + ReLU
        const float4* xf = (const float4*)X;
        float4* xsf = (float4*)Xs;
        for (int i = tid; i < 2048; i += 256) {
            int r = i >> 5, c4 = i & 31;
            int gr = row0 + r;
            float4 v = make_float4(0.f, 0.f, 0.f, 0.f);
            if (gr < NN) {
                v = xf[gr * 32 + c4];
                if (useBN) {
                    float4 sc = ((const float4*)g_scale)[c4];
                    float4 sh = ((const float4*)g_shift)[c4];
                    v.x = fmaxf(fmaf(v.x, sc.x, sh.x), 0.f);
                    v.y = fmaxf(fmaf(v.y, sc.y, sh.y), 0.f);
                    v.z = fmaxf(fmaf(v.z, sc.z, sh.z), 0.f);
                    v.w = fmaxf(fmaf(v.w, sc.w, sh.w), 0.f);
                }
            }
            xsf[i] = v;
        }
    }
    __syncthreads();

    ull acc[4][TN];
    #pragma unroll
    for (int i = 0; i < 4; i++)
        #pragma unroll
        for (int j = 0; j < TN; j++) acc[i][j] = 0ull;

    #pragma unroll 2
    for (int k = 0; k < 128; k++) {
        ull xp[4];
        #pragma unroll
        for (int i = 0; i < 4; i++) {
            float a = Xs[(ty * 8 + 2 * i) * 128 + k];
            float b = Xs[(ty * 8 + 2 * i + 1) * 128 + k];
            xp[i] = pack2(a, b);
        }
        ull wd[TN];
        #pragma unroll
        for (int j = 0; j < TN; j++) {
            float w = Ws[k * NC + tx * TN + j];
            wd[j] = pack2(w, w);
        }
        #pragma unroll
        for (int i = 0; i < 4; i++)
            #pragma unroll
            for (int j = 0; j < TN; j++)
                acc[i][j] = fma2(xp[i], wd[j], acc[i][j]);
    }

    #pragma unroll
    for (int i = 0; i < 4; i++) {
        int r0 = row0 + ty * 8 + 2 * i;
        #pragma unroll
        for (int j = 0; j < TN; j++) {
            float a, b; unpack2(acc[i][j], a, b);
            if (r0 < NN)     H[r0 * NC + tx * TN + j] = a;
            if (r0 + 1 < NN) H[(r0 + 1) * NC + tx * TN + j] = b;
        }
    }
}

// ---------------- attention logits a_src/a_dst (head-major) ----------------
template<int D>   // head dim: 32 or 40; NC = 4*D
__global__ void a2_kernel(const float* __restrict__ att) {
    constexpr int NC = 4 * D, C = NC / 32;
    int idx = blockIdx.x * blockDim.x + threadIdx.x;
    int v = idx >> 5;
    int lane = threadIdx.x & 31;
    if (v >= NN) return;
    int c0 = lane * C;
    float as = 0.f, ad = 0.f;
    #pragma unroll
    for (int j = 0; j < C; j++) {
        float h = g_h[v * NC + c0 + j];
        as = fmaf(h, att[c0 + j], as);
        ad = fmaf(h, att[NC + c0 + j], ad);
    }
    #pragma unroll
    for (int o = 4; o; o >>= 1) {
        as += __shfl_xor_sync(0xffffffffu, as, o);
        ad += __shfl_xor_sync(0xffffffffu, ad, o);
    }
    if ((lane & 7) == 0) {
        int head = lane >> 3;
        g_as[head * NN + v] = as;
        g_ad[head * NN + v] = ad;
    }
}

// ---------------- per-node softmax + aggregation (warp per node) ----------------
template<int D, bool MEAN>
__global__ void agg_kernel(float* __restrict__ outMean) {
    constexpr int NC = 4 * D, C = NC / 32;
    int idx = blockIdx.x * blockDim.x + threadIdx.x;
    int v = idx >> 5;
    int lane = threadIdx.x & 31;
    if (v >= NN) return;
    int start = g_rowptr[v], end = g_rowptr[v + 1];
    int head = lane >> 3;

    if (start >= end) {   // isolated node -> zeros
        if (MEAN) {
            if (lane < 8) {
                #pragma unroll
                for (int j = 0; j < C; j++) outMean[v * D + lane * C + j] = 0.f;
            }
        } else {
            ((float4*)g_agg)[v * 32 + lane] = make_float4(0.f, 0.f, 0.f, 0.f);
        }
        return;
    }

    float adv[4];
    #pragma unroll
    for (int h = 0; h < 4; h++) adv[h] = g_ad[h * NN + v];

    // pass 1: per-head max
    float mx[4] = {-CUDART_INF_F, -CUDART_INF_F, -CUDART_INF_F, -CUDART_INF_F};
    for (int i = start + lane; i < end; i += 32) {
        int s = g_srcs[i];
        #pragma unroll
        for (int h = 0; h < 4; h++) {
            float e = g_as[h * NN + s] + adv[h];
            e = (e >= 0.f) ? e : 0.2f * e;
            mx[h] = fmaxf(mx[h], e);
        }
    }
    #pragma unroll
    for (int h = 0; h < 4; h++)
        #pragma unroll
        for (int o = 16; o; o >>= 1)
            mx[h] = fmaxf(mx[h], __shfl_xor_sync(0xffffffffu, mx[h], o));

    // pass 2: per-head denominator
    float den[4] = {0.f, 0.f, 0.f, 0.f};
    for (int i = start + lane; i < end; i += 32) {
        int s = g_srcs[i];
        #pragma unroll
        for (int h = 0; h < 4; h++) {
            float e = g_as[h * NN + s] + adv[h];
            e = (e >= 0.f) ? e : 0.2f * e;
            den[h] += __expf(e - mx[h]);
        }
    }
    #pragma unroll
    for (int h = 0; h < 4; h++)
        #pragma unroll
        for (int o = 16; o; o >>= 1)
            den[h] += __shfl_xor_sync(0xffffffffu, den[h], o);

    float mxh = mx[head];
    float invh = 1.f / (den[head] + 1e-16f);
    float adh = adv[head];

    // pass 3: weighted gather of h[src]
    float acc[C];
    #pragma unroll
    for (int j = 0; j < C; j++) acc[j] = 0.f;
    for (int i = start; i < end; i++) {
        int s = g_srcs[i];
        float e = g_as[head * NN + s] + adh;
        e = (e >= 0.f) ? e : 0.2f * e;
        float alpha = __expf(e - mxh) * invh;
        if (C == 4) {
            float4 hv = ((const float4*)g_h)[s * 32 + lane];
            acc[0] = fmaf(hv.x, alpha, acc[0]);
            acc[1] = fmaf(hv.y, alpha, acc[1]);
            acc[2] = fmaf(hv.z, alpha, acc[2]);
            acc[3] = fmaf(hv.w, alpha, acc[3]);
        } else {
            #pragma unroll
            for (int j = 0; j < C; j++)
                acc[j] = fmaf(g_h[s * NC + lane * C + j], alpha, acc[j]);
        }
    }

    if (MEAN) {   // mean over 4 heads -> [NN, D]
        #pragma unroll
        for (int j = 0; j < C; j++) {
            float a = acc[j];
            a += __shfl_xor_sync(0xffffffffu, a, 8);
            a += __shfl_xor_sync(0xffffffffu, a, 16);
            if (lane < 8) outMean[v * D + lane * C + j] = 0.25f * a;
        }
    } else {
        ((float4*)g_agg)[v * 32 + lane] = make_float4(acc[0], acc[1], acc[2], acc[3]);
    }
}

// ---------------- batch norm ----------------
__global__ void zero_bn_kernel() {
    int c = threadIdx.x;
    g_bnsum[c] = 0.f; g_bnsq[c] = 0.f;
}
__global__ void bnstats_kernel() {
    int c = threadIdx.x;   // 128 threads
    float s = 0.f, q = 0.f;
    for (int r = blockIdx.x; r < NN; r += gridDim.x) {
        float x = g_agg[r * 128 + c];
        s += x; q = fmaf(x, x, q);
    }
    atomicAdd(&g_bnsum[c], s);
    atomicAdd(&g_bnsq[c], q);
}
__global__ void bnfinal_kernel(const float* __restrict__ gamma, const float* __restrict__ beta) {
    int c = threadIdx.x;
    float mu = g_bnsum[c] * (1.f / NN);
    float var = g_bnsq[c] * (1.f / NN) - mu * mu;
    float rstd = rsqrtf(var + 1e-5f);
    float sc = rstd * gamma[c];
    g_scale[c] = sc;
    g_shift[c] = fmaf(-mu, sc, beta[c]);
}

// ---------------- launch ----------------
extern "C" void kernel_launch(void* const* d_in, const int* in_sizes, int n_in,
                              void* d_out, int out_size) {
    (void)in_sizes; (void)n_in; (void)out_size;
    const float* x     = (const float*)d_in[0];
    const int*   ei    = (const int*)d_in[1];
    const float* w01   = (const float*)d_in[2];
    const float* s01   = (const float*)d_in[3];
    const float* att01 = (const float*)d_in[4];
    const float* w2    = (const float*)d_in[5];
    const float* s2    = (const float*)d_in[6];
    const float* att2  = (const float*)d_in[7];
    const float* gamma = (const float*)d_in[8];
    const float* beta  = (const float*)d_in[9];
    float* out = (float*)d_out;
    const int* srcp = ei;
    const int* dstp = ei + NE;

    const int THR_SMEM  = (53248 + 32) * 4;
    const int G128_SMEM = (128 * 128 + 64 * 128) * 4;   // 96 KB
    const int G160_SMEM = (160 * 128 + 64 * 128) * 4;   // 112 KB
    cudaFuncSetAttribute(thr_kernel, cudaFuncAttributeMaxDynamicSharedMemorySize, THR_SMEM);
    cudaFuncSetAttribute(gemm_kernel<128>, cudaFuncAttributeMaxDynamicSharedMemorySize, G128_SMEM);
    cudaFuncSetAttribute(gemm_kernel<160>, cudaFuncAttributeMaxDynamicSharedMemorySize, G160_SMEM);

    // threshold + masked weights
    thr_kernel<<<1, 1024, THR_SMEM>>>(s01, s2);
    mask_kernel<<<(53248 + 255) / 256, 256>>>(w01, s01, w2, s2);

    // CSR build (shared by all 3 layers)
    zero_deg_kernel<<<(NN + 255) / 256, 256>>>();
    hist_kernel<<<(NE + 255) / 256, 256>>>(dstp);
    scan_kernel<<<1, 1024>>>();
    scatter_kernel<<<(NE + 255) / 256, 256>>>(srcp, dstp);

    const int GB = (NN + 63) / 64;         // gemm blocks
    const int WB = (NN * 32 + 255) / 256;  // warp-per-node blocks

    // ---- layer 0 ----
    gemm_kernel<128><<<GB, 256, G128_SMEM>>>(x, 0, 0);
    a2_kernel<32><<<WB, 256>>>(att01);
    agg_kernel<32, false><<<WB, 256>>>(nullptr);
    zero_bn_kernel<<<1, 128>>>();
    bnstats_kernel<<<512, 128>>>();
    bnfinal_kernel<<<1, 128>>>(gamma, beta);

    // ---- layer 1 ----
    gemm_kernel<128><<<GB, 256, G128_SMEM>>>(nullptr, 1, 1);
    a2_kernel<32><<<WB, 256>>>(att01 + 256);
    agg_kernel<32, false><<<WB, 256>>>(nullptr);
    zero_bn_kernel<<<1, 128>>>();
    bnstats_kernel<<<512, 128>>>();
    bnfinal_kernel<<<1, 128>>>(gamma + 128, beta + 128);

    // ---- layer 2 (output, head-mean) ----
    gemm_kernel<160><<<GB, 256, G160_SMEM>>>(nullptr, 2, 1);
    a2_kernel<40><<<WB, 256>>>(att2);
    agg_kernel<40, true><<<WB, 256>>>(out);
}

// round 2
// speedup vs baseline: 1.2583x; 1.2583x over previous
#include <cuda_runtime.h>
#include <math_constants.h>

#define NN 100000
#define NE 1600000

typedef unsigned long long ull;

// ---------------- device scratch ----------------
__device__ float  g_h[NN * 160];
__device__ float  g_agg[NN * 128];
__device__ float4 g_as4[NN];          // a_src per node, 4 heads packed
__device__ float4 g_ad4[NN];          // a_dst per node
__device__ int    g_deg[NN];
__device__ int    g_rowptr[NN + 1];
__device__ int    g_pos[NN];
__device__ int    g_srcs[NE];
__device__ float  g_Wm0[128 * 128];
__device__ float  g_Wm1[128 * 128];
__device__ float  g_Wm2[128 * 160];
__device__ float  g_thr;
__device__ float  g_bnsum[128], g_bnsq[128];
__device__ float  g_scale[128], g_shift[128];
__device__ int    g_bsum[98], g_boff[98];

// ---------------- f32x2 helpers ----------------
__device__ __forceinline__ ull pack2(float a, float b) {
    ull r; asm("mov.b64 %0, {%1, %2};" : "=l"(r) : "f"(a), "f"(b)); return r;
}
__device__ __forceinline__ void unpack2(ull v, float& a, float& b) {
    asm("mov.b64 {%0, %1}, %2;" : "=f"(a), "=f"(b) : "l"(v));
}
__device__ __forceinline__ ull fma2(ull a, ull b, ull c) {
    ull d; asm("fma.rn.f32x2 %0, %1, %2, %3;" : "=l"(d) : "l"(a), "l"(b), "l"(c)); return d;
}
__device__ __forceinline__ float lrelu(float x) { return (x >= 0.f) ? x : 0.2f * x; }

// ---------------- exact percentile (bitwise radix rank-select) ----------------
__global__ void thr_kernel(const float* __restrict__ s01, const float* __restrict__ s2) {
    extern __shared__ unsigned sm[];
    unsigned* red = sm + 53248;
    int t = threadIdx.x;
    for (int i = t; i < 32768; i += 1024) sm[i] = __float_as_uint(fabsf(s01[i]));
    for (int i = t; i < 20480; i += 1024) sm[32768 + i] = __float_as_uint(fabsf(s2[i]));
    __syncthreads();
    unsigned prefix = 0;
    int k = 26624;
    for (int bit = 30; bit >= 0; --bit) {
        unsigned himask = 0xFFFFFFFEu << bit;
        unsigned bitm = 1u << bit;
        int cnt = 0;
        for (int i = t; i < 53248; i += 1024) {
            unsigned v = sm[i];
            cnt += ((((v ^ prefix) & himask) == 0u) && ((v & bitm) == 0u)) ? 1 : 0;
        }
        #pragma unroll
        for (int o = 16; o; o >>= 1) cnt += __shfl_xor_sync(0xffffffffu, cnt, o);
        if ((t & 31) == 0) red[t >> 5] = (unsigned)cnt;
        __syncthreads();
        int total = 0;
        #pragma unroll
        for (int w = 0; w < 32; w++) total += (int)red[w];
        if (k >= total) { prefix |= bitm; k -= total; }
        __syncthreads();
    }
    if (t == 0) g_thr = __uint_as_float(prefix);
}

// ---------------- masked weights ----------------
__global__ void mask_kernel(const float* __restrict__ w01, const float* __restrict__ s01,
                            const float* __restrict__ w2, const float* __restrict__ s2) {
    float thr = g_thr;
    int i = blockIdx.x * blockDim.x + threadIdx.x;
    if (i < 16384)       g_Wm0[i] = (fabsf(s01[i]) < thr) ? 0.f : w01[i];
    else if (i < 32768)  g_Wm1[i - 16384] = (fabsf(s01[i]) < thr) ? 0.f : w01[i];
    else if (i < 53248) { int j = i - 32768; g_Wm2[j] = (fabsf(s2[j]) < thr) ? 0.f : w2[j]; }
}

// ---------------- CSR build ----------------
__global__ void zero_deg_kernel() {
    int i = blockIdx.x * blockDim.x + threadIdx.x;
    if (i < NN) g_deg[i] = 0;
}
__global__ void hist_kernel(const int* __restrict__ dst) {
    int e = blockIdx.x * blockDim.x + threadIdx.x;
    if (e < NE) atomicAdd(&g_deg[dst[e]], 1);
}
__global__ void scan1_kernel() {   // 98 blocks x 1024: block sums, coalesced
    __shared__ int red[32];
    int t = threadIdx.x, b = blockIdx.x;
    int i = b * 1024 + t;
    int s = (i < NN) ? g_deg[i] : 0;
    #pragma unroll
    for (int o = 16; o; o >>= 1) s += __shfl_xor_sync(0xffffffffu, s, o);
    if ((t & 31) == 0) red[t >> 5] = s;
    __syncthreads();
    if (t < 32) {
        int x = red[t];
        #pragma unroll
        for (int o = 16; o; o >>= 1) x += __shfl_xor_sync(0xffffffffu, x, o);
        if (t == 0) g_bsum[b] = x;
    }
}
__global__ void scan2_kernel() {   // tiny serial prefix over 98 block sums
    if (threadIdx.x == 0) {
        int run = 0;
        for (int b = 0; b < 98; b++) { g_boff[b] = run; run += g_bsum[b]; }
        g_rowptr[NN] = run;
    }
}
__global__ void scan3_kernel() {   // 98 blocks x 1024: local scan + writeback
    __shared__ int sm[1024];
    int t = threadIdx.x, b = blockIdx.x;
    int i = b * 1024 + t;
    int v = (i < NN) ? g_deg[i] : 0;
    sm[t] = v;
    __syncthreads();
    for (int off = 1; off < 1024; off <<= 1) {
        int x = (t >= off) ? sm[t - off] : 0;
        __syncthreads();
        sm[t] += x;
        __syncthreads();
    }
    if (i < NN) {
        int excl = sm[t] - v + g_boff[b];
        g_rowptr[i] = excl;
        g_pos[i] = excl;
    }
}
__global__ void scatter_kernel(const int* __restrict__ src, const int* __restrict__ dst) {
    int e = blockIdx.x * blockDim.x + threadIdx.x;
    if (e < NE) {
        int d = dst[e];
        int p = atomicAdd(&g_pos[d], 1);
        g_srcs[p] = src[e];
    }
}

// ---------------- GEMM: h = act(X) @ Wm ----------------
// 128-row tiles. XsT transposed [k][row] -> broadcast float2 loads (1 wf).
// Columns per lane: tx + 32j -> conflict-free smem W reads + coalesced stores.
template<int NC>
__global__ void __launch_bounds__(256) gemm_kernel(const float* __restrict__ Xopt,
                                                   int widx, int useBN) {
    constexpr int TN = NC / 32;
    constexpr int ROWP = 136;
    extern __shared__ float smf[];
    float* Ws = smf;              // [128][NC]
    float* Xs = smf + 128 * NC;   // [128 k][ROWP rows]
    const float* X = Xopt ? Xopt : g_agg;
    const float* W = (widx == 0) ? g_Wm0 : (widx == 1) ? g_Wm1 : g_Wm2;

    const int tid = threadIdx.x;
    const int tx = tid & 31, ty = tid >> 5;
    const int row0 = blockIdx.x * 128;

    {   // W load (vectorized)
        float4* d = (float4*)Ws;
        const float4* s = (const float4*)W;
        for (int i = tid; i < NC * 32; i += 256) d[i] = s[i];
    }
    // X tile: transpose into Xs[k][row]; smem stores conflict-free (row varies per lane)
    for (int i = tid; i < 4096; i += 256) {
        int c4 = i >> 7, r = i & 127;
        int gr = row0 + r;
        float4 v = make_float4(0.f, 0.f, 0.f, 0.f);
        if (gr < NN) {
            v = ((const float4*)X)[gr * 32 + c4];
            if (useBN) {
                float4 sc = ((const float4*)g_scale)[c4];
                float4 sh = ((const float4*)g_shift)[c4];
                v.x = fmaxf(fmaf(v.x, sc.x, sh.x), 0.f);
                v.y = fmaxf(fmaf(v.y, sc.y, sh.y), 0.f);
                v.z = fmaxf(fmaf(v.z, sc.z, sh.z), 0.f);
                v.w = fmaxf(fmaf(v.w, sc.w, sh.w), 0.f);
            }
        }
        int c = 4 * c4;
        Xs[(c + 0) * ROWP + r] = v.x;
        Xs[(c + 1) * ROWP + r] = v.y;
        Xs[(c + 2) * ROWP + r] = v.z;
        Xs[(c + 3) * ROWP + r] = v.w;
    }
    __syncthreads();

    ull acc[8][TN];
    #pragma unroll
    for (int p = 0; p < 8; p++)
        #pragma unroll
        for (int j = 0; j < TN; j++) acc[p][j] = 0ull;

    const int rbase = ty * 16;
    #pragma unroll 4
    for (int k = 0; k < 128; k++) {
        ull xp[8];
        #pragma unroll
        for (int p = 0; p < 8; p++)
            xp[p] = *(const ull*)&Xs[k * ROWP + rbase + 2 * p];
        ull wv[TN];
        #pragma unroll
        for (int j = 0; j < TN; j++) {
            float w = Ws[k * NC + tx + 32 * j];
            wv[j] = pack2(w, w);
        }
        #pragma unroll
        for (int p = 0; p < 8; p++)
            #pragma unroll
            for (int j = 0; j < TN; j++)
                acc[p][j] = fma2(xp[p], wv[j], acc[p][j]);
    }

    #pragma unroll
    for (int p = 0; p < 8; p++) {
        int r0 = row0 + rbase + 2 * p;
        if (r0 < NN) {
            bool ok1 = (r0 + 1 < NN);
            #pragma unroll
            for (int j = 0; j < TN; j++) {
                float a, b; unpack2(acc[p][j], a, b);
                g_h[r0 * NC + tx + 32 * j] = a;
                if (ok1) g_h[(r0 + 1) * NC + tx + 32 * j] = b;
            }
        }
    }
}

// ---------------- attention logits, packed float4 per node ----------------
template<int D>
__global__ void a2_kernel(const float* __restrict__ att) {
    constexpr int NC = 4 * D, C = NC / 32;
    int idx = blockIdx.x * blockDim.x + threadIdx.x;
    int v = idx >> 5;
    int lane = threadIdx.x & 31;
    if (v >= NN) return;
    int c0 = lane * C;
    float as = 0.f, ad = 0.f;
    #pragma unroll
    for (int j = 0; j < C; j++) {
        float h = g_h[v * NC + c0 + j];
        as = fmaf(h, att[c0 + j], as);
        ad = fmaf(h, att[NC + c0 + j], ad);
    }
    #pragma unroll
    for (int o = 4; o; o >>= 1) {
        as += __shfl_xor_sync(0xffffffffu, as, o);
        ad += __shfl_xor_sync(0xffffffffu, ad, o);
    }
    float a0 = __shfl_sync(0xffffffffu, as, 0);
    float a1 = __shfl_sync(0xffffffffu, as, 8);
    float a2 = __shfl_sync(0xffffffffu, as, 16);
    float a3 = __shfl_sync(0xffffffffu, as, 24);
    float b0 = __shfl_sync(0xffffffffu, ad, 0);
    float b1 = __shfl_sync(0xffffffffu, ad, 8);
    float b2 = __shfl_sync(0xffffffffu, ad, 16);
    float b3 = __shfl_sync(0xffffffffu, ad, 24);
    if (lane == 0) g_as4[v] = make_float4(a0, a1, a2, a3);
    if (lane == 1) g_ad4[v] = make_float4(b0, b1, b2, b3);
}

// ---------------- softmax + aggregation (warp per node, smem alpha cache) ----------------
template<int C>
__device__ __forceinline__ void gather_step(int s, float alpha, float (&acc)[C], int lane) {
    if (C == 4) {
        float4 hv = ((const float4*)g_h)[s * 32 + lane];
        acc[0] = fmaf(hv.x, alpha, acc[0]);
        acc[1] = fmaf(hv.y, alpha, acc[1]);
        acc[2] = fmaf(hv.z, alpha, acc[2]);
        acc[3] = fmaf(hv.w, alpha, acc[3]);
    } else {
        #pragma unroll
        for (int j = 0; j < C; j++)
            acc[j] = fmaf(g_h[s * (32 * C) + lane * C + j], alpha, acc[j]);
    }
}

template<int D, bool MEAN>
__global__ void __launch_bounds__(256) agg_kernel(float* __restrict__ outMean) {
    constexpr int NC = 4 * D, C = NC / 32;
    __shared__ float4 ec[8][64];
    int w = threadIdx.x >> 5, lane = threadIdx.x & 31;
    int v = blockIdx.x * 8 + w;
    if (v >= NN) return;
    int start = g_rowptr[v];
    int deg = g_rowptr[v + 1] - start;
    int head = lane >> 3;

    if (deg == 0) {
        if (MEAN) {
            if (lane < 8) {
                #pragma unroll
                for (int j = 0; j < C; j++) outMean[v * D + lane * C + j] = 0.f;
            }
        } else {
            ((float4*)g_agg)[v * 32 + lane] = make_float4(0.f, 0.f, 0.f, 0.f);
        }
        return;
    }

    float4 ad = g_ad4[v];
    float acc[C];
    #pragma unroll
    for (int j = 0; j < C; j++) acc[j] = 0.f;

    float m0 = -CUDART_INF_F, m1 = m0, m2 = m0, m3 = m0;
    float d0 = 0.f, d1 = 0.f, d2 = 0.f, d3 = 0.f;

    if (deg <= 64) {
        int s0 = 0, s1 = 0;
        float4 e0, e1;
        if (lane < deg) {
            s0 = g_srcs[start + lane];
            float4 a = g_as4[s0];
            e0.x = lrelu(a.x + ad.x); e0.y = lrelu(a.y + ad.y);
            e0.z = lrelu(a.z + ad.z); e0.w = lrelu(a.w + ad.w);
            m0 = e0.x; m1 = e0.y; m2 = e0.z; m3 = e0.w;
        }
        if (lane + 32 < deg) {
            s1 = g_srcs[start + lane + 32];
            float4 a = g_as4[s1];
            e1.x = lrelu(a.x + ad.x); e1.y = lrelu(a.y + ad.y);
            e1.z = lrelu(a.z + ad.z); e1.w = lrelu(a.w + ad.w);
            m0 = fmaxf(m0, e1.x); m1 = fmaxf(m1, e1.y);
            m2 = fmaxf(m2, e1.z); m3 = fmaxf(m3, e1.w);
        }
        #pragma unroll
        for (int o = 16; o; o >>= 1) {
            m0 = fmaxf(m0, __shfl_xor_sync(0xffffffffu, m0, o));
            m1 = fmaxf(m1, __shfl_xor_sync(0xffffffffu, m1, o));
            m2 = fmaxf(m2, __shfl_xor_sync(0xffffffffu, m2, o));
            m3 = fmaxf(m3, __shfl_xor_sync(0xffffffffu, m3, o));
        }
        if (lane < deg) {
            float x0 = __expf(e0.x - m0), x1 = __expf(e0.y - m1);
            float x2 = __expf(e0.z - m2), x3 = __expf(e0.w - m3);
            ec[w][lane] = make_float4(x0, x1, x2, x3);
            d0 += x0; d1 += x1; d2 += x2; d3 += x3;
        }
        if (lane + 32 < deg) {
            float x0 = __expf(e1.x - m0), x1 = __expf(e1.y - m1);
            float x2 = __expf(e1.z - m2), x3 = __expf(e1.w - m3);
            ec[w][lane + 32] = make_float4(x0, x1, x2, x3);
            d0 += x0; d1 += x1; d2 += x2; d3 += x3;
        }
        #pragma unroll
        for (int o = 16; o; o >>= 1) {
            d0 += __shfl_xor_sync(0xffffffffu, d0, o);
            d1 += __shfl_xor_sync(0xffffffffu, d1, o);
            d2 += __shfl_xor_sync(0xffffffffu, d2, o);
            d3 += __shfl_xor_sync(0xffffffffu, d3, o);
        }
        float denh = (head == 0) ? d0 : (head == 1) ? d1 : (head == 2) ? d2 : d3;
        float invh = 1.f / (denh + 1e-16f);
        __syncwarp();
        for (int t = 0; t < deg; t++) {
            int s = __shfl_sync(0xffffffffu, (t < 32) ? s0 : s1, t & 31);
            float alpha = ((const float*)&ec[w][t])[head] * invh;
            gather_step<C>(s, alpha, acc, lane);
        }
    } else {
        // rare fallback: recompute path
        for (int i = lane; i < deg; i += 32) {
            int s = g_srcs[start + i];
            float4 a = g_as4[s];
            m0 = fmaxf(m0, lrelu(a.x + ad.x)); m1 = fmaxf(m1, lrelu(a.y + ad.y));
            m2 = fmaxf(m2, lrelu(a.z + ad.z)); m3 = fmaxf(m3, lrelu(a.w + ad.w));
        }
        #pragma unroll
        for (int o = 16; o; o >>= 1) {
            m0 = fmaxf(m0, __shfl_xor_sync(0xffffffffu, m0, o));
            m1 = fmaxf(m1, __shfl_xor_sync(0xffffffffu, m1, o));
            m2 = fmaxf(m2, __shfl_xor_sync(0xffffffffu, m2, o));
            m3 = fmaxf(m3, __shfl_xor_sync(0xffffffffu, m3, o));
        }
        for (int i = lane; i < deg; i += 32) {
            int s = g_srcs[start + i];
            float4 a = g_as4[s];
            d0 += __expf(lrelu(a.x + ad.x) - m0);
            d1 += __expf(lrelu(a.y + ad.y) - m1);
            d2 += __expf(lrelu(a.z + ad.z) - m2);
            d3 += __expf(lrelu(a.w + ad.w) - m3);
        }
        #pragma unroll
        for (int o = 16; o; o >>= 1) {
            d0 += __shfl_xor_sync(0xffffffffu, d0, o);
            d1 += __shfl_xor_sync(0xffffffffu, d1, o);
            d2 += __shfl_xor_sync(0xffffffffu, d2, o);
            d3 += __shfl_xor_sync(0xffffffffu, d3, o);
        }
        float denh = (head == 0) ? d0 : (head == 1) ? d1 : (head == 2) ? d2 : d3;
        float mxh  = (head == 0) ? m0 : (head == 1) ? m1 : (head == 2) ? m2 : m3;
        float adh  = (head == 0) ? ad.x : (head == 1) ? ad.y : (head == 2) ? ad.z : ad.w;
        float invh = 1.f / (denh + 1e-16f);
        for (int t = 0; t < deg; t++) {
            int s = g_srcs[start + t];
            float ash = ((const float*)&g_as4[s])[head];
            float e = lrelu(ash + adh);
            float alpha = __expf(e - mxh) * invh;
            gather_step<C>(s, alpha, acc, lane);
        }
    }

    if (MEAN) {
        #pragma unroll
        for (int j = 0; j < C; j++) {
            float a = acc[j];
            a += __shfl_xor_sync(0xffffffffu, a, 8);
            a += __shfl_xor_sync(0xffffffffu, a, 16);
            if (lane < 8) outMean[v * D + lane * C + j] = 0.25f * a;
        }
    } else {
        ((float4*)g_agg)[v * 32 + lane] = make_float4(acc[0], acc[1], acc[2], acc[3]);
    }
}

// ---------------- batch norm ----------------
__global__ void zero_bn_kernel() {
    int c = threadIdx.x;
    g_bnsum[c] = 0.f; g_bnsq[c] = 0.f;
}
__global__ void bnstats_kernel() {
    int c = threadIdx.x;
    float s = 0.f, q = 0.f;
    for (int r = blockIdx.x; r < NN; r += gridDim.x) {
        float x = g_agg[r * 128 + c];
        s += x; q = fmaf(x, x, q);
    }
    atomicAdd(&g_bnsum[c], s);
    atomicAdd(&g_bnsq[c], q);
}
__global__ void bnfinal_kernel(const float* __restrict__ gamma, const float* __restrict__ beta) {
    int c = threadIdx.x;
    float mu = g_bnsum[c] * (1.f / NN);
    float var = g_bnsq[c] * (1.f / NN) - mu * mu;
    float rstd = rsqrtf(var + 1e-5f);
    float sc = rstd * gamma[c];
    g_scale[c] = sc;
    g_shift[c] = fmaf(-mu, sc, beta[c]);
}

// ---------------- launch ----------------
extern "C" void kernel_launch(void* const* d_in, const int* in_sizes, int n_in,
                              void* d_out, int out_size) {
    (void)in_sizes; (void)n_in; (void)out_size;
    const float* x     = (const float*)d_in[0];
    const int*   ei    = (const int*)d_in[1];
    const float* w01   = (const float*)d_in[2];
    const float* s01   = (const float*)d_in[3];
    const float* att01 = (const float*)d_in[4];
    const float* w2    = (const float*)d_in[5];
    const float* s2    = (const float*)d_in[6];
    const float* att2  = (const float*)d_in[7];
    const float* gamma = (const float*)d_in[8];
    const float* beta  = (const float*)d_in[9];
    float* out = (float*)d_out;
    const int* srcp = ei;
    const int* dstp = ei + NE;

    const int THR_SMEM  = (53248 + 32) * 4;
    const int G128_SMEM = (128 * 128 + 128 * 136) * 4;   // 132 KB
    const int G160_SMEM = (128 * 160 + 128 * 136) * 4;   // 148 KB
    cudaFuncSetAttribute(thr_kernel, cudaFuncAttributeMaxDynamicSharedMemorySize, THR_SMEM);
    cudaFuncSetAttribute(gemm_kernel<128>, cudaFuncAttributeMaxDynamicSharedMemorySize, G128_SMEM);
    cudaFuncSetAttribute(gemm_kernel<160>, cudaFuncAttributeMaxDynamicSharedMemorySize, G160_SMEM);

    thr_kernel<<<1, 1024, THR_SMEM>>>(s01, s2);
    mask_kernel<<<(53248 + 255) / 256, 256>>>(w01, s01, w2, s2);

    zero_deg_kernel<<<(NN + 255) / 256, 256>>>();
    hist_kernel<<<(NE + 255) / 256, 256>>>(dstp);
    scan1_kernel<<<98, 1024>>>();
    scan2_kernel<<<1, 32>>>();
    scan3_kernel<<<98, 1024>>>();
    scatter_kernel<<<(NE + 255) / 256, 256>>>(srcp, dstp);

    const int GB = (NN + 127) / 128;       // 782
    const int WB = (NN + 7) / 8;           // 12500 (warp per node)

    // ---- layer 0 ----
    gemm_kernel<128><<<GB, 256, G128_SMEM>>>(x, 0, 0);
    a2_kernel<32><<<WB, 256>>>(att01);
    agg_kernel<32, false><<<WB, 256>>>(nullptr);
    zero_bn_kernel<<<1, 128>>>();
    bnstats_kernel<<<512, 128>>>();
    bnfinal_kernel<<<1, 128>>>(gamma, beta);

    // ---- layer 1 ----
    gemm_kernel<128><<<GB, 256, G128_SMEM>>>(nullptr, 1, 1);
    a2_kernel<32><<<WB, 256>>>(att01 + 256);
    agg_kernel<32, false><<<WB, 256>>>(nullptr);
    zero_bn_kernel<<<1, 128>>>();
    bnstats_kernel<<<512, 128>>>();
    bnfinal_kernel<<<1, 128>>>(gamma + 128, beta + 128);

    // ---- layer 2 ----
    gemm_kernel<160><<<GB, 256, G160_SMEM>>>(nullptr, 2, 1);
    a2_kernel<40><<<WB, 256>>>(att2);
    agg_kernel<40, true><<<WB, 256>>>(out);
}

// round 3
// speedup vs baseline: 1.4631x; 1.1627x over previous
#include <cuda_runtime.h>
#include <math_constants.h>

#define NN 100000
#define NE 1600000

typedef unsigned long long ull;

// ---------------- device scratch ----------------
__device__ float  g_h[NN * 160];
__device__ float  g_agg[NN * 128];
__device__ float4 g_as4[NN];
__device__ float4 g_ad4[NN];
__device__ int    g_deg[NN];          // zero at load; re-zeroed by scan3 each call
__device__ int    g_rowptr[NN + 1];
__device__ int    g_pos[NN];
__device__ int    g_srcs[NE];
__device__ float  g_Wm0[128 * 136];   // [128][128+8] masked W + a_src/a_dst cols
__device__ float  g_Wm1[128 * 136];
__device__ float  g_Wm2[128 * 168];   // [128][160+8]
__device__ float  g_thr;
__device__ float  g_bnsum[128], g_bnsq[128];
__device__ int    g_bsum[98], g_boff[98];

// ---------------- f32x2 helpers ----------------
__device__ __forceinline__ ull pack2(float a, float b) {
    ull r; asm("mov.b64 %0, {%1, %2};" : "=l"(r) : "f"(a), "f"(b)); return r;
}
__device__ __forceinline__ void unpack2(ull v, float& a, float& b) {
    asm("mov.b64 {%0, %1}, %2;" : "=f"(a), "=f"(b) : "l"(v));
}
__device__ __forceinline__ ull fma2(ull a, ull b, ull c) {
    ull d; asm("fma.rn.f32x2 %0, %1, %2, %3;" : "=l"(d) : "l"(a), "l"(b), "l"(c)); return d;
}
__device__ __forceinline__ float lrelu(float x) { return (x >= 0.f) ? x : 0.2f * x; }

// ---------------- exact percentile (bitwise radix rank-select) ----------------
__global__ void thr_kernel(const float* __restrict__ s01, const float* __restrict__ s2) {
    extern __shared__ unsigned sm[];
    unsigned* red = sm + 53248;
    int t = threadIdx.x;
    for (int i = t; i < 32768; i += 1024) sm[i] = __float_as_uint(fabsf(s01[i]));
    for (int i = t; i < 20480; i += 1024) sm[32768 + i] = __float_as_uint(fabsf(s2[i]));
    __syncthreads();
    unsigned prefix = 0;
    int k = 26624;
    for (int bit = 30; bit >= 0; --bit) {
        unsigned himask = 0xFFFFFFFEu << bit;
        unsigned bitm = 1u << bit;
        int cnt = 0;
        for (int i = t; i < 53248; i += 1024) {
            unsigned v = sm[i];
            cnt += ((((v ^ prefix) & himask) == 0u) && ((v & bitm) == 0u)) ? 1 : 0;
        }
        #pragma unroll
        for (int o = 16; o; o >>= 1) cnt += __shfl_xor_sync(0xffffffffu, cnt, o);
        if ((t & 31) == 0) red[t >> 5] = (unsigned)cnt;
        __syncthreads();
        int total = 0;
        #pragma unroll
        for (int w = 0; w < 32; w++) total += (int)red[w];
        if (k >= total) { prefix |= bitm; k -= total; }
        __syncthreads();
    }
    if (t == 0) g_thr = __uint_as_float(prefix);
}

// ---------------- masked weights (strided NC+8 layout) ----------------
__global__ void mask_kernel(const float* __restrict__ w01, const float* __restrict__ s01,
                            const float* __restrict__ w2, const float* __restrict__ s2) {
    float thr = g_thr;
    int i = blockIdx.x * blockDim.x + threadIdx.x;
    if (i < 16384) {
        int k = i >> 7, c = i & 127;
        g_Wm0[k * 136 + c] = (fabsf(s01[i]) < thr) ? 0.f : w01[i];
    } else if (i < 32768) {
        int j = i - 16384; int k = j >> 7, c = j & 127;
        g_Wm1[k * 136 + c] = (fabsf(s01[i]) < thr) ? 0.f : w01[i];
    } else if (i < 53248) {
        int j = i - 32768; int k = j / 160, c = j - k * 160;
        g_Wm2[k * 168 + c] = (fabsf(s2[j]) < thr) ? 0.f : w2[j];
    }
}

// ---------------- attention-folded extra columns: W @ att per head ----------------
__global__ void wext_kernel(const float* __restrict__ w01, const float* __restrict__ s01,
                            const float* __restrict__ att01,
                            const float* __restrict__ w2, const float* __restrict__ s2,
                            const float* __restrict__ att2) {
    float thr = g_thr;
    int t = threadIdx.x;               // 1024 = 128 k * 8 slots
    int k = t >> 3, slot = t & 7, sd = slot >> 2, h = slot & 3;
    #pragma unroll
    for (int L = 0; L < 2; L++) {
        float acc = 0.f;
        for (int d = 0; d < 32; d++) {
            int idx = L * 16384 + k * 128 + h * 32 + d;
            float w = (fabsf(s01[idx]) < thr) ? 0.f : w01[idx];
            acc = fmaf(w, att01[L * 256 + sd * 128 + h * 32 + d], acc);
        }
        (L ? g_Wm1 : g_Wm0)[k * 136 + 128 + slot] = acc;
    }
    {
        float acc = 0.f;
        for (int d = 0; d < 40; d++) {
            int idx = k * 160 + h * 40 + d;
            float w = (fabsf(s2[idx]) < thr) ? 0.f : w2[idx];
            acc = fmaf(w, att2[sd * 160 + h * 40 + d], acc);
        }
        g_Wm2[k * 168 + 160 + slot] = acc;
    }
}

// ---------------- CSR build ----------------
__global__ void hist_kernel(const int* __restrict__ dst) {
    int e = blockIdx.x * blockDim.x + threadIdx.x;
    if (e < NE) atomicAdd(&g_deg[dst[e]], 1);
}
__global__ void scan1_kernel() {
    __shared__ int red[32];
    int t = threadIdx.x, b = blockIdx.x;
    int i = b * 1024 + t;
    int s = (i < NN) ? g_deg[i] : 0;
    #pragma unroll
    for (int o = 16; o; o >>= 1) s += __shfl_xor_sync(0xffffffffu, s, o);
    if ((t & 31) == 0) red[t >> 5] = s;
    __syncthreads();
    if (t < 32) {
        int x = red[t];
        #pragma unroll
        for (int o = 16; o; o >>= 1) x += __shfl_xor_sync(0xffffffffu, x, o);
        if (t == 0) g_bsum[b] = x;
    }
}
__global__ void scan2_kernel() {
    if (threadIdx.x == 0) {
        int run = 0;
        for (int b = 0; b < 98; b++) { g_boff[b] = run; run += g_bsum[b]; }
        g_rowptr[NN] = run;
    }
}
__global__ void scan3_kernel() {   // local scan + writeback + re-zero deg for next call
    __shared__ int sm[1024];
    int t = threadIdx.x, b = blockIdx.x;
    int i = b * 1024 + t;
    int v = (i < NN) ? g_deg[i] : 0;
    sm[t] = v;
    __syncthreads();
    for (int off = 1; off < 1024; off <<= 1) {
        int x = (t >= off) ? sm[t - off] : 0;
        __syncthreads();
        sm[t] += x;
        __syncthreads();
    }
    if (i < NN) {
        int excl = sm[t] - v + g_boff[b];
        g_rowptr[i] = excl;
        g_pos[i] = excl;
        g_deg[i] = 0;
    }
}
__global__ void scatter_kernel(const int* __restrict__ src, const int* __restrict__ dst) {
    int e = blockIdx.x * blockDim.x + threadIdx.x;
    if (e < NE) {
        int d = dst[e];
        int p = atomicAdd(&g_pos[d], 1);
        g_srcs[p] = src[e];
    }
}

// ---------------- fused GEMM + BN/ReLU prologue + attention-logit epilogue ----------
template<int NC>
__global__ void __launch_bounds__(256) gemm_kernel(const float* __restrict__ Xopt,
                                                   int widx, int useBN,
                                                   const float* __restrict__ gamma,
                                                   const float* __restrict__ beta) {
    constexpr int TN = NC / 32;
    constexpr int NCP = NC + 8;
    constexpr int ROWP = 136;
    extern __shared__ float smf[];
    float* Ws = smf;                          // [128][NCP]
    float* Xs = smf + 128 * NCP;              // [128 k][ROWP]
    float* SC = smf + 128 * NCP + 128 * ROWP; // [128] bn scale
    float* SH = SC + 128;                     // [128] bn shift
    const float* X = Xopt ? Xopt : g_agg;
    const float* W = (widx == 0) ? g_Wm0 : (widx == 1) ? g_Wm1 : g_Wm2;

    const int tid = threadIdx.x;
    const int tx = tid & 31, ty = tid >> 5;
    const int row0 = blockIdx.x * 128;

    if (useBN && tid < 128) {
        float mu = g_bnsum[tid] * (1.f / NN);
        float var = g_bnsq[tid] * (1.f / NN) - mu * mu;
        float sc = rsqrtf(var + 1e-5f) * gamma[tid];
        SC[tid] = sc;
        SH[tid] = fmaf(-mu, sc, beta[tid]);
    }
    if (useBN) __syncthreads();

    {   // W load
        float4* d = (float4*)Ws;
        const float4* s = (const float4*)W;
        for (int i = tid; i < NCP * 32; i += 256) d[i] = s[i];
    }
    // X tile -> transposed Xs[k][row], fused BN+ReLU
    for (int i = tid; i < 4096; i += 256) {
        int c4 = i >> 7, r = i & 127;
        int gr = row0 + r;
        float4 v = make_float4(0.f, 0.f, 0.f, 0.f);
        if (gr < NN) {
            v = ((const float4*)X)[gr * 32 + c4];
            if (useBN) {
                float4 sc = ((const float4*)SC)[c4];
                float4 sh = ((const float4*)SH)[c4];
                v.x = fmaxf(fmaf(v.x, sc.x, sh.x), 0.f);
                v.y = fmaxf(fmaf(v.y, sc.y, sh.y), 0.f);
                v.z = fmaxf(fmaf(v.z, sc.z, sh.z), 0.f);
                v.w = fmaxf(fmaf(v.w, sc.w, sh.w), 0.f);
            }
        }
        int c = 4 * c4;
        Xs[(c + 0) * ROWP + r] = v.x;
        Xs[(c + 1) * ROWP + r] = v.y;
        Xs[(c + 2) * ROWP + r] = v.z;
        Xs[(c + 3) * ROWP + r] = v.w;
    }
    __syncthreads();

    ull acc[8][TN];
    ull acce[8];
    #pragma unroll
    for (int p = 0; p < 8; p++) {
        acce[p] = 0ull;
        #pragma unroll
        for (int j = 0; j < TN; j++) acc[p][j] = 0ull;
    }

    const int rbase = ty * 16;
    const int ecol = NC + (tx & 7);
    #pragma unroll 4
    for (int k = 0; k < 128; k++) {
        ull xp[8];
        #pragma unroll
        for (int p = 0; p < 8; p++)
            xp[p] = *(const ull*)&Xs[k * ROWP + rbase + 2 * p];
        ull wv[TN];
        #pragma unroll
        for (int j = 0; j < TN; j++) {
            float w = Ws[k * NCP + tx + 32 * j];
            wv[j] = pack2(w, w);
        }
        float we = Ws[k * NCP + ecol];
        ull wev = pack2(we, we);
        #pragma unroll
        for (int p = 0; p < 8; p++) {
            #pragma unroll
            for (int j = 0; j < TN; j++)
                acc[p][j] = fma2(xp[p], wv[j], acc[p][j]);
            acce[p] = fma2(xp[p], wev, acce[p]);
        }
    }

    const int lane = tx;
    #pragma unroll
    for (int p = 0; p < 8; p++) {
        int rA = row0 + rbase + 2 * p;
        int rB = rA + 1;
        if (rA < NN) {
            bool okB = (rB < NN);
            #pragma unroll
            for (int j = 0; j < TN; j++) {
                float a, b; unpack2(acc[p][j], a, b);
                g_h[rA * NC + tx + 32 * j] = a;
                if (okB) g_h[rB * NC + tx + 32 * j] = b;
            }
        }
        // attention logits: lanes 0..3 hold a_src heads, 4..7 a_dst heads (mod 8)
        ull t0 = __shfl_sync(0xffffffffu, acce[p], 0);
        ull t1 = __shfl_sync(0xffffffffu, acce[p], 1);
        ull t2 = __shfl_sync(0xffffffffu, acce[p], 2);
        ull t3 = __shfl_sync(0xffffffffu, acce[p], 3);
        ull t4 = __shfl_sync(0xffffffffu, acce[p], 4);
        ull t5 = __shfl_sync(0xffffffffu, acce[p], 5);
        ull t6 = __shfl_sync(0xffffffffu, acce[p], 6);
        ull t7 = __shfl_sync(0xffffffffu, acce[p], 7);
        float l0,h0,l1,h1,l2,h2,l3,h3,l4,h4,l5,h5,l6,h6,l7,h7;
        unpack2(t0,l0,h0); unpack2(t1,l1,h1); unpack2(t2,l2,h2); unpack2(t3,l3,h3);
        unpack2(t4,l4,h4); unpack2(t5,l5,h5); unpack2(t6,l6,h6); unpack2(t7,l7,h7);
        if (lane == 0 && rA < NN) g_as4[rA] = make_float4(l0, l1, l2, l3);
        if (lane == 1 && rB < NN) g_as4[rB] = make_float4(h0, h1, h2, h3);
        if (lane == 2 && rA < NN) g_ad4[rA] = make_float4(l4, l5, l6, l7);
        if (lane == 3 && rB < NN) g_ad4[rB] = make_float4(h4, h5, h6, h7);
    }
}

// ---------------- softmax + aggregation (+fused BN partial sums) ----------------
template<int C>
__device__ __forceinline__ void gather_step(int s, float alpha, float (&acc)[C], int lane) {
    if (C == 4) {
        float4 hv = ((const float4*)g_h)[s * 32 + lane];
        acc[0] = fmaf(hv.x, alpha, acc[0]);
        acc[1] = fmaf(hv.y, alpha, acc[1]);
        acc[2] = fmaf(hv.z, alpha, acc[2]);
        acc[3] = fmaf(hv.w, alpha, acc[3]);
    } else {
        #pragma unroll
        for (int j = 0; j < C; j++)
            acc[j] = fmaf(g_h[s * (32 * C) + lane * C + j], alpha, acc[j]);
    }
}

template<int D, bool MEAN>
__global__ void __launch_bounds__(256) agg_kernel(float* __restrict__ outMean) {
    constexpr int NC = 4 * D, C = NC / 32;
    __shared__ int    ssrc[8][64];
    __shared__ float4 ealpha[8][64];
    __shared__ float4 bnS[8][32];
    __shared__ float4 bnQ[8][32];
    int w = threadIdx.x >> 5, lane = threadIdx.x & 31;
    int v = blockIdx.x * 8 + w;               // grid = NN/8 exactly
    int head = lane >> 3;
    int start = g_rowptr[v];
    int deg = g_rowptr[v + 1] - start;
    float4 ad = g_ad4[v];

    float acc[C];
    #pragma unroll
    for (int j = 0; j < C; j++) acc[j] = 0.f;

    if (deg > 0 && deg <= 64) {
        int s0 = 0, s1 = 0;
        float4 e0, e1;
        bool h0 = lane < deg, h1 = lane + 32 < deg;
        float m0 = -CUDART_INF_F, m1 = m0, m2 = m0, m3 = m0;
        if (h0) {
            s0 = g_srcs[start + lane];
            float4 a = g_as4[s0];
            e0.x = lrelu(a.x + ad.x); e0.y = lrelu(a.y + ad.y);
            e0.z = lrelu(a.z + ad.z); e0.w = lrelu(a.w + ad.w);
            m0 = e0.x; m1 = e0.y; m2 = e0.z; m3 = e0.w;
        }
        if (h1) {
            s1 = g_srcs[start + lane + 32];
            float4 a = g_as4[s1];
            e1.x = lrelu(a.x + ad.x); e1.y = lrelu(a.y + ad.y);
            e1.z = lrelu(a.z + ad.z); e1.w = lrelu(a.w + ad.w);
            m0 = fmaxf(m0, e1.x); m1 = fmaxf(m1, e1.y);
            m2 = fmaxf(m2, e1.z); m3 = fmaxf(m3, e1.w);
        }
        #pragma unroll
        for (int o = 16; o; o >>= 1) {
            m0 = fmaxf(m0, __shfl_xor_sync(0xffffffffu, m0, o));
            m1 = fmaxf(m1, __shfl_xor_sync(0xffffffffu, m1, o));
            m2 = fmaxf(m2, __shfl_xor_sync(0xffffffffu, m2, o));
            m3 = fmaxf(m3, __shfl_xor_sync(0xffffffffu, m3, o));
        }
        float d0 = 0.f, d1 = 0.f, d2 = 0.f, d3 = 0.f;
        float x00=0,x01=0,x02=0,x03=0, x10=0,x11=0,x12=0,x13=0;
        if (h0) {
            x00 = __expf(e0.x - m0); x01 = __expf(e0.y - m1);
            x02 = __expf(e0.z - m2); x03 = __expf(e0.w - m3);
            d0 += x00; d1 += x01; d2 += x02; d3 += x03;
        }
        if (h1) {
            x10 = __expf(e1.x - m0); x11 = __expf(e1.y - m1);
            x12 = __expf(e1.z - m2); x13 = __expf(e1.w - m3);
            d0 += x10; d1 += x11; d2 += x12; d3 += x13;
        }
        #pragma unroll
        for (int o = 16; o; o >>= 1) {
            d0 += __shfl_xor_sync(0xffffffffu, d0, o);
            d1 += __shfl_xor_sync(0xffffffffu, d1, o);
            d2 += __shfl_xor_sync(0xffffffffu, d2, o);
            d3 += __shfl_xor_sync(0xffffffffu, d3, o);
        }
        float i0 = 1.f / (d0 + 1e-16f), i1 = 1.f / (d1 + 1e-16f);
        float i2 = 1.f / (d2 + 1e-16f), i3 = 1.f / (d3 + 1e-16f);
        if (h0) {
            ssrc[w][lane] = s0;
            ealpha[w][lane] = make_float4(x00 * i0, x01 * i1, x02 * i2, x03 * i3);
        }
        if (h1) {
            ssrc[w][lane + 32] = s1;
            ealpha[w][lane + 32] = make_float4(x10 * i0, x11 * i1, x12 * i2, x13 * i3);
        }
        __syncwarp();
        for (int t = 0; t < deg; t++) {
            int s = ssrc[w][t];
            float alpha = ((const float*)&ealpha[w][t])[head];
            gather_step<C>(s, alpha, acc, lane);
        }
    } else if (deg > 64) {   // rare fallback
        float m0 = -CUDART_INF_F, m1 = m0, m2 = m0, m3 = m0;
        for (int i = lane; i < deg; i += 32) {
            int s = g_srcs[start + i];
            float4 a = g_as4[s];
            m0 = fmaxf(m0, lrelu(a.x + ad.x)); m1 = fmaxf(m1, lrelu(a.y + ad.y));
            m2 = fmaxf(m2, lrelu(a.z + ad.z)); m3 = fmaxf(m3, lrelu(a.w + ad.w));
        }
        #pragma unroll
        for (int o = 16; o; o >>= 1) {
            m0 = fmaxf(m0, __shfl_xor_sync(0xffffffffu, m0, o));
            m1 = fmaxf(m1, __shfl_xor_sync(0xffffffffu, m1, o));
            m2 = fmaxf(m2, __shfl_xor_sync(0xffffffffu, m2, o));
            m3 = fmaxf(m3, __shfl_xor_sync(0xffffffffu, m3, o));
        }
        float d0 = 0.f, d1 = 0.f, d2 = 0.f, d3 = 0.f;
        for (int i = lane; i < deg; i += 32) {
            int s = g_srcs[start + i];
            float4 a = g_as4[s];
            d0 += __expf(lrelu(a.x + ad.x) - m0);
            d1 += __expf(lrelu(a.y + ad.y) - m1);
            d2 += __expf(lrelu(a.z + ad.z) - m2);
            d3 += __expf(lrelu(a.w + ad.w) - m3);
        }
        #pragma unroll
        for (int o = 16; o; o >>= 1) {
            d0 += __shfl_xor_sync(0xffffffffu, d0, o);
            d1 += __shfl_xor_sync(0xffffffffu, d1, o);
            d2 += __shfl_xor_sync(0xffffffffu, d2, o);
            d3 += __shfl_xor_sync(0xffffffffu, d3, o);
        }
        float denh = (head == 0) ? d0 : (head == 1) ? d1 : (head == 2) ? d2 : d3;
        float mxh  = (head == 0) ? m0 : (head == 1) ? m1 : (head == 2) ? m2 : m3;
        float adh  = (head == 0) ? ad.x : (head == 1) ? ad.y : (head == 2) ? ad.z : ad.w;
        float invh = 1.f / (denh + 1e-16f);
        for (int t = 0; t < deg; t++) {
            int s = g_srcs[start + t];
            float ash = ((const float*)&g_as4[s])[head];
            float alpha = __expf(lrelu(ash + adh) - mxh) * invh;
            gather_step<C>(s, alpha, acc, lane);
        }
    }

    if (MEAN) {
        #pragma unroll
        for (int j = 0; j < C; j++) {
            float a = acc[j];
            a += __shfl_xor_sync(0xffffffffu, a, 8);
            a += __shfl_xor_sync(0xffffffffu, a, 16);
            if (lane < 8) outMean[v * D + lane * C + j] = 0.25f * a;
        }
    } else {
        float4 a4 = make_float4(acc[0], acc[1], acc[2], acc[3]);
        ((float4*)g_agg)[v * 32 + lane] = a4;
        bnS[w][lane] = a4;
        bnQ[w][lane] = make_float4(a4.x * a4.x, a4.y * a4.y, a4.z * a4.z, a4.w * a4.w);
        __syncthreads();
        int t = threadIdx.x;
        if (t < 128) {
            float s = 0.f;
            #pragma unroll
            for (int i = 0; i < 8; i++) s += ((const float*)&bnS[i][t >> 2])[t & 3];
            atomicAdd(&g_bnsum[t], s);
        } else {
            int c = t - 128;
            float q = 0.f;
            #pragma unroll
            for (int i = 0; i < 8; i++) q += ((const float*)&bnQ[i][c >> 2])[c & 3];
            atomicAdd(&g_bnsq[c], q);
        }
    }
}

__global__ void zero_bn_kernel() {
    int c = threadIdx.x;
    g_bnsum[c] = 0.f; g_bnsq[c] = 0.f;
}

// ---------------- launch ----------------
extern "C" void kernel_launch(void* const* d_in, const int* in_sizes, int n_in,
                              void* d_out, int out_size) {
    (void)in_sizes; (void)n_in; (void)out_size;
    const float* x     = (const float*)d_in[0];
    const int*   ei    = (const int*)d_in[1];
    const float* w01   = (const float*)d_in[2];
    const float* s01   = (const float*)d_in[3];
    const float* att01 = (const float*)d_in[4];
    const float* w2    = (const float*)d_in[5];
    const float* s2    = (const float*)d_in[6];
    const float* att2  = (const float*)d_in[7];
    const float* gamma = (const float*)d_in[8];
    const float* beta  = (const float*)d_in[9];
    float* out = (float*)d_out;
    const int* srcp = ei;
    const int* dstp = ei + NE;

    const int THR_SMEM  = (53248 + 32) * 4;
    const int G128_SMEM = (128 * 136 + 128 * 136 + 256) * 4;   // ~137 KB
    const int G160_SMEM = (128 * 168 + 128 * 136 + 256) * 4;   // ~153 KB
    cudaFuncSetAttribute(thr_kernel, cudaFuncAttributeMaxDynamicSharedMemorySize, THR_SMEM);
    cudaFuncSetAttribute(gemm_kernel<128>, cudaFuncAttributeMaxDynamicSharedMemorySize, G128_SMEM);
    cudaFuncSetAttribute(gemm_kernel<160>, cudaFuncAttributeMaxDynamicSharedMemorySize, G160_SMEM);

    const int GB = (NN + 127) / 128;   // 782
    const int AB = NN / 8;             // 12500

    thr_kernel<<<1, 1024, THR_SMEM>>>(s01, s2);
    mask_kernel<<<208, 256>>>(w01, s01, w2, s2);
    wext_kernel<<<1, 1024>>>(w01, s01, att01, w2, s2, att2);
    // launch #4 -> ncu capture slot
    gemm_kernel<128><<<GB, 256, G128_SMEM>>>(x, 0, 0, gamma, beta);

    hist_kernel<<<(NE + 255) / 256, 256>>>(dstp);
    scan1_kernel<<<98, 1024>>>();
    scan2_kernel<<<1, 32>>>();
    scan3_kernel<<<98, 1024>>>();
    scatter_kernel<<<(NE + 255) / 256, 256>>>(srcp, dstp);

    zero_bn_kernel<<<1, 128>>>();
    agg_kernel<32, false><<<AB, 256>>>(nullptr);

    gemm_kernel<128><<<GB, 256, G128_SMEM>>>(nullptr, 1, 1, gamma, beta);
    zero_bn_kernel<<<1, 128>>>();
    agg_kernel<32, false><<<AB, 256>>>(nullptr);

    gemm_kernel<160><<<GB, 256, G160_SMEM>>>(nullptr, 2, 1, gamma + 128, beta + 128);
    agg_kernel<40, true><<<AB, 256>>>(out);
}

// round 4
// speedup vs baseline: 1.5809x; 1.0805x over previous
#include <cuda_runtime.h>
#include <math_constants.h>

#define NN 100000
#define NE 1600000

typedef unsigned long long ull;

// ---------------- device scratch ----------------
__device__ float  g_h[NN * 160];
__device__ float  g_agg[NN * 128];
__device__ float4 g_as4[NN];
__device__ float4 g_ad4[NN];
__device__ int    g_deg[NN];          // zero at load; re-zeroed by scan3 each call
__device__ int    g_rowptr[NN + 1];
__device__ int    g_pos[NN];
__device__ int    g_srcs[NE];
__device__ float  g_Wm0[128 * 136];   // [128][128+8] masked W + a_src/a_dst cols
__device__ float  g_Wm1[128 * 136];
__device__ float  g_Wm2[128 * 168];   // [128][160+8]
__device__ float  g_thr;
__device__ float  g_bnsum[128], g_bnsq[128];
__device__ int    g_bsum[98], g_boff[98];

// ---------------- f32x2 helpers ----------------
__device__ __forceinline__ ull pack2(float a, float b) {
    ull r; asm("mov.b64 %0, {%1, %2};" : "=l"(r) : "f"(a), "f"(b)); return r;
}
__device__ __forceinline__ void unpack2(ull v, float& a, float& b) {
    asm("mov.b64 {%0, %1}, %2;" : "=f"(a), "=f"(b) : "l"(v));
}
__device__ __forceinline__ ull fma2(ull a, ull b, ull c) {
    ull d; asm("fma.rn.f32x2 %0, %1, %2, %3;" : "=l"(d) : "l"(a), "l"(b), "l"(c)); return d;
}
__device__ __forceinline__ float lrelu(float x) { return (x >= 0.f) ? x : 0.2f * x; }

// ---------------- exact percentile (bitwise radix rank-select) ----------------
__global__ void thr_kernel(const float* __restrict__ s01, const float* __restrict__ s2) {
    extern __shared__ unsigned sm[];
    unsigned* red = sm + 53248;
    int t = threadIdx.x;
    for (int i = t; i < 32768; i += 1024) sm[i] = __float_as_uint(fabsf(s01[i]));
    for (int i = t; i < 20480; i += 1024) sm[32768 + i] = __float_as_uint(fabsf(s2[i]));
    __syncthreads();
    unsigned prefix = 0;
    int k = 26624;
    for (int bit = 30; bit >= 0; --bit) {
        unsigned himask = 0xFFFFFFFEu << bit;
        unsigned bitm = 1u << bit;
        int cnt = 0;
        for (int i = t; i < 53248; i += 1024) {
            unsigned v = sm[i];
            cnt += ((((v ^ prefix) & himask) == 0u) && ((v & bitm) == 0u)) ? 1 : 0;
        }
        #pragma unroll
        for (int o = 16; o; o >>= 1) cnt += __shfl_xor_sync(0xffffffffu, cnt, o);
        if ((t & 31) == 0) red[t >> 5] = (unsigned)cnt;
        __syncthreads();
        int total = 0;
        #pragma unroll
        for (int w = 0; w < 32; w++) total += (int)red[w];
        if (k >= total) { prefix |= bitm; k -= total; }
        __syncthreads();
    }
    if (t == 0) g_thr = __uint_as_float(prefix);
}

// ---------------- masked weights (strided NC+8 layout) ----------------
__global__ void mask_kernel(const float* __restrict__ w01, const float* __restrict__ s01,
                            const float* __restrict__ w2, const float* __restrict__ s2) {
    float thr = g_thr;
    int i = blockIdx.x * blockDim.x + threadIdx.x;
    if (i < 16384) {
        int k = i >> 7, c = i & 127;
        g_Wm0[k * 136 + c] = (fabsf(s01[i]) < thr) ? 0.f : w01[i];
    } else if (i < 32768) {
        int j = i - 16384; int k = j >> 7, c = j & 127;
        g_Wm1[k * 136 + c] = (fabsf(s01[i]) < thr) ? 0.f : w01[i];
    } else if (i < 53248) {
        int j = i - 32768; int k = j / 160, c = j - k * 160;
        g_Wm2[k * 168 + c] = (fabsf(s2[j]) < thr) ? 0.f : w2[j];
    }
}

// ---------------- attention-folded extra columns: W @ att per head ----------------
__global__ void wext_kernel(const float* __restrict__ w01, const float* __restrict__ s01,
                            const float* __restrict__ att01,
                            const float* __restrict__ w2, const float* __restrict__ s2,
                            const float* __restrict__ att2) {
    float thr = g_thr;
    int t = threadIdx.x;               // 1024 = 128 k * 8 slots
    int k = t >> 3, slot = t & 7, sd = slot >> 2, h = slot & 3;
    #pragma unroll
    for (int L = 0; L < 2; L++) {
        float acc = 0.f;
        for (int d = 0; d < 32; d++) {
            int idx = L * 16384 + k * 128 + h * 32 + d;
            float w = (fabsf(s01[idx]) < thr) ? 0.f : w01[idx];
            acc = fmaf(w, att01[L * 256 + sd * 128 + h * 32 + d], acc);
        }
        (L ? g_Wm1 : g_Wm0)[k * 136 + 128 + slot] = acc;
    }
    {
        float acc = 0.f;
        for (int d = 0; d < 40; d++) {
            int idx = k * 160 + h * 40 + d;
            float w = (fabsf(s2[idx]) < thr) ? 0.f : w2[idx];
            acc = fmaf(w, att2[sd * 160 + h * 40 + d], acc);
        }
        g_Wm2[k * 168 + 160 + slot] = acc;
    }
}

// ---------------- CSR build ----------------
__global__ void hist_kernel(const int* __restrict__ dst) {
    int e = blockIdx.x * blockDim.x + threadIdx.x;
    if (e < NE) atomicAdd(&g_deg[dst[e]], 1);
}
__global__ void scan1_kernel() {
    __shared__ int red[32];
    int t = threadIdx.x, b = blockIdx.x;
    int i = b * 1024 + t;
    int s = (i < NN) ? g_deg[i] : 0;
    #pragma unroll
    for (int o = 16; o; o >>= 1) s += __shfl_xor_sync(0xffffffffu, s, o);
    if ((t & 31) == 0) red[t >> 5] = s;
    __syncthreads();
    if (t < 32) {
        int x = red[t];
        #pragma unroll
        for (int o = 16; o; o >>= 1) x += __shfl_xor_sync(0xffffffffu, x, o);
        if (t == 0) g_bsum[b] = x;
    }
}
__global__ void scan2_kernel() {
    if (threadIdx.x == 0) {
        int run = 0;
        for (int b = 0; b < 98; b++) { g_boff[b] = run; run += g_bsum[b]; }
        g_rowptr[NN] = run;
    }
}
__global__ void scan3_kernel() {   // local scan + writeback + re-zero deg for next call
    __shared__ int sm[1024];
    int t = threadIdx.x, b = blockIdx.x;
    int i = b * 1024 + t;
    int v = (i < NN) ? g_deg[i] : 0;
    sm[t] = v;
    __syncthreads();
    for (int off = 1; off < 1024; off <<= 1) {
        int x = (t >= off) ? sm[t - off] : 0;
        __syncthreads();
        sm[t] += x;
        __syncthreads();
    }
    if (i < NN) {
        int excl = sm[t] - v + g_boff[b];
        g_rowptr[i] = excl;
        g_pos[i] = excl;
        g_deg[i] = 0;
    }
}
__global__ void scatter_kernel(const int* __restrict__ src, const int* __restrict__ dst) {
    int e = blockIdx.x * blockDim.x + threadIdx.x;
    if (e < NE) {
        int d = dst[e];
        int p = atomicAdd(&g_pos[d], 1);
        g_srcs[p] = src[e];
    }
}

// ---------------- fused GEMM, K-chunked for 2 CTAs/SM -------------------------
// K processed in 2 chunks of 64: Ws[64][NCP] + Xs[64][ROWP] resident -> ~69-77KB
// smem -> 2 CTAs/SM (16 warps) for latency hiding. Accumulators live across chunks.
template<int NC>
__global__ void __launch_bounds__(256, 2) gemm_kernel(const float* __restrict__ Xopt,
                                                      int widx, int useBN,
                                                      const float* __restrict__ gamma,
                                                      const float* __restrict__ beta) {
    constexpr int TN = NC / 32;
    constexpr int NCP = NC + 8;
    constexpr int ROWP = 136;
    extern __shared__ float smf[];
    float* Ws = smf;                         // [64][NCP]
    float* Xs = smf + 64 * NCP;              // [64 k][ROWP]
    float* SC = smf + 64 * NCP + 64 * ROWP;  // [128]
    float* SH = SC + 128;                    // [128]
    const float* X = Xopt ? Xopt : g_agg;
    const float* W = (widx == 0) ? g_Wm0 : (widx == 1) ? g_Wm1 : g_Wm2;

    const int tid = threadIdx.x;
    const int tx = tid & 31, ty = tid >> 5;
    const int row0 = blockIdx.x * 128;

    if (useBN && tid < 128) {
        float mu = g_bnsum[tid] * (1.f / NN);
        float var = g_bnsq[tid] * (1.f / NN) - mu * mu;
        float sc = rsqrtf(var + 1e-5f) * gamma[tid];
        SC[tid] = sc;
        SH[tid] = fmaf(-mu, sc, beta[tid]);
    }
    if (useBN) __syncthreads();

    ull acc[8][TN];
    ull acce[8];
    #pragma unroll
    for (int p = 0; p < 8; p++) {
        acce[p] = 0ull;
        #pragma unroll
        for (int j = 0; j < TN; j++) acc[p][j] = 0ull;
    }

    const int rbase = ty * 16;
    const int ecol = NC + (tx & 7);

    for (int kc = 0; kc < 2; kc++) {
        {   // W chunk: rows [kc*64, kc*64+64)
            float4* d = (float4*)Ws;
            const float4* s = (const float4*)W + kc * 16 * NCP;
            for (int i = tid; i < NCP * 16; i += 256) d[i] = s[i];
        }
        // X chunk: columns [kc*64, kc*64+64) transposed, fused BN+ReLU
        for (int i = tid; i < 2048; i += 256) {
            int c4l = i >> 7, r = i & 127;
            int c4 = kc * 16 + c4l;
            int gr = row0 + r;
            float4 v = make_float4(0.f, 0.f, 0.f, 0.f);
            if (gr < NN) {
                v = ((const float4*)X)[gr * 32 + c4];
                if (useBN) {
                    float4 sc = ((const float4*)SC)[c4];
                    float4 sh = ((const float4*)SH)[c4];
                    v.x = fmaxf(fmaf(v.x, sc.x, sh.x), 0.f);
                    v.y = fmaxf(fmaf(v.y, sc.y, sh.y), 0.f);
                    v.z = fmaxf(fmaf(v.z, sc.z, sh.z), 0.f);
                    v.w = fmaxf(fmaf(v.w, sc.w, sh.w), 0.f);
                }
            }
            int c = 4 * c4l;
            Xs[(c + 0) * ROWP + r] = v.x;
            Xs[(c + 1) * ROWP + r] = v.y;
            Xs[(c + 2) * ROWP + r] = v.z;
            Xs[(c + 3) * ROWP + r] = v.w;
        }
        __syncthreads();

        #pragma unroll 4
        for (int kk = 0; kk < 64; kk++) {
            ull xp[8];
            #pragma unroll
            for (int p = 0; p < 8; p++)
                xp[p] = *(const ull*)&Xs[kk * ROWP + rbase + 2 * p];
            ull wv[TN];
            #pragma unroll
            for (int j = 0; j < TN; j++) {
                float w = Ws[kk * NCP + tx + 32 * j];
                wv[j] = pack2(w, w);
            }
            float we = Ws[kk * NCP + ecol];
            ull wev = pack2(we, we);
            #pragma unroll
            for (int p = 0; p < 8; p++) {
                #pragma unroll
                for (int j = 0; j < TN; j++)
                    acc[p][j] = fma2(xp[p], wv[j], acc[p][j]);
                acce[p] = fma2(xp[p], wev, acce[p]);
            }
        }
        __syncthreads();
    }

    const int lane = tx;
    #pragma unroll
    for (int p = 0; p < 8; p++) {
        int rA = row0 + rbase + 2 * p;
        int rB = rA + 1;
        if (rA < NN) {
            bool okB = (rB < NN);
            #pragma unroll
            for (int j = 0; j < TN; j++) {
                float a, b; unpack2(acc[p][j], a, b);
                g_h[rA * NC + tx + 32 * j] = a;
                if (okB) g_h[rB * NC + tx + 32 * j] = b;
            }
        }
        ull t0 = __shfl_sync(0xffffffffu, acce[p], 0);
        ull t1 = __shfl_sync(0xffffffffu, acce[p], 1);
        ull t2 = __shfl_sync(0xffffffffu, acce[p], 2);
        ull t3 = __shfl_sync(0xffffffffu, acce[p], 3);
        ull t4 = __shfl_sync(0xffffffffu, acce[p], 4);
        ull t5 = __shfl_sync(0xffffffffu, acce[p], 5);
        ull t6 = __shfl_sync(0xffffffffu, acce[p], 6);
        ull t7 = __shfl_sync(0xffffffffu, acce[p], 7);
        float l0,h0,l1,h1,l2,h2,l3,h3,l4,h4,l5,h5,l6,h6,l7,h7;
        unpack2(t0,l0,h0); unpack2(t1,l1,h1); unpack2(t2,l2,h2); unpack2(t3,l3,h3);
        unpack2(t4,l4,h4); unpack2(t5,l5,h5); unpack2(t6,l6,h6); unpack2(t7,l7,h7);
        if (lane == 0 && rA < NN) g_as4[rA] = make_float4(l0, l1, l2, l3);
        if (lane == 1 && rB < NN) g_as4[rB] = make_float4(h0, h1, h2, h3);
        if (lane == 2 && rA < NN) g_ad4[rA] = make_float4(l4, l5, l6, l7);
        if (lane == 3 && rB < NN) g_ad4[rB] = make_float4(h4, h5, h6, h7);
    }
}

// ---------------- softmax + aggregation (+fused BN partial sums) ----------------
template<int C>
__device__ __forceinline__ void gather_step(int s, float alpha, float (&acc)[C], int lane) {
    if (C == 4) {
        float4 hv = ((const float4*)g_h)[s * 32 + lane];
        acc[0] = fmaf(hv.x, alpha, acc[0]);
        acc[1] = fmaf(hv.y, alpha, acc[1]);
        acc[2] = fmaf(hv.z, alpha, acc[2]);
        acc[3] = fmaf(hv.w, alpha, acc[3]);
    } else {
        #pragma unroll
        for (int j = 0; j < C; j++)
            acc[j] = fmaf(g_h[s * (32 * C) + lane * C + j], alpha, acc[j]);
    }
}

template<int D, bool MEAN>
__global__ void __launch_bounds__(256) agg_kernel(float* __restrict__ outMean) {
    constexpr int NC = 4 * D, C = NC / 32;
    __shared__ int    ssrc[8][64];
    __shared__ float4 ealpha[8][64];
    __shared__ float4 bnS[8][32];
    __shared__ float4 bnQ[8][32];
    int w = threadIdx.x >> 5, lane = threadIdx.x & 31;
    int v = blockIdx.x * 8 + w;               // grid = NN/8 exactly
    int head = lane >> 3;
    int start = g_rowptr[v];
    int deg = g_rowptr[v + 1] - start;
    float4 ad = g_ad4[v];

    float acc[C];
    #pragma unroll
    for (int j = 0; j < C; j++) acc[j] = 0.f;

    if (deg > 0 && deg <= 64) {
        int s0 = 0, s1 = 0;
        float4 e0, e1;
        bool h0 = lane < deg, h1 = lane + 32 < deg;
        float m0 = -CUDART_INF_F, m1 = m0, m2 = m0, m3 = m0;
        if (h0) {
            s0 = g_srcs[start + lane];
            float4 a = g_as4[s0];
            e0.x = lrelu(a.x + ad.x); e0.y = lrelu(a.y + ad.y);
            e0.z = lrelu(a.z + ad.z); e0.w = lrelu(a.w + ad.w);
            m0 = e0.x; m1 = e0.y; m2 = e0.z; m3 = e0.w;
        }
        if (h1) {
            s1 = g_srcs[start + lane + 32];
            float4 a = g_as4[s1];
            e1.x = lrelu(a.x + ad.x); e1.y = lrelu(a.y + ad.y);
            e1.z = lrelu(a.z + ad.z); e1.w = lrelu(a.w + ad.w);
            m0 = fmaxf(m0, e1.x); m1 = fmaxf(m1, e1.y);
            m2 = fmaxf(m2, e1.z); m3 = fmaxf(m3, e1.w);
        }
        #pragma unroll
        for (int o = 16; o; o >>= 1) {
            m0 = fmaxf(m0, __shfl_xor_sync(0xffffffffu, m0, o));
            m1 = fmaxf(m1, __shfl_xor_sync(0xffffffffu, m1, o));
            m2 = fmaxf(m2, __shfl_xor_sync(0xffffffffu, m2, o));
            m3 = fmaxf(m3, __shfl_xor_sync(0xffffffffu, m3, o));
        }
        float d0 = 0.f, d1 = 0.f, d2 = 0.f, d3 = 0.f;
        float x00=0,x01=0,x02=0,x03=0, x10=0,x11=0,x12=0,x13=0;
        if (h0) {
            x00 = __expf(e0.x - m0); x01 = __expf(e0.y - m1);
            x02 = __expf(e0.z - m2); x03 = __expf(e0.w - m3);
            d0 += x00; d1 += x01; d2 += x02; d3 += x03;
        }
        if (h1) {
            x10 = __expf(e1.x - m0); x11 = __expf(e1.y - m1);
            x12 = __expf(e1.z - m2); x13 = __expf(e1.w - m3);
            d0 += x10; d1 += x11; d2 += x12; d3 += x13;
        }
        #pragma unroll
        for (int o = 16; o; o >>= 1) {
            d0 += __shfl_xor_sync(0xffffffffu, d0, o);
            d1 += __shfl_xor_sync(0xffffffffu, d1, o);
            d2 += __shfl_xor_sync(0xffffffffu, d2, o);
            d3 += __shfl_xor_sync(0xffffffffu, d3, o);
        }
        float i0 = 1.f / (d0 + 1e-16f), i1 = 1.f / (d1 + 1e-16f);
        float i2 = 1.f / (d2 + 1e-16f), i3 = 1.f / (d3 + 1e-16f);
        if (h0) {
            ssrc[w][lane] = s0;
            ealpha[w][lane] = make_float4(x00 * i0, x01 * i1, x02 * i2, x03 * i3);
        }
        if (h1) {
            ssrc[w][lane + 32] = s1;
            ealpha[w][lane + 32] = make_float4(x10 * i0, x11 * i1, x12 * i2, x13 * i3);
        }
        __syncwarp();
        for (int t = 0; t < deg; t++) {
            int s = ssrc[w][t];
            float alpha = ((const float*)&ealpha[w][t])[head];
            gather_step<C>(s, alpha, acc, lane);
        }
    } else if (deg > 64) {   // rare fallback
        float m0 = -CUDART_INF_F, m1 = m0, m2 = m0, m3 = m0;
        for (int i = lane; i < deg; i += 32) {
            int s = g_srcs[start + i];
            float4 a = g_as4[s];
            m0 = fmaxf(m0, lrelu(a.x + ad.x)); m1 = fmaxf(m1, lrelu(a.y + ad.y));
            m2 = fmaxf(m2, lrelu(a.z + ad.z)); m3 = fmaxf(m3, lrelu(a.w + ad.w));
        }
        #pragma unroll
        for (int o = 16; o; o >>= 1) {
            m0 = fmaxf(m0, __shfl_xor_sync(0xffffffffu, m0, o));
            m1 = fmaxf(m1, __shfl_xor_sync(0xffffffffu, m1, o));
            m2 = fmaxf(m2, __shfl_xor_sync(0xffffffffu, m2, o));
            m3 = fmaxf(m3, __shfl_xor_sync(0xffffffffu, m3, o));
        }
        float d0 = 0.f, d1 = 0.f, d2 = 0.f, d3 = 0.f;
        for (int i = lane; i < deg; i += 32) {
            int s = g_srcs[start + i];
            float4 a = g_as4[s];
            d0 += __expf(lrelu(a.x + ad.x) - m0);
            d1 += __expf(lrelu(a.y + ad.y) - m1);
            d2 += __expf(lrelu(a.z + ad.z) - m2);
            d3 += __expf(lrelu(a.w + ad.w) - m3);
        }
        #pragma unroll
        for (int o = 16; o; o >>= 1) {
            d0 += __shfl_xor_sync(0xffffffffu, d0, o);
            d1 += __shfl_xor_sync(0xffffffffu, d1, o);
            d2 += __shfl_xor_sync(0xffffffffu, d2, o);
            d3 += __shfl_xor_sync(0xffffffffu, d3, o);
        }
        float denh = (head == 0) ? d0 : (head == 1) ? d1 : (head == 2) ? d2 : d3;
        float mxh  = (head == 0) ? m0 : (head == 1) ? m1 : (head == 2) ? m2 : m3;
        float adh  = (head == 0) ? ad.x : (head == 1) ? ad.y : (head == 2) ? ad.z : ad.w;
        float invh = 1.f / (denh + 1e-16f);
        for (int t = 0; t < deg; t++) {
            int s = g_srcs[start + t];
            float ash = ((const float*)&g_as4[s])[head];
            float alpha = __expf(lrelu(ash + adh) - mxh) * invh;
            gather_step<C>(s, alpha, acc, lane);
        }
    }

    if (MEAN) {
        #pragma unroll
        for (int j = 0; j < C; j++) {
            float a = acc[j];
            a += __shfl_xor_sync(0xffffffffu, a, 8);
            a += __shfl_xor_sync(0xffffffffu, a, 16);
            if (lane < 8) outMean[v * D + lane * C + j] = 0.25f * a;
        }
    } else {
        float4 a4 = make_float4(acc[0], acc[1], acc[2], acc[3]);
        ((float4*)g_agg)[v * 32 + lane] = a4;
        bnS[w][lane] = a4;
        bnQ[w][lane] = make_float4(a4.x * a4.x, a4.y * a4.y, a4.z * a4.z, a4.w * a4.w);
        __syncthreads();
        int t = threadIdx.x;
        if (t < 128) {
            float s = 0.f;
            #pragma unroll
            for (int i = 0; i < 8; i++) s += ((const float*)&bnS[i][t >> 2])[t & 3];
            atomicAdd(&g_bnsum[t], s);
        } else {
            int c = t - 128;
            float q = 0.f;
            #pragma unroll
            for (int i = 0; i < 8; i++) q += ((const float*)&bnQ[i][c >> 2])[c & 3];
            atomicAdd(&g_bnsq[c], q);
        }
    }
}

__global__ void zero_bn_kernel() {
    int c = threadIdx.x;
    g_bnsum[c] = 0.f; g_bnsq[c] = 0.f;
}

// ---------------- launch ----------------
extern "C" void kernel_launch(void* const* d_in, const int* in_sizes, int n_in,
                              void* d_out, int out_size) {
    (void)in_sizes; (void)n_in; (void)out_size;
    const float* x     = (const float*)d_in[0];
    const int*   ei    = (const int*)d_in[1];
    const float* w01   = (const float*)d_in[2];
    const float* s01   = (const float*)d_in[3];
    const float* att01 = (const float*)d_in[4];
    const float* w2    = (const float*)d_in[5];
    const float* s2    = (const float*)d_in[6];
    const float* att2  = (const float*)d_in[7];
    const float* gamma = (const float*)d_in[8];
    const float* beta  = (const float*)d_in[9];
    float* out = (float*)d_out;
    const int* srcp = ei;
    const int* dstp = ei + NE;

    const int THR_SMEM  = (53248 + 32) * 4;
    const int G128_SMEM = (64 * 136 + 64 * 136 + 256) * 4;   // ~69 KB -> 2 CTAs/SM
    const int G160_SMEM = (64 * 168 + 64 * 136 + 256) * 4;   // ~77 KB -> 2 CTAs/SM
    cudaFuncSetAttribute(thr_kernel, cudaFuncAttributeMaxDynamicSharedMemorySize, THR_SMEM);
    cudaFuncSetAttribute(gemm_kernel<128>, cudaFuncAttributeMaxDynamicSharedMemorySize, G128_SMEM);
    cudaFuncSetAttribute(gemm_kernel<160>, cudaFuncAttributeMaxDynamicSharedMemorySize, G160_SMEM);

    const int GB = (NN + 127) / 128;   // 782
    const int AB = NN / 8;             // 12500

    thr_kernel<<<1, 1024, THR_SMEM>>>(s01, s2);
    mask_kernel<<<208, 256>>>(w01, s01, w2, s2);
    wext_kernel<<<1, 1024>>>(w01, s01, att01, w2, s2, att2);
    // launch #4 -> ncu capture slot
    gemm_kernel<128><<<GB, 256, G128_SMEM>>>(x, 0, 0, gamma, beta);

    hist_kernel<<<(NE + 255) / 256, 256>>>(dstp);
    scan1_kernel<<<98, 1024>>>();
    scan2_kernel<<<1, 32>>>();
    scan3_kernel<<<98, 1024>>>();
    scatter_kernel<<<(NE + 255) / 256, 256>>>(srcp, dstp);

    zero_bn_kernel<<<1, 128>>>();
    agg_kernel<32, false><<<AB, 256>>>(nullptr);

    gemm_kernel<128><<<GB, 256, G128_SMEM>>>(nullptr, 1, 1, gamma, beta);
    zero_bn_kernel<<<1, 128>>>();
    agg_kernel<32, false><<<AB, 256>>>(nullptr);

    gemm_kernel<160><<<GB, 256, G160_SMEM>>>(nullptr, 2, 1, gamma + 128, beta + 128);
    agg_kernel<40, true><<<AB, 256>>>(out);
}

// round 6
// speedup vs baseline: 1.7518x; 1.1081x over previous
#include <cuda_runtime.h>
#include <cuda_bf16.h>
#include <math_constants.h>
#include <cstdint>

#define NN 100000
#define NE 1600000

typedef unsigned long long ull;

// ---------------- device scratch ----------------
__device__ float  g_h[NN * 160];
__device__ float  g_agg[NN * 128];
__device__ float4 g_as4[NN];
__device__ float4 g_ad4[NN];
__device__ int    g_deg[NN];
__device__ int    g_rowptr[NN + 1];
__device__ int    g_pos[NN];
__device__ int    g_srcs[NE];
// bf16 hi/lo masked weights, W^T layout [n][128] per layer, layer stride 22528
__device__ __nv_bfloat16 g_Bh[3 * 22528];
__device__ __nv_bfloat16 g_Bl[3 * 22528];
__device__ float  g_thr;
__device__ float  g_bnsum[128], g_bnsq[128];
__device__ int    g_bsum[98], g_boff[98];

__device__ __forceinline__ float lrelu(float x) { return (x >= 0.f) ? x : 0.2f * x; }

__device__ __forceinline__ uint32_t smem_u32(const void* p) {
    uint32_t a;
    asm("{ .reg .u64 t; cvta.to.shared.u64 t, %1; cvt.u32.u64 %0, t; }" : "=r"(a) : "l"(p));
    return a;
}
__device__ __forceinline__ void ldmx4(uint32_t addr, uint32_t r[4]) {
    asm volatile("ldmatrix.sync.aligned.m8n8.x4.shared.b16 {%0,%1,%2,%3}, [%4];"
        : "=r"(r[0]), "=r"(r[1]), "=r"(r[2]), "=r"(r[3]) : "r"(addr));
}
__device__ __forceinline__ void ldmx2(uint32_t addr, uint32_t r[2]) {
    asm volatile("ldmatrix.sync.aligned.m8n8.x2.shared.b16 {%0,%1}, [%2];"
        : "=r"(r[0]), "=r"(r[1]) : "r"(addr));
}
__device__ __forceinline__ void mma_bf16(float c[4], const uint32_t a[4],
                                         uint32_t b0, uint32_t b1) {
    asm volatile("mma.sync.aligned.m16n8k16.row.col.f32.bf16.bf16.f32 "
        "{%0,%1,%2,%3}, {%4,%5,%6,%7}, {%8,%9}, {%0,%1,%2,%3};"
        : "+f"(c[0]), "+f"(c[1]), "+f"(c[2]), "+f"(c[3])
        : "r"(a[0]), "r"(a[1]), "r"(a[2]), "r"(a[3]), "r"(b0), "r"(b1));
}
__device__ __forceinline__ void bfsplit(float v, __nv_bfloat16& h, __nv_bfloat16& l) {
    h = __float2bfloat16(v);
    l = __float2bfloat16(v - __bfloat162float(h));
}

// ---------------- exact percentile (bitwise radix rank-select) ----------------
__global__ void thr_kernel(const float* __restrict__ s01, const float* __restrict__ s2) {
    extern __shared__ unsigned sm[];
    unsigned* red = sm + 53248;
    int t = threadIdx.x;
    for (int i = t; i < 32768; i += 1024) sm[i] = __float_as_uint(fabsf(s01[i]));
    for (int i = t; i < 20480; i += 1024) sm[32768 + i] = __float_as_uint(fabsf(s2[i]));
    __syncthreads();
    unsigned prefix = 0;
    int k = 26624;
    for (int bit = 30; bit >= 0; --bit) {
        unsigned himask = 0xFFFFFFFEu << bit;
        unsigned bitm = 1u << bit;
        int cnt = 0;
        for (int i = t; i < 53248; i += 1024) {
            unsigned v = sm[i];
            cnt += ((((v ^ prefix) & himask) == 0u) && ((v & bitm) == 0u)) ? 1 : 0;
        }
        #pragma unroll
        for (int o = 16; o; o >>= 1) cnt += __shfl_xor_sync(0xffffffffu, cnt, o);
        if ((t & 31) == 0) red[t >> 5] = (unsigned)cnt;
        __syncthreads();
        int total = 0;
        #pragma unroll
        for (int w = 0; w < 32; w++) total += (int)red[w];
        if (k >= total) { prefix |= bitm; k -= total; }
        __syncthreads();
    }
    if (t == 0) g_thr = __uint_as_float(prefix);
}

// ---------------- masked weights -> bf16 hi/lo, W^T [n][128] ----------------
__global__ void prep_mask_kernel(const float* __restrict__ w01, const float* __restrict__ s01,
                                 const float* __restrict__ w2, const float* __restrict__ s2) {
    float thr = g_thr;
    int i = blockIdx.x * blockDim.x + threadIdx.x;
    if (i >= 53248) return;
    int L, k, n;
    float val;
    if (i < 16384) {
        L = 0; k = i >> 7; n = i & 127;
        val = (fabsf(s01[i]) < thr) ? 0.f : w01[i];
    } else if (i < 32768) {
        int j = i - 16384;
        L = 1; k = j >> 7; n = j & 127;
        val = (fabsf(s01[i]) < thr) ? 0.f : w01[i];
    } else {
        int j = i - 32768;
        L = 2; k = j / 160; n = j - k * 160;
        val = (fabsf(s2[j]) < thr) ? 0.f : w2[j];
    }
    __nv_bfloat16 hi, lo;
    bfsplit(val, hi, lo);
    int idx = L * 22528 + n * 128 + k;
    g_Bh[idx] = hi;
    g_Bl[idx] = lo;
}

// ---------------- attention-folded extra columns ----------------
__global__ void wext_kernel(const float* __restrict__ w01, const float* __restrict__ s01,
                            const float* __restrict__ att01,
                            const float* __restrict__ w2, const float* __restrict__ s2,
                            const float* __restrict__ att2) {
    float thr = g_thr;
    int t = threadIdx.x;               // 1024 = 128 k * 8 slots
    int k = t >> 3, slot = t & 7, sd = slot >> 2, h = slot & 3;
    #pragma unroll
    for (int L = 0; L < 2; L++) {
        float acc = 0.f;
        for (int d = 0; d < 32; d++) {
            int idx = L * 16384 + k * 128 + h * 32 + d;
            float w = (fabsf(s01[idx]) < thr) ? 0.f : w01[idx];
            acc = fmaf(w, att01[L * 256 + sd * 128 + h * 32 + d], acc);
        }
        __nv_bfloat16 hi, lo;
        bfsplit(acc, hi, lo);
        int idx2 = L * 22528 + (128 + slot) * 128 + k;
        g_Bh[idx2] = hi; g_Bl[idx2] = lo;
    }
    {
        float acc = 0.f;
        for (int d = 0; d < 40; d++) {
            int idx = k * 160 + h * 40 + d;
            float w = (fabsf(s2[idx]) < thr) ? 0.f : w2[idx];
            acc = fmaf(w, att2[sd * 160 + h * 40 + d], acc);
        }
        __nv_bfloat16 hi, lo;
        bfsplit(acc, hi, lo);
        int idx2 = 2 * 22528 + (160 + slot) * 128 + k;
        g_Bh[idx2] = hi; g_Bl[idx2] = lo;
    }
}

// ---------------- CSR build ----------------
__global__ void hist_kernel(const int* __restrict__ dst) {
    int e = blockIdx.x * blockDim.x + threadIdx.x;
    if (e < NE) atomicAdd(&g_deg[dst[e]], 1);
}
__global__ void scan1_kernel() {
    __shared__ int red[32];
    int t = threadIdx.x, b = blockIdx.x;
    int i = b * 1024 + t;
    int s = (i < NN) ? g_deg[i] : 0;
    #pragma unroll
    for (int o = 16; o; o >>= 1) s += __shfl_xor_sync(0xffffffffu, s, o);
    if ((t & 31) == 0) red[t >> 5] = s;
    __syncthreads();
    if (t < 32) {
        int x = red[t];
        #pragma unroll
        for (int o = 16; o; o >>= 1) x += __shfl_xor_sync(0xffffffffu, x, o);
        if (t == 0) g_bsum[b] = x;
    }
}
__global__ void scan2_kernel() {
    if (threadIdx.x == 0) {
        int run = 0;
        for (int b = 0; b < 98; b++) { g_boff[b] = run; run += g_bsum[b]; }
        g_rowptr[NN] = run;
    }
}
__global__ void scan3_kernel() {
    __shared__ int sm[1024];
    int t = threadIdx.x, b = blockIdx.x;
    int i = b * 1024 + t;
    int v = (i < NN) ? g_deg[i] : 0;
    sm[t] = v;
    __syncthreads();
    for (int off = 1; off < 1024; off <<= 1) {
        int x = (t >= off) ? sm[t - off] : 0;
        __syncthreads();
        sm[t] += x;
        __syncthreads();
    }
    if (i < NN) {
        int excl = sm[t] - v + g_boff[b];
        g_rowptr[i] = excl;
        g_pos[i] = excl;
        g_deg[i] = 0;
    }
}
__global__ void scatter_kernel(const int* __restrict__ src, const int* __restrict__ dst) {
    int e = blockIdx.x * blockDim.x + threadIdx.x;
    if (e < NE) {
        int d = dst[e];
        int p = atomicAdd(&g_pos[d], 1);
        g_srcs[p] = src[e];
    }
}

// ---------------- mma.sync bf16 GEMM (2-term split), fused BN + logits --------
// D[128, NCP] = act(X)[128,128] @ W[128,NCP]; W^T in smem, 3 HMMA per n-tile.
template<int NC>
__global__ void __launch_bounds__(256) gemm_kernel(const float* __restrict__ Xopt,
                                                   int widx, int useBN,
                                                   const float* __restrict__ gamma,
                                                   const float* __restrict__ beta) {
    constexpr int NCP = NC + 8;
    constexpr int NT = NCP / 8;        // 17 or 21 n-tiles (last = logits)
    extern __shared__ char dsm[];
    float* SC = (float*)dsm;                 // [128]
    float* SH = SC + 128;                    // [128]
    __nv_bfloat16* Ah = (__nv_bfloat16*)(dsm + 1024);   // [128][136]
    __nv_bfloat16* Al = Ah + 128 * 136;
    __nv_bfloat16* Bh = Al + 128 * 136;                 // [NCP][136]
    __nv_bfloat16* Bl = Bh + NCP * 136;

    const float* X = Xopt ? Xopt : g_agg;
    const int tid = threadIdx.x;
    const int wid = tid >> 5, lane = tid & 31;
    const int row0 = blockIdx.x * 128;

    if (useBN && tid < 128) {
        float mu = g_bnsum[tid] * (1.f / NN);
        float var = g_bnsq[tid] * (1.f / NN) - mu * mu;
        float sc = rsqrtf(var + 1e-5f) * gamma[tid];
        SC[tid] = sc;
        SH[tid] = fmaf(-mu, sc, beta[tid]);
    }
    if (useBN) __syncthreads();

    // B copy: global bf16 [n][128] -> smem [n][136]
    {
        const char* sH = (const char*)(g_Bh + widx * 22528);
        const char* sL = (const char*)(g_Bl + widx * 22528);
        for (int i = tid; i < NCP * 16; i += 256) {
            int row = i >> 4, seg = i & 15;
            *(float4*)((char*)Bh + row * 272 + seg * 16) = *(const float4*)(sH + row * 256 + seg * 16);
            *(float4*)((char*)Bl + row * 272 + seg * 16) = *(const float4*)(sL + row * 256 + seg * 16);
        }
    }
    // A: load X tile, BN+ReLU, bf16 hi/lo split
    {
        __nv_bfloat162* A2h = (__nv_bfloat162*)Ah;
        __nv_bfloat162* A2l = (__nv_bfloat162*)Al;
        for (int i = tid; i < 4096; i += 256) {
            int r = i >> 5, c4 = i & 31;
            int gr = row0 + r;
            float4 v = make_float4(0.f, 0.f, 0.f, 0.f);
            if (gr < NN) {
                v = ((const float4*)X)[gr * 32 + c4];
                if (useBN) {
                    float4 sc = ((const float4*)SC)[c4];
                    float4 sh = ((const float4*)SH)[c4];
                    v.x = fmaxf(fmaf(v.x, sc.x, sh.x), 0.f);
                    v.y = fmaxf(fmaf(v.y, sc.y, sh.y), 0.f);
                    v.z = fmaxf(fmaf(v.z, sc.z, sh.z), 0.f);
                    v.w = fmaxf(fmaf(v.w, sc.w, sh.w), 0.f);
                }
            }
            __nv_bfloat16 hx, lx, hy, ly, hz, lz, hw, lw;
            bfsplit(v.x, hx, lx); bfsplit(v.y, hy, ly);
            bfsplit(v.z, hz, lz); bfsplit(v.w, hw, lw);
            int o2 = r * 68 + c4 * 2;
            __nv_bfloat162 p0, p1, q0, q1;
            p0.x = hx; p0.y = hy; p1.x = hz; p1.y = hw;
            q0.x = lx; q0.y = ly; q1.x = lz; q1.y = lw;
            A2h[o2] = p0; A2h[o2 + 1] = p1;
            A2l[o2] = q0; A2l[o2 + 1] = q1;
        }
    }
    __syncthreads();

    const uint32_t au = smem_u32(Ah), alu = smem_u32(Al);
    const uint32_t bu = smem_u32(Bh), blu = smem_u32(Bl);

    float c[NT][4];
    #pragma unroll
    for (int ntI = 0; ntI < NT; ntI++)
        #pragma unroll
        for (int q = 0; q < 4; q++) c[ntI][q] = 0.f;

    const int arow = wid * 16 + (lane & 15);
    const int acol0 = (lane >> 4) * 8;
    const int brow_x4 = (lane & 7) + ((lane >> 4) * 8);
    const int bcolsel = ((lane >> 3) & 1) * 8;

    for (int kb = 0; kb < 8; kb++) {
        uint32_t ah[4], al[4];
        uint32_t aoff = (uint32_t)((arow * 136 + kb * 16 + acol0) * 2);
        ldmx4(au + aoff, ah);
        ldmx4(alu + aoff, al);
        #pragma unroll
        for (int p = 0; p < NT / 2; p++) {
            uint32_t bh[4], bl[4];
            uint32_t boff = (uint32_t)(((p * 16 + brow_x4) * 136 + kb * 16 + bcolsel) * 2);
            ldmx4(bu + boff, bh);
            ldmx4(blu + boff, bl);
            mma_bf16(c[2 * p], ah, bh[0], bh[1]);
            mma_bf16(c[2 * p], ah, bl[0], bl[1]);
            mma_bf16(c[2 * p], al, bh[0], bh[1]);
            mma_bf16(c[2 * p + 1], ah, bh[2], bh[3]);
            mma_bf16(c[2 * p + 1], ah, bl[2], bl[3]);
            mma_bf16(c[2 * p + 1], al, bh[2], bh[3]);
        }
        {   // last (odd) tile via x2
            uint32_t bh[2], bl[2];
            int brow2 = (NT - 1) * 8 + (lane & 7);
            uint32_t boff = (uint32_t)((brow2 * 136 + kb * 16 + bcolsel) * 2);
            ldmx2(bu + boff, bh);
            ldmx2(blu + boff, bl);
            mma_bf16(c[NT - 1], ah, bh[0], bh[1]);
            mma_bf16(c[NT - 1], ah, bl[0], bl[1]);
            mma_bf16(c[NT - 1], al, bh[0], bh[1]);
        }
    }

    // epilogue
    const int g = lane >> 2, tig = lane & 3;
    const int rA = row0 + wid * 16 + g;
    const int rB = rA + 8;
    const bool okA = rA < NN, okB = rB < NN;
    #pragma unroll
    for (int ntI = 0; ntI < NT - 1; ntI++) {
        if (okA) *(float2*)&g_h[rA * NC + ntI * 8 + tig * 2] = make_float2(c[ntI][0], c[ntI][1]);
        if (okB) *(float2*)&g_h[rB * NC + ntI * 8 + tig * 2] = make_float2(c[ntI][2], c[ntI][3]);
    }
    {
        float e0 = c[NT - 1][0], e1 = c[NT - 1][1], e2 = c[NT - 1][2], e3 = c[NT - 1][3];
        float o0 = __shfl_xor_sync(0xffffffffu, e0, 1);
        float o1 = __shfl_xor_sync(0xffffffffu, e1, 1);
        float o2 = __shfl_xor_sync(0xffffffffu, e2, 1);
        float o3 = __shfl_xor_sync(0xffffffffu, e3, 1);
        if (tig == 0) {
            if (okA) g_as4[rA] = make_float4(e0, e1, o0, o1);
            if (okB) g_as4[rB] = make_float4(e2, e3, o2, o3);
        } else if (tig == 2) {
            if (okA) g_ad4[rA] = make_float4(e0, e1, o0, o1);
            if (okB) g_ad4[rB] = make_float4(e2, e3, o2, o3);
        }
    }
}

// ---------------- softmax + aggregation (+fused BN partial sums) ----------------
template<int C>
__device__ __forceinline__ void gather_step(int s, float alpha, float (&acc)[C], int lane) {
    if (C == 4) {
        float4 hv = ((const float4*)g_h)[s * 32 + lane];
        acc[0] = fmaf(hv.x, alpha, acc[0]);
        acc[1] = fmaf(hv.y, alpha, acc[1]);
        acc[2] = fmaf(hv.z, alpha, acc[2]);
        acc[3] = fmaf(hv.w, alpha, acc[3]);
    } else {
        #pragma unroll
        for (int j = 0; j < C; j++)
            acc[j] = fmaf(g_h[s * (32 * C) + lane * C + j], alpha, acc[j]);
    }
}

template<int D, bool MEAN>
__global__ void __launch_bounds__(256) agg_kernel(float* __restrict__ outMean) {
    constexpr int C = D / 8;
    __shared__ int    ssrc[8][64];
    __shared__ float4 ealpha[8][64];
    __shared__ float4 bnS[8][32];
    __shared__ float4 bnQ[8][32];
    int w = threadIdx.x >> 5, lane = threadIdx.x & 31;
    int v = blockIdx.x * 8 + w;
    int head = lane >> 3;
    int start = g_rowptr[v];
    int deg = g_rowptr[v + 1] - start;
    float4 ad = g_ad4[v];

    float acc[C];
    #pragma unroll
    for (int j = 0; j < C; j++) acc[j] = 0.f;

    if (deg > 0 && deg <= 64) {
        int s0 = 0, s1 = 0;
        float4 e0, e1;
        bool h0 = lane < deg, h1 = lane + 32 < deg;
        float m0 = -CUDART_INF_F, m1 = m0, m2 = m0, m3 = m0;
        if (h0) {
            s0 = g_srcs[start + lane];
            float4 a = g_as4[s0];
            e0.x = lrelu(a.x + ad.x); e0.y = lrelu(a.y + ad.y);
            e0.z = lrelu(a.z + ad.z); e0.w = lrelu(a.w + ad.w);
            m0 = e0.x; m1 = e0.y; m2 = e0.z; m3 = e0.w;
        }
        if (h1) {
            s1 = g_srcs[start + lane + 32];
            float4 a = g_as4[s1];
            e1.x = lrelu(a.x + ad.x); e1.y = lrelu(a.y + ad.y);
            e1.z = lrelu(a.z + ad.z); e1.w = lrelu(a.w + ad.w);
            m0 = fmaxf(m0, e1.x); m1 = fmaxf(m1, e1.y);
            m2 = fmaxf(m2, e1.z); m3 = fmaxf(m3, e1.w);
        }
        #pragma unroll
        for (int o = 16; o; o >>= 1) {
            m0 = fmaxf(m0, __shfl_xor_sync(0xffffffffu, m0, o));
            m1 = fmaxf(m1, __shfl_xor_sync(0xffffffffu, m1, o));
            m2 = fmaxf(m2, __shfl_xor_sync(0xffffffffu, m2, o));
            m3 = fmaxf(m3, __shfl_xor_sync(0xffffffffu, m3, o));
        }
        float d0 = 0.f, d1 = 0.f, d2 = 0.f, d3 = 0.f;
        float x00=0,x01=0,x02=0,x03=0, x10=0,x11=0,x12=0,x13=0;
        if (h0) {
            x00 = __expf(e0.x - m0); x01 = __expf(e0.y - m1);
            x02 = __expf(e0.z - m2); x03 = __expf(e0.w - m3);
            d0 += x00; d1 += x01; d2 += x02; d3 += x03;
        }
        if (h1) {
            x10 = __expf(e1.x - m0); x11 = __expf(e1.y - m1);
            x12 = __expf(e1.z - m2); x13 = __expf(e1.w - m3);
            d0 += x10; d1 += x11; d2 += x12; d3 += x13;
        }
        #pragma unroll
        for (int o = 16; o; o >>= 1) {
            d0 += __shfl_xor_sync(0xffffffffu, d0, o);
            d1 += __shfl_xor_sync(0xffffffffu, d1, o);
            d2 += __shfl_xor_sync(0xffffffffu, d2, o);
            d3 += __shfl_xor_sync(0xffffffffu, d3, o);
        }
        float i0 = 1.f / (d0 + 1e-16f), i1 = 1.f / (d1 + 1e-16f);
        float i2 = 1.f / (d2 + 1e-16f), i3 = 1.f / (d3 + 1e-16f);
        if (h0) {
            ssrc[w][lane] = s0;
            ealpha[w][lane] = make_float4(x00 * i0, x01 * i1, x02 * i2, x03 * i3);
        }
        if (h1) {
            ssrc[w][lane + 32] = s1;
            ealpha[w][lane + 32] = make_float4(x10 * i0, x11 * i1, x12 * i2, x13 * i3);
        }
        __syncwarp();
        for (int t = 0; t < deg; t++) {
            int s = ssrc[w][t];
            float alpha = ((const float*)&ealpha[w][t])[head];
            gather_step<C>(s, alpha, acc, lane);
        }
    } else if (deg > 64) {
        float m0 = -CUDART_INF_F, m1 = m0, m2 = m0, m3 = m0;
        for (int i = lane; i < deg; i += 32) {
            int s = g_srcs[start + i];
            float4 a = g_as4[s];
            m0 = fmaxf(m0, lrelu(a.x + ad.x)); m1 = fmaxf(m1, lrelu(a.y + ad.y));
            m2 = fmaxf(m2, lrelu(a.z + ad.z)); m3 = fmaxf(m3, lrelu(a.w + ad.w));
        }
        #pragma unroll
        for (int o = 16; o; o >>= 1) {
            m0 = fmaxf(m0, __shfl_xor_sync(0xffffffffu, m0, o));
            m1 = fmaxf(m1, __shfl_xor_sync(0xffffffffu, m1, o));
            m2 = fmaxf(m2, __shfl_xor_sync(0xffffffffu, m2, o));
            m3 = fmaxf(m3, __shfl_xor_sync(0xffffffffu, m3, o));
        }
        float d0 = 0.f, d1 = 0.f, d2 = 0.f, d3 = 0.f;
        for (int i = lane; i < deg; i += 32) {
            int s = g_srcs[start + i];
            float4 a = g_as4[s];
            d0 += __expf(lrelu(a.x + ad.x) - m0);
            d1 += __expf(lrelu(a.y + ad.y) - m1);
            d2 += __expf(lrelu(a.z + ad.z) - m2);
            d3 += __expf(lrelu(a.w + ad.w) - m3);
        }
        #pragma unroll
        for (int o = 16; o; o >>= 1) {
            d0 += __shfl_xor_sync(0xffffffffu, d0, o);
            d1 += __shfl_xor_sync(0xffffffffu, d1, o);
            d2 += __shfl_xor_sync(0xffffffffu, d2, o);
            d3 += __shfl_xor_sync(0xffffffffu, d3, o);
        }
        float denh = (head == 0) ? d0 : (head == 1) ? d1 : (head == 2) ? d2 : d3;
        float mxh  = (head == 0) ? m0 : (head == 1) ? m1 : (head == 2) ? m2 : m3;
        float adh  = (head == 0) ? ad.x : (head == 1) ? ad.y : (head == 2) ? ad.z : ad.w;
        float invh = 1.f / (denh + 1e-16f);
        for (int t = 0; t < deg; t++) {
            int s = g_srcs[start + t];
            float ash = ((const float*)&g_as4[s])[head];
            float alpha = __expf(lrelu(ash + adh) - mxh) * invh;
            gather_step<C>(s, alpha, acc, lane);
        }
    }

    if (MEAN) {
        #pragma unroll
        for (int j = 0; j < C; j++) {
            float a = acc[j];
            a += __shfl_xor_sync(0xffffffffu, a, 8);
            a += __shfl_xor_sync(0xffffffffu, a, 16);
            if (lane < 8) outMean[v * D + lane * C + j] = 0.25f * a;
        }
    } else {
        float4 a4 = make_float4(acc[0], acc[1], acc[2], acc[3]);
        ((float4*)g_agg)[v * 32 + lane] = a4;
        bnS[w][lane] = a4;
        bnQ[w][lane] = make_float4(a4.x * a4.x, a4.y * a4.y, a4.z * a4.z, a4.w * a4.w);
        __syncthreads();
        int t = threadIdx.x;
        if (t < 128) {
            float s = 0.f;
            #pragma unroll
            for (int i = 0; i < 8; i++) s += ((const float*)&bnS[i][t >> 2])[t & 3];
            atomicAdd(&g_bnsum[t], s);
        } else {
            int cc = t - 128;
            float q = 0.f;
            #pragma unroll
            for (int i = 0; i < 8; i++) q += ((const float*)&bnQ[i][cc >> 2])[cc & 3];
            atomicAdd(&g_bnsq[cc], q);
        }
    }
}

__global__ void zero_bn_kernel() {
    int c = threadIdx.x;
    g_bnsum[c] = 0.f; g_bnsq[c] = 0.f;
}

// ---------------- launch ----------------
extern "C" void kernel_launch(void* const* d_in, const int* in_sizes, int n_in,
                              void* d_out, int out_size) {
    (void)in_sizes; (void)n_in; (void)out_size;
    const float* x     = (const float*)d_in[0];
    const int*   ei    = (const int*)d_in[1];
    const float* w01   = (const float*)d_in[2];
    const float* s01   = (const float*)d_in[3];
    const float* att01 = (const float*)d_in[4];
    const float* w2    = (const float*)d_in[5];
    const float* s2    = (const float*)d_in[6];
    const float* att2  = (const float*)d_in[7];
    const float* gamma = (const float*)d_in[8];
    const float* beta  = (const float*)d_in[9];
    float* out = (float*)d_out;
    const int* srcp = ei;
    const int* dstp = ei + NE;

    const int THR_SMEM  = (53248 + 32) * 4;
    const int G128_SMEM = 1024 + 2 * 128 * 136 * 2 + 2 * 136 * 136 * 2;   // 144640
    const int G160_SMEM = 1024 + 2 * 128 * 136 * 2 + 2 * 168 * 136 * 2;   // 162048
    cudaFuncSetAttribute(thr_kernel, cudaFuncAttributeMaxDynamicSharedMemorySize, THR_SMEM);
    cudaFuncSetAttribute(gemm_kernel<128>, cudaFuncAttributeMaxDynamicSharedMemorySize, G128_SMEM);
    cudaFuncSetAttribute(gemm_kernel<160>, cudaFuncAttributeMaxDynamicSharedMemorySize, G160_SMEM);

    const int GB = (NN + 127) / 128;   // 782
    const int AB = NN / 8;             // 12500

    thr_kernel<<<1, 1024, THR_SMEM>>>(s01, s2);
    prep_mask_kernel<<<208, 256>>>(w01, s01, w2, s2);
    wext_kernel<<<1, 1024>>>(w01, s01, att01, w2, s2, att2);
    // launch #4 -> ncu capture slot
    gemm_kernel<128><<<GB, 256, G128_SMEM>>>(x, 0, 0, gamma, beta);

    hist_kernel<<<(NE + 255) / 256, 256>>>(dstp);
    scan1_kernel<<<98, 1024>>>();
    scan2_kernel<<<1, 32>>>();
    scan3_kernel<<<98, 1024>>>();
    scatter_kernel<<<(NE + 255) / 256, 256>>>(srcp, dstp);

    zero_bn_kernel<<<1, 128>>>();
    agg_kernel<32, false><<<AB, 256>>>(nullptr);

    gemm_kernel<128><<<GB, 256, G128_SMEM>>>(nullptr, 1, 1, gamma, beta);
    zero_bn_kernel<<<1, 128>>>();
    agg_kernel<32, false><<<AB, 256>>>(nullptr);

    gemm_kernel<160><<<GB, 256, G160_SMEM>>>(nullptr, 2, 1, gamma + 128, beta + 128);
    agg_kernel<40, true><<<AB, 256>>>(out);
}

// round 7
// speedup vs baseline: 1.9641x; 1.1212x over previous
#include <cuda_runtime.h>
#include <cuda_bf16.h>
#include <math_constants.h>
#include <cstdint>

#define NN 100000
#define NE 1600000

typedef unsigned long long ull;

// ---------------- device scratch ----------------
__device__ float  g_h[NN * 160];
__device__ float  g_agg[NN * 128];
__device__ float4 g_as4[NN];
__device__ float4 g_ad4[NN];
__device__ int    g_deg[NN];
__device__ int    g_rowptr[NN + 1];
__device__ int    g_pos[NN];
__device__ int    g_srcs[NE];
// bf16 hi/lo masked weights, W^T layout [n][128] per layer, layer stride 22528
__device__ __nv_bfloat16 g_Bh[3 * 22528];
__device__ __nv_bfloat16 g_Bl[3 * 22528];
__device__ float  g_thr;
__device__ float  g_bnsum[128], g_bnsq[128];
__device__ int    g_bsum[98], g_boff[98];

__device__ __forceinline__ float lrelu(float x) { return (x >= 0.f) ? x : 0.2f * x; }

__device__ __forceinline__ uint32_t smem_u32(const void* p) {
    uint32_t a;
    asm("{ .reg .u64 t; cvta.to.shared.u64 t, %1; cvt.u32.u64 %0, t; }" : "=r"(a) : "l"(p));
    return a;
}
__device__ __forceinline__ void ldmx4(uint32_t addr, uint32_t r[4]) {
    asm volatile("ldmatrix.sync.aligned.m8n8.x4.shared.b16 {%0,%1,%2,%3}, [%4];"
        : "=r"(r[0]), "=r"(r[1]), "=r"(r[2]), "=r"(r[3]) : "r"(addr));
}
__device__ __forceinline__ void ldmx2(uint32_t addr, uint32_t r[2]) {
    asm volatile("ldmatrix.sync.aligned.m8n8.x2.shared.b16 {%0,%1}, [%2];"
        : "=r"(r[0]), "=r"(r[1]) : "r"(addr));
}
__device__ __forceinline__ void mma_bf16(float c[4], const uint32_t a[4],
                                         uint32_t b0, uint32_t b1) {
    asm volatile("mma.sync.aligned.m16n8k16.row.col.f32.bf16.bf16.f32 "
        "{%0,%1,%2,%3}, {%4,%5,%6,%7}, {%8,%9}, {%0,%1,%2,%3};"
        : "+f"(c[0]), "+f"(c[1]), "+f"(c[2]), "+f"(c[3])
        : "r"(a[0]), "r"(a[1]), "r"(a[2]), "r"(a[3]), "r"(b0), "r"(b1));
}
__device__ __forceinline__ void bfsplit(float v, __nv_bfloat16& h, __nv_bfloat16& l) {
    h = __float2bfloat16(v);
    l = __float2bfloat16(v - __bfloat162float(h));
}

// ---------------- exact percentile (bitwise radix rank-select) ----------------
__global__ void thr_kernel(const float* __restrict__ s01, const float* __restrict__ s2) {
    extern __shared__ unsigned sm[];
    unsigned* red = sm + 53248;
    int t = threadIdx.x;
    for (int i = t; i < 32768; i += 1024) sm[i] = __float_as_uint(fabsf(s01[i]));
    for (int i = t; i < 20480; i += 1024) sm[32768 + i] = __float_as_uint(fabsf(s2[i]));
    __syncthreads();
    unsigned prefix = 0;
    int k = 26624;
    for (int bit = 30; bit >= 0; --bit) {
        unsigned himask = 0xFFFFFFFEu << bit;
        unsigned bitm = 1u << bit;
        int cnt = 0;
        for (int i = t; i < 53248; i += 1024) {
            unsigned v = sm[i];
            cnt += ((((v ^ prefix) & himask) == 0u) && ((v & bitm) == 0u)) ? 1 : 0;
        }
        #pragma unroll
        for (int o = 16; o; o >>= 1) cnt += __shfl_xor_sync(0xffffffffu, cnt, o);
        if ((t & 31) == 0) red[t >> 5] = (unsigned)cnt;
        __syncthreads();
        int total = 0;
        #pragma unroll
        for (int w = 0; w < 32; w++) total += (int)red[w];
        if (k >= total) { prefix |= bitm; k -= total; }
        __syncthreads();
    }
    if (t == 0) g_thr = __uint_as_float(prefix);
}

// ---------------- masked weights -> bf16 hi/lo, W^T [n][128] ----------------
__global__ void prep_mask_kernel(const float* __restrict__ w01, const float* __restrict__ s01,
                                 const float* __restrict__ w2, const float* __restrict__ s2) {
    float thr = g_thr;
    int i = blockIdx.x * blockDim.x + threadIdx.x;
    if (i >= 53248) return;
    int L, k, n;
    float val;
    if (i < 16384) {
        L = 0; k = i >> 7; n = i & 127;
        val = (fabsf(s01[i]) < thr) ? 0.f : w01[i];
    } else if (i < 32768) {
        int j = i - 16384;
        L = 1; k = j >> 7; n = j & 127;
        val = (fabsf(s01[i]) < thr) ? 0.f : w01[i];
    } else {
        int j = i - 32768;
        L = 2; k = j / 160; n = j - k * 160;
        val = (fabsf(s2[j]) < thr) ? 0.f : w2[j];
    }
    __nv_bfloat16 hi, lo;
    bfsplit(val, hi, lo);
    int idx = L * 22528 + n * 128 + k;
    g_Bh[idx] = hi;
    g_Bl[idx] = lo;
}

// ---------------- attention-folded extra columns ----------------
__global__ void wext_kernel(const float* __restrict__ w01, const float* __restrict__ s01,
                            const float* __restrict__ att01,
                            const float* __restrict__ w2, const float* __restrict__ s2,
                            const float* __restrict__ att2) {
    float thr = g_thr;
    int t = threadIdx.x;               // 1024 = 128 k * 8 slots
    int k = t >> 3, slot = t & 7, sd = slot >> 2, h = slot & 3;
    #pragma unroll
    for (int L = 0; L < 2; L++) {
        float acc = 0.f;
        for (int d = 0; d < 32; d++) {
            int idx = L * 16384 + k * 128 + h * 32 + d;
            float w = (fabsf(s01[idx]) < thr) ? 0.f : w01[idx];
            acc = fmaf(w, att01[L * 256 + sd * 128 + h * 32 + d], acc);
        }
        __nv_bfloat16 hi, lo;
        bfsplit(acc, hi, lo);
        int idx2 = L * 22528 + (128 + slot) * 128 + k;
        g_Bh[idx2] = hi; g_Bl[idx2] = lo;
    }
    {
        float acc = 0.f;
        for (int d = 0; d < 40; d++) {
            int idx = k * 160 + h * 40 + d;
            float w = (fabsf(s2[idx]) < thr) ? 0.f : w2[idx];
            acc = fmaf(w, att2[sd * 160 + h * 40 + d], acc);
        }
        __nv_bfloat16 hi, lo;
        bfsplit(acc, hi, lo);
        int idx2 = 2 * 22528 + (160 + slot) * 128 + k;
        g_Bh[idx2] = hi; g_Bl[idx2] = lo;
    }
}

// ---------------- CSR build ----------------
__global__ void hist_kernel(const int* __restrict__ dst) {
    int e = blockIdx.x * blockDim.x + threadIdx.x;
    if (e < NE) atomicAdd(&g_deg[dst[e]], 1);
}
__global__ void scan1_kernel() {
    __shared__ int red[32];
    int t = threadIdx.x, b = blockIdx.x;
    int i = b * 1024 + t;
    int s = (i < NN) ? g_deg[i] : 0;
    #pragma unroll
    for (int o = 16; o; o >>= 1) s += __shfl_xor_sync(0xffffffffu, s, o);
    if ((t & 31) == 0) red[t >> 5] = s;
    __syncthreads();
    if (t < 32) {
        int x = red[t];
        #pragma unroll
        for (int o = 16; o; o >>= 1) x += __shfl_xor_sync(0xffffffffu, x, o);
        if (t == 0) g_bsum[b] = x;
    }
}
__global__ void scan2_kernel() {
    if (threadIdx.x == 0) {
        int run = 0;
        for (int b = 0; b < 98; b++) { g_boff[b] = run; run += g_bsum[b]; }
        g_rowptr[NN] = run;
    }
}
__global__ void scan3_kernel() {
    __shared__ int sm[1024];
    int t = threadIdx.x, b = blockIdx.x;
    int i = b * 1024 + t;
    int v = (i < NN) ? g_deg[i] : 0;
    sm[t] = v;
    __syncthreads();
    for (int off = 1; off < 1024; off <<= 1) {
        int x = (t >= off) ? sm[t - off] : 0;
        __syncthreads();
        sm[t] += x;
        __syncthreads();
    }
    if (i < NN) {
        int excl = sm[t] - v + g_boff[b];
        g_rowptr[i] = excl;
        g_pos[i] = excl;
        g_deg[i] = 0;
    }
}
__global__ void scatter_kernel(const int* __restrict__ src, const int* __restrict__ dst) {
    int e = blockIdx.x * blockDim.x + threadIdx.x;
    if (e < NE) {
        int d = dst[e];
        int p = atomicAdd(&g_pos[d], 1);
        g_srcs[p] = src[e];
    }
}

// ---------------- mma.sync bf16 GEMM, 512 threads: 8 row-groups x 2 n-halves ---
template<int NC>
__global__ void __launch_bounds__(512) gemm_kernel(const float* __restrict__ Xopt,
                                                   int widx, int useBN,
                                                   const float* __restrict__ gamma,
                                                   const float* __restrict__ beta) {
    constexpr int NCP = NC + 8;
    constexpr int NT = NCP / 8;              // 17 or 21 (odd; last tile = logits)
    constexpr int NPAIRS = (NT + 1) / 2;     // 9 or 11; last pair is single
    constexpr int MAXP = (NPAIRS + 1) / 2;   // pairs per warp (wn stride 2)
    extern __shared__ char dsm[];
    float* SC = (float*)dsm;                 // [128]
    float* SH = SC + 128;                    // [128]
    __nv_bfloat16* Ah = (__nv_bfloat16*)(dsm + 1024);   // [128][136]
    __nv_bfloat16* Al = Ah + 128 * 136;
    __nv_bfloat16* Bh = Al + 128 * 136;                 // [NCP][136]
    __nv_bfloat16* Bl = Bh + NCP * 136;

    const float* X = Xopt ? Xopt : g_agg;
    const int tid = threadIdx.x;
    const int wid = tid >> 5, lane = tid & 31;
    const int wy = wid & 7;                  // row group
    const int wn = wid >> 3;                 // n-half
    const int row0 = blockIdx.x * 128;

    if (useBN && tid < 128) {
        float mu = g_bnsum[tid] * (1.f / NN);
        float var = g_bnsq[tid] * (1.f / NN) - mu * mu;
        float sc = rsqrtf(var + 1e-5f) * gamma[tid];
        SC[tid] = sc;
        SH[tid] = fmaf(-mu, sc, beta[tid]);
    }
    if (useBN) __syncthreads();

    // B copy: global bf16 [n][128] -> smem [n][136]
    {
        const char* sH = (const char*)(g_Bh + widx * 22528);
        const char* sL = (const char*)(g_Bl + widx * 22528);
        for (int i = tid; i < NCP * 16; i += 512) {
            int row = i >> 4, seg = i & 15;
            *(float4*)((char*)Bh + row * 272 + seg * 16) = *(const float4*)(sH + row * 256 + seg * 16);
            *(float4*)((char*)Bl + row * 272 + seg * 16) = *(const float4*)(sL + row * 256 + seg * 16);
        }
    }
    // A: load X tile, BN+ReLU, bf16 hi/lo split
    {
        __nv_bfloat162* A2h = (__nv_bfloat162*)Ah;
        __nv_bfloat162* A2l = (__nv_bfloat162*)Al;
        for (int i = tid; i < 4096; i += 512) {
            int r = i >> 5, c4 = i & 31;
            int gr = row0 + r;
            float4 v = make_float4(0.f, 0.f, 0.f, 0.f);
            if (gr < NN) {
                v = ((const float4*)X)[gr * 32 + c4];
                if (useBN) {
                    float4 sc = ((const float4*)SC)[c4];
                    float4 sh = ((const float4*)SH)[c4];
                    v.x = fmaxf(fmaf(v.x, sc.x, sh.x), 0.f);
                    v.y = fmaxf(fmaf(v.y, sc.y, sh.y), 0.f);
                    v.z = fmaxf(fmaf(v.z, sc.z, sh.z), 0.f);
                    v.w = fmaxf(fmaf(v.w, sc.w, sh.w), 0.f);
                }
            }
            __nv_bfloat16 hx, lx, hy, ly, hz, lz, hw, lw;
            bfsplit(v.x, hx, lx); bfsplit(v.y, hy, ly);
            bfsplit(v.z, hz, lz); bfsplit(v.w, hw, lw);
            int o2 = r * 68 + c4 * 2;
            __nv_bfloat162 p0, p1, q0, q1;
            p0.x = hx; p0.y = hy; p1.x = hz; p1.y = hw;
            q0.x = lx; q0.y = ly; q1.x = lz; q1.y = lw;
            A2h[o2] = p0; A2h[o2 + 1] = p1;
            A2l[o2] = q0; A2l[o2 + 1] = q1;
        }
    }
    __syncthreads();

    const uint32_t au = smem_u32(Ah), alu = smem_u32(Al);
    const uint32_t bu = smem_u32(Bh), blu = smem_u32(Bl);

    float c[MAXP][2][4];
    #pragma unroll
    for (int pi = 0; pi < MAXP; pi++)
        #pragma unroll
        for (int u = 0; u < 2; u++)
            #pragma unroll
            for (int q = 0; q < 4; q++) c[pi][u][q] = 0.f;

    const int arow = wy * 16 + (lane & 15);
    const int acol0 = (lane >> 4) * 8;
    const int brow_x4 = (lane & 7) + ((lane >> 4) * 8);
    const int bcolsel = ((lane >> 3) & 1) * 8;

    for (int kb = 0; kb < 8; kb++) {
        uint32_t ah[4], al[4];
        uint32_t aoff = (uint32_t)((arow * 136 + kb * 16 + acol0) * 2);
        ldmx4(au + aoff, ah);
        ldmx4(alu + aoff, al);
        #pragma unroll
        for (int pi = 0; pi < MAXP; pi++) {
            int p = wn + 2 * pi;
            if (p >= NPAIRS) break;
            if (2 * p + 1 < NT) {            // full pair (16 B-rows)
                uint32_t bh[4], bl[4];
                uint32_t boff = (uint32_t)(((p * 16 + brow_x4) * 136 + kb * 16 + bcolsel) * 2);
                ldmx4(bu + boff, bh);
                ldmx4(blu + boff, bl);
                mma_bf16(c[pi][0], ah, bh[0], bh[1]);
                mma_bf16(c[pi][0], ah, bl[0], bl[1]);
                mma_bf16(c[pi][0], al, bh[0], bh[1]);
                mma_bf16(c[pi][1], ah, bh[2], bh[3]);
                mma_bf16(c[pi][1], ah, bl[2], bl[3]);
                mma_bf16(c[pi][1], al, bh[2], bh[3]);
            } else {                         // single (logits) tile
                uint32_t bh[2], bl[2];
                int brow2 = 2 * p * 8 + (lane & 7);
                uint32_t boff = (uint32_t)((brow2 * 136 + kb * 16 + bcolsel) * 2);
                ldmx2(bu + boff, bh);
                ldmx2(blu + boff, bl);
                mma_bf16(c[pi][0], ah, bh[0], bh[1]);
                mma_bf16(c[pi][0], ah, bl[0], bl[1]);
                mma_bf16(c[pi][0], al, bh[0], bh[1]);
            }
        }
    }

    // epilogue
    const int g = lane >> 2, tig = lane & 3;
    const int rA = row0 + wy * 16 + g;
    const int rB = rA + 8;
    const bool okA = rA < NN, okB = rB < NN;
    #pragma unroll
    for (int pi = 0; pi < MAXP; pi++) {
        int p = wn + 2 * pi;
        if (p >= NPAIRS) break;
        #pragma unroll
        for (int u = 0; u < 2; u++) {
            int ntI = 2 * p + u;
            if (ntI >= NT) break;
            if (ntI < NT - 1) {
                if (okA) *(float2*)&g_h[rA * NC + ntI * 8 + tig * 2] = make_float2(c[pi][u][0], c[pi][u][1]);
                if (okB) *(float2*)&g_h[rB * NC + ntI * 8 + tig * 2] = make_float2(c[pi][u][2], c[pi][u][3]);
            } else {
                float e0 = c[pi][u][0], e1 = c[pi][u][1], e2 = c[pi][u][2], e3 = c[pi][u][3];
                float o0 = __shfl_xor_sync(0xffffffffu, e0, 1);
                float o1 = __shfl_xor_sync(0xffffffffu, e1, 1);
                float o2 = __shfl_xor_sync(0xffffffffu, e2, 1);
                float o3 = __shfl_xor_sync(0xffffffffu, e3, 1);
                if (tig == 0) {
                    if (okA) g_as4[rA] = make_float4(e0, e1, o0, o1);
                    if (okB) g_as4[rB] = make_float4(e2, e3, o2, o3);
                } else if (tig == 2) {
                    if (okA) g_ad4[rA] = make_float4(e0, e1, o0, o1);
                    if (okB) g_ad4[rB] = make_float4(e2, e3, o2, o3);
                }
            }
        }
    }
}

// ---------------- softmax + aggregation (+fused BN partial sums) ----------------
template<int C>
__device__ __forceinline__ void gather_step(int s, float alpha, float (&acc)[C], int lane) {
    if (C == 4) {
        float4 hv = ((const float4*)g_h)[s * 32 + lane];
        acc[0] = fmaf(hv.x, alpha, acc[0]);
        acc[1] = fmaf(hv.y, alpha, acc[1]);
        acc[2] = fmaf(hv.z, alpha, acc[2]);
        acc[3] = fmaf(hv.w, alpha, acc[3]);
    } else {
        #pragma unroll
        for (int j = 0; j < C; j++)
            acc[j] = fmaf(g_h[s * (32 * C) + lane * C + j], alpha, acc[j]);
    }
}

template<int D, bool MEAN>
__global__ void __launch_bounds__(256) agg_kernel(float* __restrict__ outMean) {
    constexpr int C = D / 8;
    __shared__ int    ssrc[8][64];
    __shared__ float4 ealpha[8][64];
    __shared__ float4 bnS[8][32];
    __shared__ float4 bnQ[8][32];
    int w = threadIdx.x >> 5, lane = threadIdx.x & 31;
    int v = blockIdx.x * 8 + w;
    int head = lane >> 3;
    int start = g_rowptr[v];
    int deg = g_rowptr[v + 1] - start;
    float4 ad = g_ad4[v];

    float acc[C];
    #pragma unroll
    for (int j = 0; j < C; j++) acc[j] = 0.f;

    if (deg > 0 && deg <= 64) {
        int s0 = 0, s1 = 0;
        float4 e0, e1;
        bool h0 = lane < deg, h1 = lane + 32 < deg;
        float m0 = -CUDART_INF_F, m1 = m0, m2 = m0, m3 = m0;
        if (h0) {
            s0 = g_srcs[start + lane];
            float4 a = g_as4[s0];
            e0.x = lrelu(a.x + ad.x); e0.y = lrelu(a.y + ad.y);
            e0.z = lrelu(a.z + ad.z); e0.w = lrelu(a.w + ad.w);
            m0 = e0.x; m1 = e0.y; m2 = e0.z; m3 = e0.w;
        }
        if (h1) {
            s1 = g_srcs[start + lane + 32];
            float4 a = g_as4[s1];
            e1.x = lrelu(a.x + ad.x); e1.y = lrelu(a.y + ad.y);
            e1.z = lrelu(a.z + ad.z); e1.w = lrelu(a.w + ad.w);
            m0 = fmaxf(m0, e1.x); m1 = fmaxf(m1, e1.y);
            m2 = fmaxf(m2, e1.z); m3 = fmaxf(m3, e1.w);
        }
        #pragma unroll
        for (int o = 16; o; o >>= 1) {
            m0 = fmaxf(m0, __shfl_xor_sync(0xffffffffu, m0, o));
            m1 = fmaxf(m1, __shfl_xor_sync(0xffffffffu, m1, o));
            m2 = fmaxf(m2, __shfl_xor_sync(0xffffffffu, m2, o));
            m3 = fmaxf(m3, __shfl_xor_sync(0xffffffffu, m3, o));
        }
        float d0 = 0.f, d1 = 0.f, d2 = 0.f, d3 = 0.f;
        float x00=0,x01=0,x02=0,x03=0, x10=0,x11=0,x12=0,x13=0;
        if (h0) {
            x00 = __expf(e0.x - m0); x01 = __expf(e0.y - m1);
            x02 = __expf(e0.z - m2); x03 = __expf(e0.w - m3);
            d0 += x00; d1 += x01; d2 += x02; d3 += x03;
        }
        if (h1) {
            x10 = __expf(e1.x - m0); x11 = __expf(e1.y - m1);
            x12 = __expf(e1.z - m2); x13 = __expf(e1.w - m3);
            d0 += x10; d1 += x11; d2 += x12; d3 += x13;
        }
        #pragma unroll
        for (int o = 16; o; o >>= 1) {
            d0 += __shfl_xor_sync(0xffffffffu, d0, o);
            d1 += __shfl_xor_sync(0xffffffffu, d1, o);
            d2 += __shfl_xor_sync(0xffffffffu, d2, o);
            d3 += __shfl_xor_sync(0xffffffffu, d3, o);
        }
        float i0 = 1.f / (d0 + 1e-16f), i1 = 1.f / (d1 + 1e-16f);
        float i2 = 1.f / (d2 + 1e-16f), i3 = 1.f / (d3 + 1e-16f);
        if (h0) {
            ssrc[w][lane] = s0;
            ealpha[w][lane] = make_float4(x00 * i0, x01 * i1, x02 * i2, x03 * i3);
        }
        if (h1) {
            ssrc[w][lane + 32] = s1;
            ealpha[w][lane + 32] = make_float4(x10 * i0, x11 * i1, x12 * i2, x13 * i3);
        }
        __syncwarp();
        for (int t = 0; t < deg; t++) {
            int s = ssrc[w][t];
            float alpha = ((const float*)&ealpha[w][t])[head];
            gather_step<C>(s, alpha, acc, lane);
        }
    } else if (deg > 64) {
        float m0 = -CUDART_INF_F, m1 = m0, m2 = m0, m3 = m0;
        for (int i = lane; i < deg; i += 32) {
            int s = g_srcs[start + i];
            float4 a = g_as4[s];
            m0 = fmaxf(m0, lrelu(a.x + ad.x)); m1 = fmaxf(m1, lrelu(a.y + ad.y));
            m2 = fmaxf(m2, lrelu(a.z + ad.z)); m3 = fmaxf(m3, lrelu(a.w + ad.w));
        }
        #pragma unroll
        for (int o = 16; o; o >>= 1) {
            m0 = fmaxf(m0, __shfl_xor_sync(0xffffffffu, m0, o));
            m1 = fmaxf(m1, __shfl_xor_sync(0xffffffffu, m1, o));
            m2 = fmaxf(m2, __shfl_xor_sync(0xffffffffu, m2, o));
            m3 = fmaxf(m3, __shfl_xor_sync(0xffffffffu, m3, o));
        }
        float d0 = 0.f, d1 = 0.f, d2 = 0.f, d3 = 0.f;
        for (int i = lane; i < deg; i += 32) {
            int s = g_srcs[start + i];
            float4 a = g_as4[s];
            d0 += __expf(lrelu(a.x + ad.x) - m0);
            d1 += __expf(lrelu(a.y + ad.y) - m1);
            d2 += __expf(lrelu(a.z + ad.z) - m2);
            d3 += __expf(lrelu(a.w + ad.w) - m3);
        }
        #pragma unroll
        for (int o = 16; o; o >>= 1) {
            d0 += __shfl_xor_sync(0xffffffffu, d0, o);
            d1 += __shfl_xor_sync(0xffffffffu, d1, o);
            d2 += __shfl_xor_sync(0xffffffffu, d2, o);
            d3 += __shfl_xor_sync(0xffffffffu, d3, o);
        }
        float denh = (head == 0) ? d0 : (head == 1) ? d1 : (head == 2) ? d2 : d3;
        float mxh  = (head == 0) ? m0 : (head == 1) ? m1 : (head == 2) ? m2 : m3;
        float adh  = (head == 0) ? ad.x : (head == 1) ? ad.y : (head == 2) ? ad.z : ad.w;
        float invh = 1.f / (denh + 1e-16f);
        for (int t = 0; t < deg; t++) {
            int s = g_srcs[start + t];
            float ash = ((const float*)&g_as4[s])[head];
            float alpha = __expf(lrelu(ash + adh) - mxh) * invh;
            gather_step<C>(s, alpha, acc, lane);
        }
    }

    if (MEAN) {
        #pragma unroll
        for (int j = 0; j < C; j++) {
            float a = acc[j];
            a += __shfl_xor_sync(0xffffffffu, a, 8);
            a += __shfl_xor_sync(0xffffffffu, a, 16);
            if (lane < 8) outMean[v * D + lane * C + j] = 0.25f * a;
        }
    } else {
        float4 a4 = make_float4(acc[0], acc[1], acc[2], acc[3]);
        ((float4*)g_agg)[v * 32 + lane] = a4;
        bnS[w][lane] = a4;
        bnQ[w][lane] = make_float4(a4.x * a4.x, a4.y * a4.y, a4.z * a4.z, a4.w * a4.w);
        __syncthreads();
        int t = threadIdx.x;
        if (t < 128) {
            float s = 0.f;
            #pragma unroll
            for (int i = 0; i < 8; i++) s += ((const float*)&bnS[i][t >> 2])[t & 3];
            atomicAdd(&g_bnsum[t], s);
        } else {
            int cc = t - 128;
            float q = 0.f;
            #pragma unroll
            for (int i = 0; i < 8; i++) q += ((const float*)&bnQ[i][cc >> 2])[cc & 3];
            atomicAdd(&g_bnsq[cc], q);
        }
    }
}

__global__ void zero_bn_kernel() {
    int c = threadIdx.x;
    g_bnsum[c] = 0.f; g_bnsq[c] = 0.f;
}

// ---------------- launch ----------------
extern "C" void kernel_launch(void* const* d_in, const int* in_sizes, int n_in,
                              void* d_out, int out_size) {
    (void)in_sizes; (void)n_in; (void)out_size;
    const float* x     = (const float*)d_in[0];
    const int*   ei    = (const int*)d_in[1];
    const float* w01   = (const float*)d_in[2];
    const float* s01   = (const float*)d_in[3];
    const float* att01 = (const float*)d_in[4];
    const float* w2    = (const float*)d_in[5];
    const float* s2    = (const float*)d_in[6];
    const float* att2  = (const float*)d_in[7];
    const float* gamma = (const float*)d_in[8];
    const float* beta  = (const float*)d_in[9];
    float* out = (float*)d_out;
    const int* srcp = ei;
    const int* dstp = ei + NE;

    const int THR_SMEM  = (53248 + 32) * 4;
    const int G128_SMEM = 1024 + 2 * 128 * 136 * 2 + 2 * 136 * 136 * 2;   // 144640
    const int G160_SMEM = 1024 + 2 * 128 * 136 * 2 + 2 * 168 * 136 * 2;   // 162048
    cudaFuncSetAttribute(thr_kernel, cudaFuncAttributeMaxDynamicSharedMemorySize, THR_SMEM);
    cudaFuncSetAttribute(gemm_kernel<128>, cudaFuncAttributeMaxDynamicSharedMemorySize, G128_SMEM);
    cudaFuncSetAttribute(gemm_kernel<160>, cudaFuncAttributeMaxDynamicSharedMemorySize, G160_SMEM);

    const int GB = (NN + 127) / 128;   // 782
    const int AB = NN / 8;             // 12500

    thr_kernel<<<1, 1024, THR_SMEM>>>(s01, s2);
    prep_mask_kernel<<<208, 256>>>(w01, s01, w2, s2);
    wext_kernel<<<1, 1024>>>(w01, s01, att01, w2, s2, att2);
    // launch #4 -> ncu capture slot
    gemm_kernel<128><<<GB, 512, G128_SMEM>>>(x, 0, 0, gamma, beta);

    hist_kernel<<<(NE + 255) / 256, 256>>>(dstp);
    scan1_kernel<<<98, 1024>>>();
    scan2_kernel<<<1, 32>>>();
    scan3_kernel<<<98, 1024>>>();
    scatter_kernel<<<(NE + 255) / 256, 256>>>(srcp, dstp);

    zero_bn_kernel<<<1, 128>>>();
    agg_kernel<32, false><<<AB, 256>>>(nullptr);

    gemm_kernel<128><<<GB, 512, G128_SMEM>>>(nullptr, 1, 1, gamma, beta);
    zero_bn_kernel<<<1, 128>>>();
    agg_kernel<32, false><<<AB, 256>>>(nullptr);

    gemm_kernel<160><<<GB, 512, G160_SMEM>>>(nullptr, 2, 1, gamma + 128, beta + 128);
    agg_kernel<40, true><<<AB, 256>>>(out);
}

// round 9
// speedup vs baseline: 2.0447x; 1.0410x over previous
#include <cuda_runtime.h>
#include <cuda_bf16.h>
#include <math_constants.h>
#include <cstdint>

#define NN 100000
#define NE 1600000

typedef unsigned long long ull;

// ---------------- device scratch ----------------
__device__ float  g_h[NN * 160];
__device__ float  g_agg[NN * 128];
__device__ float4 g_as4[NN];
__device__ float4 g_ad4[NN];
__device__ int    g_deg[NN];
__device__ int    g_rowptr[NN + 1];
__device__ int    g_pos[NN];
__device__ int    g_srcs[NE];
// bf16 hi/lo masked weights, W^T layout [n][128] per layer, layer stride 22528
__device__ __nv_bfloat16 g_Bh[3 * 22528];
__device__ __nv_bfloat16 g_Bl[3 * 22528];
__device__ float  g_thr;
__device__ float  g_bnsum[128], g_bnsq[128];
__device__ int    g_bsum[98], g_boff[98];

__device__ __forceinline__ float lrelu(float x) { return (x >= 0.f) ? x : 0.2f * x; }

__device__ __forceinline__ uint32_t smem_u32(const void* p) {
    uint32_t a;
    asm("{ .reg .u64 t; cvta.to.shared.u64 t, %1; cvt.u32.u64 %0, t; }" : "=r"(a) : "l"(p));
    return a;
}
__device__ __forceinline__ void ldmx4(uint32_t addr, uint32_t r[4]) {
    asm volatile("ldmatrix.sync.aligned.m8n8.x4.shared.b16 {%0,%1,%2,%3}, [%4];"
        : "=r"(r[0]), "=r"(r[1]), "=r"(r[2]), "=r"(r[3]) : "r"(addr));
}
__device__ __forceinline__ void ldmx2(uint32_t addr, uint32_t r[2]) {
    asm volatile("ldmatrix.sync.aligned.m8n8.x2.shared.b16 {%0,%1}, [%2];"
        : "=r"(r[0]), "=r"(r[1]) : "r"(addr));
}
__device__ __forceinline__ void mma_bf16(float c[4], const uint32_t a[4],
                                         uint32_t b0, uint32_t b1) {
    asm volatile("mma.sync.aligned.m16n8k16.row.col.f32.bf16.bf16.f32 "
        "{%0,%1,%2,%3}, {%4,%5,%6,%7}, {%8,%9}, {%0,%1,%2,%3};"
        : "+f"(c[0]), "+f"(c[1]), "+f"(c[2]), "+f"(c[3])
        : "r"(a[0]), "r"(a[1]), "r"(a[2]), "r"(a[3]), "r"(b0), "r"(b1));
}
__device__ __forceinline__ void bfsplit(float v, __nv_bfloat16& h, __nv_bfloat16& l) {
    h = __float2bfloat16(v);
    l = __float2bfloat16(v - __bfloat162float(h));
}

// ---------------- exact percentile (bitwise radix rank-select) ----------------
__global__ void thr_kernel(const float* __restrict__ s01, const float* __restrict__ s2) {
    extern __shared__ unsigned sm[];
    unsigned* red = sm + 53248;
    int t = threadIdx.x;
    for (int i = t; i < 32768; i += 1024) sm[i] = __float_as_uint(fabsf(s01[i]));
    for (int i = t; i < 20480; i += 1024) sm[32768 + i] = __float_as_uint(fabsf(s2[i]));
    __syncthreads();
    unsigned prefix = 0;
    int k = 26624;
    for (int bit = 30; bit >= 0; --bit) {
        unsigned himask = 0xFFFFFFFEu << bit;
        unsigned bitm = 1u << bit;
        int cnt = 0;
        for (int i = t; i < 53248; i += 1024) {
            unsigned v = sm[i];
            cnt += ((((v ^ prefix) & himask) == 0u) && ((v & bitm) == 0u)) ? 1 : 0;
        }
        #pragma unroll
        for (int o = 16; o; o >>= 1) cnt += __shfl_xor_sync(0xffffffffu, cnt, o);
        if ((t & 31) == 0) red[t >> 5] = (unsigned)cnt;
        __syncthreads();
        int total = 0;
        #pragma unroll
        for (int w = 0; w < 32; w++) total += (int)red[w];
        if (k >= total) { prefix |= bitm; k -= total; }
        __syncthreads();
    }
    if (t == 0) g_thr = __uint_as_float(prefix);
}

// ---------------- masked weights -> bf16 hi/lo, W^T [n][128] ----------------
__global__ void prep_mask_kernel(const float* __restrict__ w01, const float* __restrict__ s01,
                                 const float* __restrict__ w2, const float* __restrict__ s2) {
    float thr = g_thr;
    int i = blockIdx.x * blockDim.x + threadIdx.x;
    if (i >= 53248) return;
    int L, k, n;
    float val;
    if (i < 16384) {
        L = 0; k = i >> 7; n = i & 127;
        val = (fabsf(s01[i]) < thr) ? 0.f : w01[i];
    } else if (i < 32768) {
        int j = i - 16384;
        L = 1; k = j >> 7; n = j & 127;
        val = (fabsf(s01[i]) < thr) ? 0.f : w01[i];
    } else {
        int j = i - 32768;
        L = 2; k = j / 160; n = j - k * 160;
        val = (fabsf(s2[j]) < thr) ? 0.f : w2[j];
    }
    __nv_bfloat16 hi, lo;
    bfsplit(val, hi, lo);
    int idx = L * 22528 + n * 128 + k;
    g_Bh[idx] = hi;
    g_Bl[idx] = lo;
}

// ---------------- attention-folded extra columns ----------------
__global__ void wext_kernel(const float* __restrict__ w01, const float* __restrict__ s01,
                            const float* __restrict__ att01,
                            const float* __restrict__ w2, const float* __restrict__ s2,
                            const float* __restrict__ att2) {
    float thr = g_thr;
    int t = threadIdx.x;               // 1024 = 128 k * 8 slots
    int k = t >> 3, slot = t & 7, sd = slot >> 2, h = slot & 3;
    #pragma unroll
    for (int L = 0; L < 2; L++) {
        float acc = 0.f;
        for (int d = 0; d < 32; d++) {
            int idx = L * 16384 + k * 128 + h * 32 + d;
            float w = (fabsf(s01[idx]) < thr) ? 0.f : w01[idx];
            acc = fmaf(w, att01[L * 256 + sd * 128 + h * 32 + d], acc);
        }
        __nv_bfloat16 hi, lo;
        bfsplit(acc, hi, lo);
        int idx2 = L * 22528 + (128 + slot) * 128 + k;
        g_Bh[idx2] = hi; g_Bl[idx2] = lo;
    }
    {
        float acc = 0.f;
        for (int d = 0; d < 40; d++) {
            int idx = k * 160 + h * 40 + d;
            float w = (fabsf(s2[idx]) < thr) ? 0.f : w2[idx];
            acc = fmaf(w, att2[sd * 160 + h * 40 + d], acc);
        }
        __nv_bfloat16 hi, lo;
        bfsplit(acc, hi, lo);
        int idx2 = 2 * 22528 + (160 + slot) * 128 + k;
        g_Bh[idx2] = hi; g_Bl[idx2] = lo;
    }
}

// ---------------- CSR build ----------------
__global__ void hist_kernel(const int* __restrict__ dst) {
    int e = blockIdx.x * blockDim.x + threadIdx.x;
    if (e < NE) atomicAdd(&g_deg[dst[e]], 1);
}
__global__ void scan1_kernel() {
    __shared__ int red[32];
    int t = threadIdx.x, b = blockIdx.x;
    int i = b * 1024 + t;
    int s = (i < NN) ? g_deg[i] : 0;
    #pragma unroll
    for (int o = 16; o; o >>= 1) s += __shfl_xor_sync(0xffffffffu, s, o);
    if ((t & 31) == 0) red[t >> 5] = s;
    __syncthreads();
    if (t < 32) {
        int x = red[t];
        #pragma unroll
        for (int o = 16; o; o >>= 1) x += __shfl_xor_sync(0xffffffffu, x, o);
        if (t == 0) g_bsum[b] = x;
    }
}
__global__ void scan2_kernel() {
    if (threadIdx.x == 0) {
        int run = 0;
        for (int b = 0; b < 98; b++) { g_boff[b] = run; run += g_bsum[b]; }
        g_rowptr[NN] = run;
    }
}
__global__ void scan3_kernel() {
    __shared__ int sm[1024];
    int t = threadIdx.x, b = blockIdx.x;
    int i = b * 1024 + t;
    int v = (i < NN) ? g_deg[i] : 0;
    sm[t] = v;
    __syncthreads();
    for (int off = 1; off < 1024; off <<= 1) {
        int x = (t >= off) ? sm[t - off] : 0;
        __syncthreads();
        sm[t] += x;
        __syncthreads();
    }
    if (i < NN) {
        int excl = sm[t] - v + g_boff[b];
        g_rowptr[i] = excl;
        g_pos[i] = excl;
        g_deg[i] = 0;
    }
}
__global__ void scatter_kernel(const int* __restrict__ src, const int* __restrict__ dst) {
    int e = blockIdx.x * blockDim.x + threadIdx.x;
    if (e < NE) {
        int d = dst[e];
        int p = atomicAdd(&g_pos[d], 1);
        g_srcs[p] = src[e];
    }
}

// ---------------- mma.sync bf16 GEMM, K-chunked (2 CTAs/SM), 512 threads ------
template<int NC>
__global__ void __launch_bounds__(512, 2) gemm_kernel(const float* __restrict__ Xopt,
                                                      int widx, int useBN,
                                                      const float* __restrict__ gamma,
                                                      const float* __restrict__ beta) {
    constexpr int NCP = NC + 8;
    constexpr int NT = NCP / 8;              // 17 or 21 (odd; last tile = logits)
    constexpr int NPAIRS = (NT + 1) / 2;     // 9 or 11; last pair is single
    constexpr int MAXP = (NPAIRS + 1) / 2;   // pairs per warp (wn stride 2)
    constexpr int KS = 72;                   // chunk row stride in bf16 (64 + 8 pad)
    extern __shared__ char dsm[];
    float* SC = (float*)dsm;                 // [128]
    float* SH = SC + 128;                    // [128]
    __nv_bfloat16* Ah = (__nv_bfloat16*)(dsm + 1024);   // [128][KS]
    __nv_bfloat16* Al = Ah + 128 * KS;
    __nv_bfloat16* Bh = Al + 128 * KS;                  // [NCP][KS]
    __nv_bfloat16* Bl = Bh + NCP * KS;

    const float* X = Xopt ? Xopt : g_agg;
    const int tid = threadIdx.x;
    const int wid = tid >> 5, lane = tid & 31;
    const int wy = wid & 7;                  // row group
    const int wn = wid >> 3;                 // n-half
    const int row0 = blockIdx.x * 128;

    if (useBN && tid < 128) {
        float mu = g_bnsum[tid] * (1.f / NN);
        float var = g_bnsq[tid] * (1.f / NN) - mu * mu;
        float sc = rsqrtf(var + 1e-5f) * gamma[tid];
        SC[tid] = sc;
        SH[tid] = fmaf(-mu, sc, beta[tid]);
    }
    if (useBN) __syncthreads();

    float c[MAXP][2][4];
    #pragma unroll
    for (int pi = 0; pi < MAXP; pi++)
        #pragma unroll
        for (int u = 0; u < 2; u++)
            #pragma unroll
            for (int q = 0; q < 4; q++) c[pi][u][q] = 0.f;

    const uint32_t au = smem_u32(Ah), alu = smem_u32(Al);
    const uint32_t bu = smem_u32(Bh), blu = smem_u32(Bl);
    const int arow = wy * 16 + (lane & 15);
    const int acol0 = (lane >> 4) * 8;
    const int brow_x4 = (lane & 7) + ((lane >> 4) * 8);
    const int bcolsel = ((lane >> 3) & 1) * 8;

    for (int kc = 0; kc < 2; kc++) {
        // B chunk copy: [n][kc*64 .. +64) -> smem [n][KS]
        {
            const char* sH = (const char*)(g_Bh + widx * 22528) + kc * 128;
            const char* sL = (const char*)(g_Bl + widx * 22528) + kc * 128;
            for (int i = tid; i < NCP * 8; i += 512) {
                int row = i >> 3, seg = i & 7;
                *(float4*)((char*)Bh + row * (KS * 2) + seg * 16) = *(const float4*)(sH + row * 256 + seg * 16);
                *(float4*)((char*)Bl + row * (KS * 2) + seg * 16) = *(const float4*)(sL + row * 256 + seg * 16);
            }
        }
        // A chunk: load X cols [kc*64, +64), BN+ReLU, bf16 hi/lo split
        {
            __nv_bfloat162* A2h = (__nv_bfloat162*)Ah;
            __nv_bfloat162* A2l = (__nv_bfloat162*)Al;
            for (int i = tid; i < 2048; i += 512) {
                int r = i >> 4, c4l = i & 15;
                int c4 = kc * 16 + c4l;
                int gr = row0 + r;
                float4 v = make_float4(0.f, 0.f, 0.f, 0.f);
                if (gr < NN) {
                    v = ((const float4*)X)[gr * 32 + c4];
                    if (useBN) {
                        float4 sc = ((const float4*)SC)[c4];
                        float4 sh = ((const float4*)SH)[c4];
                        v.x = fmaxf(fmaf(v.x, sc.x, sh.x), 0.f);
                        v.y = fmaxf(fmaf(v.y, sc.y, sh.y), 0.f);
                        v.z = fmaxf(fmaf(v.z, sc.z, sh.z), 0.f);
                        v.w = fmaxf(fmaf(v.w, sc.w, sh.w), 0.f);
                    }
                }
                __nv_bfloat16 hx, lx, hy, ly, hz, lz, hw, lw;
                bfsplit(v.x, hx, lx); bfsplit(v.y, hy, ly);
                bfsplit(v.z, hz, lz); bfsplit(v.w, hw, lw);
                int o2 = r * (KS / 2) + c4l * 2;
                __nv_bfloat162 p0, p1, q0, q1;
                p0.x = hx; p0.y = hy; p1.x = hz; p1.y = hw;
                q0.x = lx; q0.y = ly; q1.x = lz; q1.y = lw;
                A2h[o2] = p0; A2h[o2 + 1] = p1;
                A2l[o2] = q0; A2l[o2 + 1] = q1;
            }
        }
        __syncthreads();

        for (int kb = 0; kb < 4; kb++) {
            uint32_t ah[4], al[4];
            uint32_t aoff = (uint32_t)((arow * KS + kb * 16 + acol0) * 2);
            ldmx4(au + aoff, ah);
            ldmx4(alu + aoff, al);
            #pragma unroll
            for (int pi = 0; pi < MAXP; pi++) {
                int p = wn + 2 * pi;
                if (p >= NPAIRS) break;
                if (2 * p + 1 < NT) {            // full pair (16 B-rows)
                    uint32_t bh[4], bl[4];
                    uint32_t boff = (uint32_t)(((p * 16 + brow_x4) * KS + kb * 16 + bcolsel) * 2);
                    ldmx4(bu + boff, bh);
                    ldmx4(blu + boff, bl);
                    mma_bf16(c[pi][0], ah, bh[0], bh[1]);
                    mma_bf16(c[pi][0], ah, bl[0], bl[1]);
                    mma_bf16(c[pi][0], al, bh[0], bh[1]);
                    mma_bf16(c[pi][1], ah, bh[2], bh[3]);
                    mma_bf16(c[pi][1], ah, bl[2], bl[3]);
                    mma_bf16(c[pi][1], al, bh[2], bh[3]);
                } else {                         // single (logits) tile
                    uint32_t bh[2], bl[2];
                    int brow2 = 2 * p * 8 + (lane & 7);
                    uint32_t boff = (uint32_t)((brow2 * KS + kb * 16 + bcolsel) * 2);
                    ldmx2(bu + boff, bh);
                    ldmx2(blu + boff, bl);
                    mma_bf16(c[pi][0], ah, bh[0], bh[1]);
                    mma_bf16(c[pi][0], ah, bl[0], bl[1]);
                    mma_bf16(c[pi][0], al, bh[0], bh[1]);
                }
            }
        }
        __syncthreads();
    }

    // epilogue
    const int g = lane >> 2, tig = lane & 3;
    const int rA = row0 + wy * 16 + g;
    const int rB = rA + 8;
    const bool okA = rA < NN, okB = rB < NN;
    #pragma unroll
    for (int pi = 0; pi < MAXP; pi++) {
        int p = wn + 2 * pi;
        if (p >= NPAIRS) break;
        #pragma unroll
        for (int u = 0; u < 2; u++) {
            int ntI = 2 * p + u;
            if (ntI >= NT) break;
            if (ntI < NT - 1) {
                if (okA) *(float2*)&g_h[rA * NC + ntI * 8 + tig * 2] = make_float2(c[pi][u][0], c[pi][u][1]);
                if (okB) *(float2*)&g_h[rB * NC + ntI * 8 + tig * 2] = make_float2(c[pi][u][2], c[pi][u][3]);
            } else {
                float e0 = c[pi][u][0], e1 = c[pi][u][1], e2 = c[pi][u][2], e3 = c[pi][u][3];
                float o0 = __shfl_xor_sync(0xffffffffu, e0, 1);
                float o1 = __shfl_xor_sync(0xffffffffu, e1, 1);
                float o2 = __shfl_xor_sync(0xffffffffu, e2, 1);
                float o3 = __shfl_xor_sync(0xffffffffu, e3, 1);
                if (tig == 0) {
                    if (okA) g_as4[rA] = make_float4(e0, e1, o0, o1);
                    if (okB) g_as4[rB] = make_float4(e2, e3, o2, o3);
                } else if (tig == 2) {
                    if (okA) g_ad4[rA] = make_float4(e0, e1, o0, o1);
                    if (okB) g_ad4[rB] = make_float4(e2, e3, o2, o3);
                }
            }
        }
    }
}

// ---------------- softmax + aggregation (+fused BN partial sums) ----------------
template<int C>
__device__ __forceinline__ void gather_step(int s, float alpha, float (&acc)[C], int lane) {
    if (C == 4) {
        float4 hv = ((const float4*)g_h)[s * 32 + lane];
        acc[0] = fmaf(hv.x, alpha, acc[0]);
        acc[1] = fmaf(hv.y, alpha, acc[1]);
        acc[2] = fmaf(hv.z, alpha, acc[2]);
        acc[3] = fmaf(hv.w, alpha, acc[3]);
    } else {
        #pragma unroll
        for (int j = 0; j < C; j++)
            acc[j] = fmaf(g_h[s * (32 * C) + lane * C + j], alpha, acc[j]);
    }
}

template<int D, bool MEAN>
__global__ void __launch_bounds__(256) agg_kernel(float* __restrict__ outMean) {
    constexpr int C = D / 8;
    __shared__ int    ssrc[8][64];
    __shared__ float4 ealpha[8][64];
    __shared__ float4 bnS[8][32];
    __shared__ float4 bnQ[8][32];
    int w = threadIdx.x >> 5, lane = threadIdx.x & 31;
    int v = blockIdx.x * 8 + w;
    int head = lane >> 3;
    int start = g_rowptr[v];
    int deg = g_rowptr[v + 1] - start;
    float4 ad = g_ad4[v];

    float acc[C];
    #pragma unroll
    for (int j = 0; j < C; j++) acc[j] = 0.f;

    if (deg > 0 && deg <= 64) {
        int s0 = 0, s1 = 0;
        float4 e0, e1;
        bool h0 = lane < deg, h1 = lane + 32 < deg;
        float m0 = -CUDART_INF_F, m1 = m0, m2 = m0, m3 = m0;
        if (h0) {
            s0 = g_srcs[start + lane];
            float4 a = g_as4[s0];
            e0.x = lrelu(a.x + ad.x); e0.y = lrelu(a.y + ad.y);
            e0.z = lrelu(a.z + ad.z); e0.w = lrelu(a.w + ad.w);
            m0 = e0.x; m1 = e0.y; m2 = e0.z; m3 = e0.w;
        }
        if (h1) {
            s1 = g_srcs[start + lane + 32];
            float4 a = g_as4[s1];
            e1.x = lrelu(a.x + ad.x); e1.y = lrelu(a.y + ad.y);
            e1.z = lrelu(a.z + ad.z); e1.w = lrelu(a.w + ad.w);
            m0 = fmaxf(m0, e1.x); m1 = fmaxf(m1, e1.y);
            m2 = fmaxf(m2, e1.z); m3 = fmaxf(m3, e1.w);
        }
        #pragma unroll
        for (int o = 16; o; o >>= 1) {
            m0 = fmaxf(m0, __shfl_xor_sync(0xffffffffu, m0, o));
            m1 = fmaxf(m1, __shfl_xor_sync(0xffffffffu, m1, o));
            m2 = fmaxf(m2, __shfl_xor_sync(0xffffffffu, m2, o));
            m3 = fmaxf(m3, __shfl_xor_sync(0xffffffffu, m3, o));
        }
        float d0 = 0.f, d1 = 0.f, d2 = 0.f, d3 = 0.f;
        float x00=0,x01=0,x02=0,x03=0, x10=0,x11=0,x12=0,x13=0;
        if (h0) {
            x00 = __expf(e0.x - m0); x01 = __expf(e0.y - m1);
            x02 = __expf(e0.z - m2); x03 = __expf(e0.w - m3);
            d0 += x00; d1 += x01; d2 += x02; d3 += x03;
        }
        if (h1) {
            x10 = __expf(e1.x - m0); x11 = __expf(e1.y - m1);
            x12 = __expf(e1.z - m2); x13 = __expf(e1.w - m3);
            d0 += x10; d1 += x11; d2 += x12; d3 += x13;
        }
        #pragma unroll
        for (int o = 16; o; o >>= 1) {
            d0 += __shfl_xor_sync(0xffffffffu, d0, o);
            d1 += __shfl_xor_sync(0xffffffffu, d1, o);
            d2 += __shfl_xor_sync(0xffffffffu, d2, o);
            d3 += __shfl_xor_sync(0xffffffffu, d3, o);
        }
        float i0 = 1.f / (d0 + 1e-16f), i1 = 1.f / (d1 + 1e-16f);
        float i2 = 1.f / (d2 + 1e-16f), i3 = 1.f / (d3 + 1e-16f);
        if (h0) {
            ssrc[w][lane] = s0;
            ealpha[w][lane] = make_float4(x00 * i0, x01 * i1, x02 * i2, x03 * i3);
        }
        if (h1) {
            ssrc[w][lane + 32] = s1;
            ealpha[w][lane + 32] = make_float4(x10 * i0, x11 * i1, x12 * i2, x13 * i3);
        }
        __syncwarp();
        #pragma unroll 4
        for (int t = 0; t < deg; t++) {
            int s = ssrc[w][t];
            float alpha = ((const float*)&ealpha[w][t])[head];
            gather_step<C>(s, alpha, acc, lane);
        }
    } else if (deg > 64) {
        float m0 = -CUDART_INF_F, m1 = m0, m2 = m0, m3 = m0;
        for (int i = lane; i < deg; i += 32) {
            int s = g_srcs[start + i];
            float4 a = g_as4[s];
            m0 = fmaxf(m0, lrelu(a.x + ad.x)); m1 = fmaxf(m1, lrelu(a.y + ad.y));
            m2 = fmaxf(m2, lrelu(a.z + ad.z)); m3 = fmaxf(m3, lrelu(a.w + ad.w));
        }
        #pragma unroll
        for (int o = 16; o; o >>= 1) {
            m0 = fmaxf(m0, __shfl_xor_sync(0xffffffffu, m0, o));
            m1 = fmaxf(m1, __shfl_xor_sync(0xffffffffu, m1, o));
            m2 = fmaxf(m2, __shfl_xor_sync(0xffffffffu, m2, o));
            m3 = fmaxf(m3, __shfl_xor_sync(0xffffffffu, m3, o));
        }
        float d0 = 0.f, d1 = 0.f, d2 = 0.f, d3 = 0.f;
        for (int i = lane; i < deg; i += 32) {
            int s = g_srcs[start + i];
            float4 a = g_as4[s];
            d0 += __expf(lrelu(a.x + ad.x) - m0);
            d1 += __expf(lrelu(a.y + ad.y) - m1);
            d2 += __expf(lrelu(a.z + ad.z) - m2);
            d3 += __expf(lrelu(a.w + ad.w) - m3);
        }
        #pragma unroll
        for (int o = 16; o; o >>= 1) {
            d0 += __shfl_xor_sync(0xffffffffu, d0, o);
            d1 += __shfl_xor_sync(0xffffffffu, d1, o);
            d2 += __shfl_xor_sync(0xffffffffu, d2, o);
            d3 += __shfl_xor_sync(0xffffffffu, d3, o);
        }
        float denh = (head == 0) ? d0 : (head == 1) ? d1 : (head == 2) ? d2 : d3;
        float mxh  = (head == 0) ? m0 : (head == 1) ? m1 : (head == 2) ? m2 : m3;
        float adh  = (head == 0) ? ad.x : (head == 1) ? ad.y : (head == 2) ? ad.z : ad.w;
        float invh = 1.f / (denh + 1e-16f);
        for (int t = 0; t < deg; t++) {
            int s = g_srcs[start + t];
            float ash = ((const float*)&g_as4[s])[head];
            float alpha = __expf(lrelu(ash + adh) - mxh) * invh;
            gather_step<C>(s, alpha, acc, lane);
        }
    }

    if (MEAN) {
        #pragma unroll
        for (int j = 0; j < C; j++) {
            float a = acc[j];
            a += __shfl_xor_sync(0xffffffffu, a, 8);
            a += __shfl_xor_sync(0xffffffffu, a, 16);
            if (lane < 8) outMean[v * D + lane * C + j] = 0.25f * a;
        }
    } else {
        float4 a4 = make_float4(acc[0], acc[1], acc[2], acc[3]);
        ((float4*)g_agg)[v * 32 + lane] = a4;
        bnS[w][lane] = a4;
        bnQ[w][lane] = make_float4(a4.x * a4.x, a4.y * a4.y, a4.z * a4.z, a4.w * a4.w);
        __syncthreads();
        int t = threadIdx.x;
        if (t < 128) {
            float s = 0.f;
            #pragma unroll
            for (int i = 0; i < 8; i++) s += ((const float*)&bnS[i][t >> 2])[t & 3];
            atomicAdd(&g_bnsum[t], s);
        } else {
            int cc = t - 128;
            float q = 0.f;
            #pragma unroll
            for (int i = 0; i < 8; i++) q += ((const float*)&bnQ[i][cc >> 2])[cc & 3];
            atomicAdd(&g_bnsq[cc], q);
        }
    }
}

__global__ void zero_bn_kernel() {
    int c = threadIdx.x;
    g_bnsum[c] = 0.f; g_bnsq[c] = 0.f;
}

// ---------------- launch ----------------
extern "C" void kernel_launch(void* const* d_in, const int* in_sizes, int n_in,
                              void* d_out, int out_size) {
    (void)in_sizes; (void)n_in; (void)out_size;
    const float* x     = (const float*)d_in[0];
    const int*   ei    = (const int*)d_in[1];
    const float* w01   = (const float*)d_in[2];
    const float* s01   = (const float*)d_in[3];
    const float* att01 = (const float*)d_in[4];
    const float* w2    = (const float*)d_in[5];
    const float* s2    = (const float*)d_in[6];
    const float* att2  = (const float*)d_in[7];
    const float* gamma = (const float*)d_in[8];
    const float* beta  = (const float*)d_in[9];
    float* out = (float*)d_out;
    const int* srcp = ei;
    const int* dstp = ei + NE;

    const int THR_SMEM  = (53248 + 32) * 4;
    const int G128_SMEM = 1024 + 2 * 128 * 72 * 2 + 2 * 136 * 72 * 2;   // 77056 (~75 KB)
    const int G160_SMEM = 1024 + 2 * 128 * 72 * 2 + 2 * 168 * 72 * 2;   // 86272 (~84 KB)
    cudaFuncSetAttribute(thr_kernel, cudaFuncAttributeMaxDynamicSharedMemorySize, THR_SMEM);
    cudaFuncSetAttribute(gemm_kernel<128>, cudaFuncAttributeMaxDynamicSharedMemorySize, G128_SMEM);
    cudaFuncSetAttribute(gemm_kernel<160>, cudaFuncAttributeMaxDynamicSharedMemorySize, G160_SMEM);

    const int GB = (NN + 127) / 128;   // 782
    const int AB = NN / 8;             // 12500

    thr_kernel<<<1, 1024, THR_SMEM>>>(s01, s2);
    prep_mask_kernel<<<208, 256>>>(w01, s01, w2, s2);
    wext_kernel<<<1, 1024>>>(w01, s01, att01, w2, s2, att2);
    // launch #4 -> ncu capture slot
    gemm_kernel<128><<<GB, 512, G128_SMEM>>>(x, 0, 0, gamma, beta);

    hist_kernel<<<(NE + 255) / 256, 256>>>(dstp);
    scan1_kernel<<<98, 1024>>>();
    scan2_kernel<<<1, 32>>>();
    scan3_kernel<<<98, 1024>>>();
    scatter_kernel<<<(NE + 255) / 256, 256>>>(srcp, dstp);

    zero_bn_kernel<<<1, 128>>>();
    agg_kernel<32, false><<<AB, 256>>>(nullptr);

    gemm_kernel<128><<<GB, 512, G128_SMEM>>>(nullptr, 1, 1, gamma, beta);
    zero_bn_kernel<<<1, 128>>>();
    agg_kernel<32, false><<<AB, 256>>>(nullptr);

    gemm_kernel<160><<<GB, 512, G160_SMEM>>>(nullptr, 2, 1, gamma + 128, beta + 128);
    agg_kernel<40, true><<<AB, 256>>>(out);
}

// round 10
// speedup vs baseline: 2.1112x; 1.0325x over previous
#include <cuda_runtime.h>
#include <cuda_bf16.h>
#include <math_constants.h>
#include <cstdint>

#define NN 100000
#define NE 1600000

typedef unsigned long long ull;

// ---------------- device scratch ----------------
__device__ float  g_h[NN * 160];
__device__ float  g_agg[NN * 128];
__device__ float4 g_as4[NN];
__device__ float4 g_ad4[NN];
__device__ int    g_deg[NN];
__device__ int    g_rowptr[NN + 1];
__device__ int    g_pos[NN];
__device__ int    g_srcs[NE];
// bf16 hi/lo masked weights, W^T layout [n][128] per layer, layer stride 22528
__device__ __nv_bfloat16 g_Bh[3 * 22528];
__device__ __nv_bfloat16 g_Bl[3 * 22528];
__device__ float  g_thr;
__device__ float  g_bnsum[256], g_bnsq[256];   // ping-pong: buf0 (L0->L1), buf1 (L1->L2)
__device__ int    g_bsum[98], g_boff[98];

__device__ __forceinline__ float lrelu(float x) { return (x >= 0.f) ? x : 0.2f * x; }

__device__ __forceinline__ uint32_t smem_u32(const void* p) {
    uint32_t a;
    asm("{ .reg .u64 t; cvta.to.shared.u64 t, %1; cvt.u32.u64 %0, t; }" : "=r"(a) : "l"(p));
    return a;
}
__device__ __forceinline__ void ldmx4(uint32_t addr, uint32_t r[4]) {
    asm volatile("ldmatrix.sync.aligned.m8n8.x4.shared.b16 {%0,%1,%2,%3}, [%4];"
        : "=r"(r[0]), "=r"(r[1]), "=r"(r[2]), "=r"(r[3]) : "r"(addr));
}
__device__ __forceinline__ void ldmx2(uint32_t addr, uint32_t r[2]) {
    asm volatile("ldmatrix.sync.aligned.m8n8.x2.shared.b16 {%0,%1}, [%2];"
        : "=r"(r[0]), "=r"(r[1]) : "r"(addr));
}
__device__ __forceinline__ void mma_bf16(float c[4], const uint32_t a[4],
                                         uint32_t b0, uint32_t b1) {
    asm volatile("mma.sync.aligned.m16n8k16.row.col.f32.bf16.bf16.f32 "
        "{%0,%1,%2,%3}, {%4,%5,%6,%7}, {%8,%9}, {%0,%1,%2,%3};"
        : "+f"(c[0]), "+f"(c[1]), "+f"(c[2]), "+f"(c[3])
        : "r"(a[0]), "r"(a[1]), "r"(a[2]), "r"(a[3]), "r"(b0), "r"(b1));
}
__device__ __forceinline__ void bfsplit(float v, __nv_bfloat16& h, __nv_bfloat16& l) {
    h = __float2bfloat16(v);
    l = __float2bfloat16(v - __bfloat162float(h));
}

// ---------------- exact percentile (bitwise radix rank-select) ----------------
__global__ void thr_kernel(const float* __restrict__ s01, const float* __restrict__ s2) {
    extern __shared__ unsigned sm[];
    unsigned* red = sm + 53248;
    int t = threadIdx.x;
    for (int i = t; i < 32768; i += 1024) sm[i] = __float_as_uint(fabsf(s01[i]));
    for (int i = t; i < 20480; i += 1024) sm[32768 + i] = __float_as_uint(fabsf(s2[i]));
    __syncthreads();
    unsigned prefix = 0;
    int k = 26624;
    for (int bit = 30; bit >= 0; --bit) {
        unsigned himask = 0xFFFFFFFEu << bit;
        unsigned bitm = 1u << bit;
        int cnt = 0;
        for (int i = t; i < 53248; i += 1024) {
            unsigned v = sm[i];
            cnt += ((((v ^ prefix) & himask) == 0u) && ((v & bitm) == 0u)) ? 1 : 0;
        }
        #pragma unroll
        for (int o = 16; o; o >>= 1) cnt += __shfl_xor_sync(0xffffffffu, cnt, o);
        if ((t & 31) == 0) red[t >> 5] = (unsigned)cnt;
        __syncthreads();
        int total = 0;
        #pragma unroll
        for (int w = 0; w < 32; w++) total += (int)red[w];
        if (k >= total) { prefix |= bitm; k -= total; }
        __syncthreads();
    }
    if (t == 0) g_thr = __uint_as_float(prefix);
}

// ---------------- masked weights + attention-folded columns (merged) ----------
__global__ void __launch_bounds__(1024) maskwext_kernel(
        const float* __restrict__ w01, const float* __restrict__ s01,
        const float* __restrict__ att01,
        const float* __restrict__ w2, const float* __restrict__ s2,
        const float* __restrict__ att2) {
    float thr = g_thr;
    int b = blockIdx.x, t = threadIdx.x;
    if (b < 52) {
        int i = b * 1024 + t;
        if (i < 53248) {
            int L, k, n;
            float val;
            if (i < 16384) {
                L = 0; k = i >> 7; n = i & 127;
                val = (fabsf(s01[i]) < thr) ? 0.f : w01[i];
            } else if (i < 32768) {
                int j = i - 16384;
                L = 1; k = j >> 7; n = j & 127;
                val = (fabsf(s01[i]) < thr) ? 0.f : w01[i];
            } else {
                int j = i - 32768;
                L = 2; k = j / 160; n = j - k * 160;
                val = (fabsf(s2[j]) < thr) ? 0.f : w2[j];
            }
            __nv_bfloat16 hi, lo;
            bfsplit(val, hi, lo);
            int idx = L * 22528 + n * 128 + k;
            g_Bh[idx] = hi;
            g_Bl[idx] = lo;
        }
    } else {
        // wext: 1024 threads = 128 k * 8 slots
        int k = t >> 3, slot = t & 7, sd = slot >> 2, h = slot & 3;
        #pragma unroll
        for (int L = 0; L < 2; L++) {
            float acc = 0.f;
            for (int d = 0; d < 32; d++) {
                int idx = L * 16384 + k * 128 + h * 32 + d;
                float w = (fabsf(s01[idx]) < thr) ? 0.f : w01[idx];
                acc = fmaf(w, att01[L * 256 + sd * 128 + h * 32 + d], acc);
            }
            __nv_bfloat16 hi, lo;
            bfsplit(acc, hi, lo);
            int idx2 = L * 22528 + (128 + slot) * 128 + k;
            g_Bh[idx2] = hi; g_Bl[idx2] = lo;
        }
        {
            float acc = 0.f;
            for (int d = 0; d < 40; d++) {
                int idx = k * 160 + h * 40 + d;
                float w = (fabsf(s2[idx]) < thr) ? 0.f : w2[idx];
                acc = fmaf(w, att2[sd * 160 + h * 40 + d], acc);
            }
            __nv_bfloat16 hi, lo;
            bfsplit(acc, hi, lo);
            int idx2 = 2 * 22528 + (160 + slot) * 128 + k;
            g_Bh[idx2] = hi; g_Bl[idx2] = lo;
        }
    }
}

// ---------------- CSR build ----------------
__global__ void hist_kernel(const int* __restrict__ dst) {
    int e = blockIdx.x * blockDim.x + threadIdx.x;
    if (e < NE) atomicAdd(&g_deg[dst[e]], 1);
}
__global__ void scan1_kernel() {
    __shared__ int red[32];
    int t = threadIdx.x, b = blockIdx.x;
    int i = b * 1024 + t;
    int s = (i < NN) ? g_deg[i] : 0;
    #pragma unroll
    for (int o = 16; o; o >>= 1) s += __shfl_xor_sync(0xffffffffu, s, o);
    if ((t & 31) == 0) red[t >> 5] = s;
    __syncthreads();
    if (t < 32) {
        int x = red[t];
        #pragma unroll
        for (int o = 16; o; o >>= 1) x += __shfl_xor_sync(0xffffffffu, x, o);
        if (t == 0) g_bsum[b] = x;
    }
}
__global__ void scan2_kernel() {
    if (threadIdx.x == 0) {
        int run = 0;
        for (int b = 0; b < 98; b++) { g_boff[b] = run; run += g_bsum[b]; }
        g_rowptr[NN] = run;
    }
}
__global__ void scan3_kernel() {
    __shared__ int sm[1024];
    int t = threadIdx.x, b = blockIdx.x;
    int i = b * 1024 + t;
    int v = (i < NN) ? g_deg[i] : 0;
    sm[t] = v;
    __syncthreads();
    for (int off = 1; off < 1024; off <<= 1) {
        int x = (t >= off) ? sm[t - off] : 0;
        __syncthreads();
        sm[t] += x;
        __syncthreads();
    }
    if (i < NN) {
        int excl = sm[t] - v + g_boff[b];
        g_rowptr[i] = excl;
        g_pos[i] = excl;
        g_deg[i] = 0;
    }
}
__global__ void scatter_kernel(const int* __restrict__ src, const int* __restrict__ dst) {
    int e = blockIdx.x * blockDim.x + threadIdx.x;
    if (blockIdx.x == 0 && threadIdx.x < 256) {   // zero both BN ping-pong buffers
        g_bnsum[threadIdx.x] = 0.f;
        g_bnsq[threadIdx.x] = 0.f;
    }
    if (e < NE) {
        int d = dst[e];
        int p = atomicAdd(&g_pos[d], 1);
        g_srcs[p] = src[e];
    }
}

// ---------------- mma.sync bf16 GEMM, K-chunked (2 CTAs/SM), 512 threads ------
template<int NC>
__global__ void __launch_bounds__(512, 2) gemm_kernel(const float* __restrict__ Xopt,
                                                      int widx, int bnbuf,
                                                      const float* __restrict__ gamma,
                                                      const float* __restrict__ beta) {
    constexpr int NCP = NC + 8;
    constexpr int NT = NCP / 8;              // 17 or 21 (odd; last tile = logits)
    constexpr int NPAIRS = (NT + 1) / 2;     // 9 or 11; last pair is single
    constexpr int MAXP = (NPAIRS + 1) / 2;   // pairs per warp (wn stride 2)
    constexpr int KS = 72;                   // chunk row stride in bf16 (64 + 8 pad)
    extern __shared__ char dsm[];
    float* SC = (float*)dsm;                 // [128]
    float* SH = SC + 128;                    // [128]
    __nv_bfloat16* Ah = (__nv_bfloat16*)(dsm + 1024);   // [128][KS]
    __nv_bfloat16* Al = Ah + 128 * KS;
    __nv_bfloat16* Bh = Al + 128 * KS;                  // [NCP][KS]
    __nv_bfloat16* Bl = Bh + NCP * KS;

    const int useBN = (bnbuf >= 0);
    const float* X = Xopt ? Xopt : g_agg;
    const int tid = threadIdx.x;
    const int wid = tid >> 5, lane = tid & 31;
    const int wy = wid & 7;                  // row group
    const int wn = wid >> 3;                 // n-half
    const int row0 = blockIdx.x * 128;

    if (useBN && tid < 128) {
        float mu = g_bnsum[bnbuf * 128 + tid] * (1.f / NN);
        float var = g_bnsq[bnbuf * 128 + tid] * (1.f / NN) - mu * mu;
        float sc = rsqrtf(var + 1e-5f) * gamma[tid];
        SC[tid] = sc;
        SH[tid] = fmaf(-mu, sc, beta[tid]);
    }
    if (useBN) __syncthreads();

    float c[MAXP][2][4];
    #pragma unroll
    for (int pi = 0; pi < MAXP; pi++)
        #pragma unroll
        for (int u = 0; u < 2; u++)
            #pragma unroll
            for (int q = 0; q < 4; q++) c[pi][u][q] = 0.f;

    const uint32_t au = smem_u32(Ah), alu = smem_u32(Al);
    const uint32_t bu = smem_u32(Bh), blu = smem_u32(Bl);
    const int arow = wy * 16 + (lane & 15);
    const int acol0 = (lane >> 4) * 8;
    const int brow_x4 = (lane & 7) + ((lane >> 4) * 8);
    const int bcolsel = ((lane >> 3) & 1) * 8;

    for (int kc = 0; kc < 2; kc++) {
        // B chunk copy: [n][kc*64 .. +64) -> smem [n][KS]
        {
            const char* sH = (const char*)(g_Bh + widx * 22528) + kc * 128;
            const char* sL = (const char*)(g_Bl + widx * 22528) + kc * 128;
            for (int i = tid; i < NCP * 8; i += 512) {
                int row = i >> 3, seg = i & 7;
                *(float4*)((char*)Bh + row * (KS * 2) + seg * 16) = *(const float4*)(sH + row * 256 + seg * 16);
                *(float4*)((char*)Bl + row * (KS * 2) + seg * 16) = *(const float4*)(sL + row * 256 + seg * 16);
            }
        }
        // A chunk: load X cols [kc*64, +64), BN+ReLU, bf16 hi/lo split
        {
            __nv_bfloat162* A2h = (__nv_bfloat162*)Ah;
            __nv_bfloat162* A2l = (__nv_bfloat162*)Al;
            for (int i = tid; i < 2048; i += 512) {
                int r = i >> 4, c4l = i & 15;
                int c4 = kc * 16 + c4l;
                int gr = row0 + r;
                float4 v = make_float4(0.f, 0.f, 0.f, 0.f);
                if (gr < NN) {
                    v = ((const float4*)X)[gr * 32 + c4];
                    if (useBN) {
                        float4 sc = ((const float4*)SC)[c4];
                        float4 sh = ((const float4*)SH)[c4];
                        v.x = fmaxf(fmaf(v.x, sc.x, sh.x), 0.f);
                        v.y = fmaxf(fmaf(v.y, sc.y, sh.y), 0.f);
                        v.z = fmaxf(fmaf(v.z, sc.z, sh.z), 0.f);
                        v.w = fmaxf(fmaf(v.w, sc.w, sh.w), 0.f);
                    }
                }
                __nv_bfloat16 hx, lx, hy, ly, hz, lz, hw, lw;
                bfsplit(v.x, hx, lx); bfsplit(v.y, hy, ly);
                bfsplit(v.z, hz, lz); bfsplit(v.w, hw, lw);
                int o2 = r * (KS / 2) + c4l * 2;
                __nv_bfloat162 p0, p1, q0, q1;
                p0.x = hx; p0.y = hy; p1.x = hz; p1.y = hw;
                q0.x = lx; q0.y = ly; q1.x = lz; q1.y = lw;
                A2h[o2] = p0; A2h[o2 + 1] = p1;
                A2l[o2] = q0; A2l[o2 + 1] = q1;
            }
        }
        __syncthreads();

        for (int kb = 0; kb < 4; kb++) {
            uint32_t ah[4], al[4];
            uint32_t aoff = (uint32_t)((arow * KS + kb * 16 + acol0) * 2);
            ldmx4(au + aoff, ah);
            ldmx4(alu + aoff, al);
            #pragma unroll
            for (int pi = 0; pi < MAXP; pi++) {
                int p = wn + 2 * pi;
                if (p >= NPAIRS) break;
                if (2 * p + 1 < NT) {            // full pair (16 B-rows)
                    uint32_t bh[4], bl[4];
                    uint32_t boff = (uint32_t)(((p * 16 + brow_x4) * KS + kb * 16 + bcolsel) * 2);
                    ldmx4(bu + boff, bh);
                    ldmx4(blu + boff, bl);
                    mma_bf16(c[pi][0], ah, bh[0], bh[1]);
                    mma_bf16(c[pi][0], ah, bl[0], bl[1]);
                    mma_bf16(c[pi][0], al, bh[0], bh[1]);
                    mma_bf16(c[pi][1], ah, bh[2], bh[3]);
                    mma_bf16(c[pi][1], ah, bl[2], bl[3]);
                    mma_bf16(c[pi][1], al, bh[2], bh[3]);
                } else {                         // single (logits) tile
                    uint32_t bh[2], bl[2];
                    int brow2 = 2 * p * 8 + (lane & 7);
                    uint32_t boff = (uint32_t)((brow2 * KS + kb * 16 + bcolsel) * 2);
                    ldmx2(bu + boff, bh);
                    ldmx2(blu + boff, bl);
                    mma_bf16(c[pi][0], ah, bh[0], bh[1]);
                    mma_bf16(c[pi][0], ah, bl[0], bl[1]);
                    mma_bf16(c[pi][0], al, bh[0], bh[1]);
                }
            }
        }
        __syncthreads();
    }

    // epilogue
    const int g = lane >> 2, tig = lane & 3;
    const int rA = row0 + wy * 16 + g;
    const int rB = rA + 8;
    const bool okA = rA < NN, okB = rB < NN;
    #pragma unroll
    for (int pi = 0; pi < MAXP; pi++) {
        int p = wn + 2 * pi;
        if (p >= NPAIRS) break;
        #pragma unroll
        for (int u = 0; u < 2; u++) {
            int ntI = 2 * p + u;
            if (ntI >= NT) break;
            if (ntI < NT - 1) {
                if (okA) *(float2*)&g_h[rA * NC + ntI * 8 + tig * 2] = make_float2(c[pi][u][0], c[pi][u][1]);
                if (okB) *(float2*)&g_h[rB * NC + ntI * 8 + tig * 2] = make_float2(c[pi][u][2], c[pi][u][3]);
            } else {
                float e0 = c[pi][u][0], e1 = c[pi][u][1], e2 = c[pi][u][2], e3 = c[pi][u][3];
                float o0 = __shfl_xor_sync(0xffffffffu, e0, 1);
                float o1 = __shfl_xor_sync(0xffffffffu, e1, 1);
                float o2 = __shfl_xor_sync(0xffffffffu, e2, 1);
                float o3 = __shfl_xor_sync(0xffffffffu, e3, 1);
                if (tig == 0) {
                    if (okA) g_as4[rA] = make_float4(e0, e1, o0, o1);
                    if (okB) g_as4[rB] = make_float4(e2, e3, o2, o3);
                } else if (tig == 2) {
                    if (okA) g_ad4[rA] = make_float4(e0, e1, o0, o1);
                    if (okB) g_ad4[rB] = make_float4(e2, e3, o2, o3);
                }
            }
        }
    }
}

// ---------------- softmax + aggregation (+fused BN partial sums) ----------------
template<int C>
__device__ __forceinline__ void gather_step(int s, float alpha, float (&acc)[C], int lane) {
    if (C == 4) {
        float4 hv = ((const float4*)g_h)[s * 32 + lane];
        acc[0] = fmaf(hv.x, alpha, acc[0]);
        acc[1] = fmaf(hv.y, alpha, acc[1]);
        acc[2] = fmaf(hv.z, alpha, acc[2]);
        acc[3] = fmaf(hv.w, alpha, acc[3]);
    } else {
        #pragma unroll
        for (int j = 0; j < C; j++)
            acc[j] = fmaf(g_h[s * (32 * C) + lane * C + j], alpha, acc[j]);
    }
}

template<int D, bool MEAN>
__global__ void __launch_bounds__(256) agg_kernel(float* __restrict__ outMean, int bnbuf) {
    constexpr int C = D / 8;
    __shared__ int    ssrc[8][64];
    __shared__ float4 ealpha[8][64];
    __shared__ float4 bnS[8][32];
    __shared__ float4 bnQ[8][32];
    int w = threadIdx.x >> 5, lane = threadIdx.x & 31;
    int v = blockIdx.x * 8 + w;
    int head = lane >> 3;
    int start = g_rowptr[v];
    int deg = g_rowptr[v + 1] - start;
    float4 ad = g_ad4[v];

    float acc[C];
    #pragma unroll
    for (int j = 0; j < C; j++) acc[j] = 0.f;

    if (deg > 0 && deg <= 64) {
        int s0 = 0, s1 = 0;
        float4 e0, e1;
        bool h0 = lane < deg, h1 = lane + 32 < deg;
        float m0 = -CUDART_INF_F, m1 = m0, m2 = m0, m3 = m0;
        if (h0) {
            s0 = g_srcs[start + lane];
            float4 a = g_as4[s0];
            e0.x = lrelu(a.x + ad.x); e0.y = lrelu(a.y + ad.y);
            e0.z = lrelu(a.z + ad.z); e0.w = lrelu(a.w + ad.w);
            m0 = e0.x; m1 = e0.y; m2 = e0.z; m3 = e0.w;
        }
        if (h1) {
            s1 = g_srcs[start + lane + 32];
            float4 a = g_as4[s1];
            e1.x = lrelu(a.x + ad.x); e1.y = lrelu(a.y + ad.y);
            e1.z = lrelu(a.z + ad.z); e1.w = lrelu(a.w + ad.w);
            m0 = fmaxf(m0, e1.x); m1 = fmaxf(m1, e1.y);
            m2 = fmaxf(m2, e1.z); m3 = fmaxf(m3, e1.w);
        }
        #pragma unroll
        for (int o = 16; o; o >>= 1) {
            m0 = fmaxf(m0, __shfl_xor_sync(0xffffffffu, m0, o));
            m1 = fmaxf(m1, __shfl_xor_sync(0xffffffffu, m1, o));
            m2 = fmaxf(m2, __shfl_xor_sync(0xffffffffu, m2, o));
            m3 = fmaxf(m3, __shfl_xor_sync(0xffffffffu, m3, o));
        }
        float d0 = 0.f, d1 = 0.f, d2 = 0.f, d3 = 0.f;
        float x00=0,x01=0,x02=0,x03=0, x10=0,x11=0,x12=0,x13=0;
        if (h0) {
            x00 = __expf(e0.x - m0); x01 = __expf(e0.y - m1);
            x02 = __expf(e0.z - m2); x03 = __expf(e0.w - m3);
            d0 += x00; d1 += x01; d2 += x02; d3 += x03;
        }
        if (h1) {
            x10 = __expf(e1.x - m0); x11 = __expf(e1.y - m1);
            x12 = __expf(e1.z - m2); x13 = __expf(e1.w - m3);
            d0 += x10; d1 += x11; d2 += x12; d3 += x13;
        }
        #pragma unroll
        for (int o = 16; o; o >>= 1) {
            d0 += __shfl_xor_sync(0xffffffffu, d0, o);
            d1 += __shfl_xor_sync(0xffffffffu, d1, o);
            d2 += __shfl_xor_sync(0xffffffffu, d2, o);
            d3 += __shfl_xor_sync(0xffffffffu, d3, o);
        }
        float i0 = 1.f / (d0 + 1e-16f), i1 = 1.f / (d1 + 1e-16f);
        float i2 = 1.f / (d2 + 1e-16f), i3 = 1.f / (d3 + 1e-16f);
        if (h0) {
            ssrc[w][lane] = s0;
            ealpha[w][lane] = make_float4(x00 * i0, x01 * i1, x02 * i2, x03 * i3);
        }
        if (h1) {
            ssrc[w][lane + 32] = s1;
            ealpha[w][lane + 32] = make_float4(x10 * i0, x11 * i1, x12 * i2, x13 * i3);
        }
        __syncwarp();
        #pragma unroll 4
        for (int t = 0; t < deg; t++) {
            int s = ssrc[w][t];
            float alpha = ((const float*)&ealpha[w][t])[head];
            gather_step<C>(s, alpha, acc, lane);
        }
    } else if (deg > 64) {
        float m0 = -CUDART_INF_F, m1 = m0, m2 = m0, m3 = m0;
        for (int i = lane; i < deg; i += 32) {
            int s = g_srcs[start + i];
            float4 a = g_as4[s];
            m0 = fmaxf(m0, lrelu(a.x + ad.x)); m1 = fmaxf(m1, lrelu(a.y + ad.y));
            m2 = fmaxf(m2, lrelu(a.z + ad.z)); m3 = fmaxf(m3, lrelu(a.w + ad.w));
        }
        #pragma unroll
        for (int o = 16; o; o >>= 1) {
            m0 = fmaxf(m0, __shfl_xor_sync(0xffffffffu, m0, o));
            m1 = fmaxf(m1, __shfl_xor_sync(0xffffffffu, m1, o));
            m2 = fmaxf(m2, __shfl_xor_sync(0xffffffffu, m2, o));
            m3 = fmaxf(m3, __shfl_xor_sync(0xffffffffu, m3, o));
        }
        float d0 = 0.f, d1 = 0.f, d2 = 0.f, d3 = 0.f;
        for (int i = lane; i < deg; i += 32) {
            int s = g_srcs[start + i];
            float4 a = g_as4[s];
            d0 += __expf(lrelu(a.x + ad.x) - m0);
            d1 += __expf(lrelu(a.y + ad.y) - m1);
            d2 += __expf(lrelu(a.z + ad.z) - m2);
            d3 += __expf(lrelu(a.w + ad.w) - m3);
        }
        #pragma unroll
        for (int o = 16; o; o >>= 1) {
            d0 += __shfl_xor_sync(0xffffffffu, d0, o);
            d1 += __shfl_xor_sync(0xffffffffu, d1, o);
            d2 += __shfl_xor_sync(0xffffffffu, d2, o);
            d3 += __shfl_xor_sync(0xffffffffu, d3, o);
        }
        float denh = (head == 0) ? d0 : (head == 1) ? d1 : (head == 2) ? d2 : d3;
        float mxh  = (head == 0) ? m0 : (head == 1) ? m1 : (head == 2) ? m2 : m3;
        float adh  = (head == 0) ? ad.x : (head == 1) ? ad.y : (head == 2) ? ad.z : ad.w;
        float invh = 1.f / (denh + 1e-16f);
        for (int t = 0; t < deg; t++) {
            int s = g_srcs[start + t];
            float ash = ((const float*)&g_as4[s])[head];
            float alpha = __expf(lrelu(ash + adh) - mxh) * invh;
            gather_step<C>(s, alpha, acc, lane);
        }
    }

    if (MEAN) {
        #pragma unroll
        for (int j = 0; j < C; j++) {
            float a = acc[j];
            a += __shfl_xor_sync(0xffffffffu, a, 8);
            a += __shfl_xor_sync(0xffffffffu, a, 16);
            if (lane < 8) outMean[v * D + lane * C + j] = 0.25f * a;
        }
    } else {
        float4 a4 = make_float4(acc[0], acc[1], acc[2], acc[3]);
        ((float4*)g_agg)[v * 32 + lane] = a4;
        bnS[w][lane] = a4;
        bnQ[w][lane] = make_float4(a4.x * a4.x, a4.y * a4.y, a4.z * a4.z, a4.w * a4.w);
        __syncthreads();
        int t = threadIdx.x;
        if (t < 128) {
            float s = 0.f;
            #pragma unroll
            for (int i = 0; i < 8; i++) s += ((const float*)&bnS[i][t >> 2])[t & 3];
            atomicAdd(&g_bnsum[bnbuf * 128 + t], s);
        } else {
            int cc = t - 128;
            float q = 0.f;
            #pragma unroll
            for (int i = 0; i < 8; i++) q += ((const float*)&bnQ[i][cc >> 2])[cc & 3];
            atomicAdd(&g_bnsq[bnbuf * 128 + cc], q);
        }
    }
}

// ---------------- launch ----------------
extern "C" void kernel_launch(void* const* d_in, const int* in_sizes, int n_in,
                              void* d_out, int out_size) {
    (void)in_sizes; (void)n_in; (void)out_size;
    const float* x     = (const float*)d_in[0];
    const int*   ei    = (const int*)d_in[1];
    const float* w01   = (const float*)d_in[2];
    const float* s01   = (const float*)d_in[3];
    const float* att01 = (const float*)d_in[4];
    const float* w2    = (const float*)d_in[5];
    const float* s2    = (const float*)d_in[6];
    const float* att2  = (const float*)d_in[7];
    const float* gamma = (const float*)d_in[8];
    const float* beta  = (const float*)d_in[9];
    float* out = (float*)d_out;
    const int* srcp = ei;
    const int* dstp = ei + NE;

    const int THR_SMEM  = (53248 + 32) * 4;
    const int G128_SMEM = 1024 + 2 * 128 * 72 * 2 + 2 * 136 * 72 * 2;   // ~75 KB
    const int G160_SMEM = 1024 + 2 * 128 * 72 * 2 + 2 * 168 * 72 * 2;   // ~84 KB
    cudaFuncSetAttribute(thr_kernel, cudaFuncAttributeMaxDynamicSharedMemorySize, THR_SMEM);
    cudaFuncSetAttribute(gemm_kernel<128>, cudaFuncAttributeMaxDynamicSharedMemorySize, G128_SMEM);
    cudaFuncSetAttribute(gemm_kernel<160>, cudaFuncAttributeMaxDynamicSharedMemorySize, G160_SMEM);

    const int GB = (NN + 127) / 128;   // 782
    const int AB = NN / 8;             // 12500

    thr_kernel<<<1, 1024, THR_SMEM>>>(s01, s2);
    maskwext_kernel<<<53, 1024>>>(w01, s01, att01, w2, s2, att2);

    // Fork: CSR build on a side stream, concurrent with gemm L0.
    cudaStream_t side;
    cudaEvent_t evFork, evJoin;
    cudaStreamCreateWithFlags(&side, cudaStreamNonBlocking);
    cudaEventCreateWithFlags(&evFork, cudaEventDisableTiming);
    cudaEventCreateWithFlags(&evJoin, cudaEventDisableTiming);

    cudaEventRecord(evFork, 0);
    cudaStreamWaitEvent(side, evFork, 0);

    // side: CSR chain (+ BN buffer zeroing folded into scatter)
    hist_kernel<<<(NE + 255) / 256, 256, 0, side>>>(dstp);
    scan1_kernel<<<98, 1024, 0, side>>>();
    scan2_kernel<<<1, 32, 0, side>>>();
    scan3_kernel<<<98, 1024, 0, side>>>();
    scatter_kernel<<<(NE + 255) / 256, 256, 0, side>>>(srcp, dstp);
    cudaEventRecord(evJoin, side);

    // main: gemm L0 (no BN)
    gemm_kernel<128><<<GB, 512, G128_SMEM>>>(x, 0, -1, gamma, beta);

    cudaStreamWaitEvent(0, evJoin, 0);

    agg_kernel<32, false><<<AB, 256>>>(nullptr, 0);
    gemm_kernel<128><<<GB, 512, G128_SMEM>>>(nullptr, 1, 0, gamma, beta);
    agg_kernel<32, false><<<AB, 256>>>(nullptr, 1);
    gemm_kernel<160><<<GB, 512, G160_SMEM>>>(nullptr, 2, 1, gamma + 128, beta + 128);
    agg_kernel<40, true><<<AB, 256>>>(out, 0);

    cudaStreamDestroy(side);
    cudaEventDestroy(evFork);
    cudaEventDestroy(evJoin);
}